// round 9
// baseline (speedup 1.0000x reference)
#include <cuda_runtime.h>
#include <cstdint>
#include <cstddef>

// ---------------- problem constants ----------------
#define Tt      4
#define Bt      64
#define BpC     16
#define Cc      512
#define Nn      512
#define Hh      8
#define GD      64
#define TAU     0.5f
#define THRESH  1.0f
#define SCALE   0.125f
#define EPSBN   1e-5f
#define SZ      (Bt*Cc*Nn)      // 16,777,216
#define CN      (Cc*Nn)         // 262,144

typedef unsigned long long ull;

// ---------------- scratch (device globals) ----------------
__device__ __align__(128) float  g_pre[3ll*SZ];
__device__ __align__(128) float  g_spk[3ll*SZ];
__device__ __align__(128) float  g_so [SZ];
__device__ __align__(128) int8_t g_wq8h[4ll*CN];
__device__ __align__(128) int8_t g_wq8l[4ll*CN];
__device__ __align__(128) float  g_wscl[4*Cc];
__device__ __align__(128) int8_t g_xq8h[SZ];        // x hi, transposed [b][n][c]
__device__ __align__(128) int8_t g_xq8l[SZ];        // x lo
__device__ __align__(128) float  g_xscl[Bt*Nn];     // per (b,n) column scale
__device__ __align__(128) int8_t g_sq8 [SZ];        // spikes s8, transposed [b][n][c]

// ---------------- PTX helpers ----------------
static __device__ __forceinline__ uint32_t smem_u32(const void* p) {
    uint32_t a;
    asm("{ .reg .u64 t; cvta.to.shared.u64 t, %1; cvt.u32.u64 %0, t; }" : "=r"(a) : "l"(p));
    return a;
}
static __device__ __forceinline__ void cpasync16(uint32_t dst, const void* src) {
    asm volatile("cp.async.cg.shared.global [%0], [%1], 16;" :: "r"(dst), "l"(src));
}
#define CP_COMMIT()  asm volatile("cp.async.commit_group;" ::: "memory")
#define CP_WAIT(n)   asm volatile("cp.async.wait_group %0;" :: "n"(n) : "memory")

static __device__ __forceinline__ void ldm_x4(uint32_t* r, uint32_t addr) {
    asm volatile("ldmatrix.sync.aligned.m8n8.x4.shared.b16 {%0,%1,%2,%3}, [%4];"
        : "=r"(r[0]), "=r"(r[1]), "=r"(r[2]), "=r"(r[3]) : "r"(addr));
}
static __device__ __forceinline__ void mma_s8(int* c, const uint32_t* a, const uint32_t* b) {
    asm volatile("mma.sync.aligned.m16n8k32.row.col.s32.s8.s8.s32 "
        "{%0,%1,%2,%3}, {%4,%5,%6,%7}, {%8,%9}, {%0,%1,%2,%3};"
        : "+r"(c[0]), "+r"(c[1]), "+r"(c[2]), "+r"(c[3])
        : "r"(a[0]), "r"(a[1]), "r"(a[2]), "r"(a[3]), "r"(b[0]), "r"(b[1]));
}

// ---------------- fp32x2 helpers (attn kernel) ----------------
static __device__ __forceinline__ void ffma2(ull& d, ull a, ull b) {
    asm("fma.rn.f32x2 %0, %1, %2, %0;" : "+l"(d) : "l"(a), "l"(b));
}
static __device__ __forceinline__ ull bcast2(float w) {
    ull r; asm("mov.b64 %0, {%1, %1};" : "=l"(r) : "f"(w)); return r;
}
static __device__ __forceinline__ float2 unpack2(ull v) {
    float2 f; asm("mov.b64 {%0, %1}, %2;" : "=f"(f.x), "=f"(f.y) : "l"(v)); return f;
}

// =====================================================================
// weight quant: per-row 2-term s8 split. grid (512 rows, 4 mats), 128 thr
// =====================================================================
__global__ __launch_bounds__(128) void wquant_kernel(
    const float* __restrict__ wq, const float* __restrict__ wk,
    const float* __restrict__ wv, const float* __restrict__ wp)
{
    __shared__ float sm[4];
    __shared__ float s_bcast;
    const int sel = blockIdx.y, row = blockIdx.x, tid = threadIdx.x;
    const float* w = (sel == 0) ? wq : (sel == 1) ? wk : (sel == 2) ? wv : wp;
    const float* wr = w + (size_t)row * Cc;

    float v[4], m = 0.f;
    #pragma unroll
    for (int j = 0; j < 4; j++) { v[j] = wr[tid + j*128]; m = fmaxf(m, fabsf(v[j])); }
    #pragma unroll
    for (int o = 16; o > 0; o >>= 1) m = fmaxf(m, __shfl_xor_sync(0xffffffffu, m, o));
    if ((tid & 31) == 0) sm[tid >> 5] = m;
    __syncthreads();
    if (tid == 0) {
        float mm = fmaxf(fmaxf(sm[0], sm[1]), fmaxf(sm[2], sm[3]));
        float s = mm / 127.4f + 1e-30f;
        g_wscl[sel*Cc + row] = s;
        s_bcast = s;
    }
    __syncthreads();
    const float invs = 1.f / s_bcast;
    #pragma unroll
    for (int j = 0; j < 4; j++) {
        float q = v[j] * invs;
        float qh = rintf(q);
        float ql = rintf((q - qh) * 254.f);
        g_wq8h[(size_t)sel*CN + (size_t)row*Cc + tid + j*128] = (int8_t)(int)qh;
        g_wq8l[(size_t)sel*CN + (size_t)row*Cc + tid + j*128] = (int8_t)(int)ql;
    }
}

// =====================================================================
// x column max: grid (4 ntiles, 64 b), 128 threads, one n each
// =====================================================================
__global__ __launch_bounds__(128) void colmax_kernel(const float* __restrict__ x)
{
    const int b = blockIdx.y, n = blockIdx.x * 128 + threadIdx.x;
    const float* xb = x + (size_t)b * CN;
    float m = 1e-30f;
    for (int c = 0; c < Cc; c++) m = fmaxf(m, fabsf(xb[(size_t)c * Nn + n]));
    g_xscl[b*Nn + n] = m / 127.4f;
}

// =====================================================================
// x transpose+quant 2-term: [b][c][n] f32 -> [b][n][c] s8 hi/lo
// grid (16 ntiles, 16 ctiles, 64 b), 256 threads
// =====================================================================
__global__ __launch_bounds__(256) void xquant_t_kernel(const float* __restrict__ x)
{
    __shared__ float t[32][33];
    const int b = blockIdx.z, c0 = blockIdx.y * 32, n0 = blockIdx.x * 32;
    const int tid = threadIdx.x;
    const int tx = tid & 31, ty = tid >> 5;          // read: tx=n, ty covers c
    const float* xb = x + (size_t)b * CN;
    #pragma unroll
    for (int j = 0; j < 4; j++)
        t[ty + 8*j][tx] = xb[(size_t)(c0 + ty + 8*j) * Nn + n0 + tx];
    __syncthreads();
    // write: 32 n-rows x 8 c-quads
    const int n = tid >> 3;               // 0..31
    const int cq = (tid & 7) * 4;         // 0..28
    const float invs = 1.f / g_xscl[b*Nn + n0 + n];
    char4 h, l;
    float q, qh;
    q = t[cq+0][n]*invs; qh = rintf(q); h.x = (int8_t)(int)qh; l.x = (int8_t)(int)rintf((q-qh)*254.f);
    q = t[cq+1][n]*invs; qh = rintf(q); h.y = (int8_t)(int)qh; l.y = (int8_t)(int)rintf((q-qh)*254.f);
    q = t[cq+2][n]*invs; qh = rintf(q); h.z = (int8_t)(int)qh; l.z = (int8_t)(int)rintf((q-qh)*254.f);
    q = t[cq+3][n]*invs; qh = rintf(q); h.w = (int8_t)(int)qh; l.w = (int8_t)(int)rintf((q-qh)*254.f);
    const size_t o = (size_t)b * CN + (size_t)(n0 + n) * Cc + c0 + cq;
    *(char4*)&g_xq8h[o] = h;
    *(char4*)&g_xq8l[o] = l;
}

// =====================================================================
// spike transpose: g_so [b][c][n] f32 (0/1) -> g_sq8 [b][n][c] s8 exact
// =====================================================================
__global__ __launch_bounds__(256) void squant_t_kernel()
{
    __shared__ float t[32][33];
    const int b = blockIdx.z, c0 = blockIdx.y * 32, n0 = blockIdx.x * 32;
    const int tid = threadIdx.x;
    const int tx = tid & 31, ty = tid >> 5;
    const float* sb = g_so + (size_t)b * CN;
    #pragma unroll
    for (int j = 0; j < 4; j++)
        t[ty + 8*j][tx] = sb[(size_t)(c0 + ty + 8*j) * Nn + n0 + tx];
    __syncthreads();
    const int n = tid >> 3;
    const int cq = (tid & 7) * 4;
    char4 h;
    h.x = (int8_t)(int)t[cq+0][n];
    h.y = (int8_t)(int)t[cq+1][n];
    h.z = (int8_t)(int)t[cq+2][n];
    h.w = (int8_t)(int)t[cq+3][n];
    *(char4*)&g_sq8[(size_t)b * CN + (size_t)(n0 + n) * Cc + c0 + cq] = h;
}

// =====================================================================
// int8 conv_bn GEMM: D[128m x 128n] = W @ B^T per batch, K=512, + BN
// s8 2-term splits, s32 mma k32, term-major issue, cp.async double buffer
// mode 0: merged qkv (by 0..11), B = x quant, out = g_pre
// mode 1: proj (by 0..3),       B = spikes s8 (exact), out = extout
// =====================================================================
#define ROWB   144                      // 128 s8 + 16B pad
#define TILEB  (128*ROWB)               // 18432
#define STAGEB (4*TILEB)                // Ah|Al|Bh|Bl = 73728

__global__ __launch_bounds__(256) void i8_conv(
    float* __restrict__ extout,
    const float* __restrict__ bng, const float* __restrict__ bnb,
    const float* __restrict__ bnm, const float* __restrict__ bnv,
    int mode)
{
    extern __shared__ char smem[];
    const uint32_t sb = smem_u32(smem);
    const int tid  = threadIdx.x;
    const int wid  = tid >> 5, lane = tid & 31;
    const int n0   = blockIdx.x * 128;
    const int b    = blockIdx.z;

    int wsel, r0, terms;
    float* out;
    const int8_t *bhp, *blp;
    if (mode == 0) {
        wsel = blockIdx.y >> 2; r0 = (blockIdx.y & 3) * 128; terms = 3;
        out  = g_pre + (size_t)wsel * SZ;
        bhp  = g_xq8h + (size_t)b * CN + (size_t)n0 * Cc;
        blp  = g_xq8l + (size_t)b * CN + (size_t)n0 * Cc;
    } else {
        wsel = 3; r0 = blockIdx.y * 128; terms = 2;
        out  = extout;
        bhp  = g_sq8 + (size_t)b * CN + (size_t)n0 * Cc;
        blp  = bhp;
    }
    const int bnrow = wsel;
    const int8_t* whp = g_wq8h + (size_t)wsel * CN + (size_t)r0 * Cc;
    const int8_t* wlp = g_wq8l + (size_t)wsel * CN + (size_t)r0 * Cc;

    // loader: 256 threads cover 128 rows x 8 16B-chunks (4 chunks each)
    const int lrow = tid >> 1;
    const int cb0  = (tid & 1) * 4;
    const uint32_t rowOff = (uint32_t)lrow * ROWB;
    const int8_t* gAh = whp + (size_t)lrow * Cc;
    const int8_t* gAl = wlp + (size_t)lrow * Cc;
    const int8_t* gBh = bhp + (size_t)lrow * Cc;
    const int8_t* gBl = blp + (size_t)lrow * Cc;

    int acc0[4][4][4], acc1[4][4][4];
    #pragma unroll
    for (int i = 0; i < 4; i++)
        #pragma unroll
        for (int j = 0; j < 4; j++)
            #pragma unroll
            for (int q = 0; q < 4; q++) { acc0[i][j][q] = 0; acc1[i][j][q] = 0; }

    const int wm = wid & 1, wn = wid >> 1;
    const int grp = lane >> 3, wi = lane & 7;

    // stage loader (k0 in s8 elements == bytes)
    auto load_stage = [&](uint32_t st, int k0) {
        #pragma unroll
        for (int j = 0; j < 4; j++) {
            const int c = cb0 + j;
            const uint32_t off = rowOff + c * 16;
            cpasync16(st + off,           gAh + k0 + c*16);
            cpasync16(st + TILEB + off,   gAl + k0 + c*16);
            cpasync16(st + 2*TILEB + off, gBh + k0 + c*16);
            if (terms == 3) cpasync16(st + 3*TILEB + off, gBl + k0 + c*16);
        }
    };

    load_stage(sb, 0);
    CP_COMMIT();

    for (int kc = 0; kc < 4; kc++) {            // K = 4 * 128
        const int s = kc & 1;
        if (kc < 3) {
            load_stage(sb + (s^1)*STAGEB, (kc + 1) * 128);
            CP_COMMIT();
            CP_WAIT(1);
        } else {
            CP_WAIT(0);
        }
        __syncthreads();

        const uint32_t st = sb + s * STAGEB;
        #pragma unroll
        for (int ks = 0; ks < 4; ks++) {        // 4 x k32 per stage
            uint32_t Ah[4][4], Al[4][4], Bh[4][2], Bl[4][2];
            #pragma unroll
            for (int mi = 0; mi < 4; mi++) {
                const uint32_t ra = st
                    + (uint32_t)(wm*64 + mi*16 + wi + (grp&1)*8) * ROWB
                    + (uint32_t)(ks*32 + (grp>>1)*16);
                ldm_x4(Ah[mi], ra);
                ldm_x4(Al[mi], ra + TILEB);
            }
            #pragma unroll
            for (int bt = 0; bt < 2; bt++) {
                const uint32_t rb = st + 2*TILEB
                    + (uint32_t)(wn*32 + bt*16 + wi + (grp>>1)*8) * ROWB
                    + (uint32_t)(ks*32 + (grp&1)*16);
                uint32_t r[4];
                ldm_x4(r, rb);
                Bh[bt*2][0] = r[0]; Bh[bt*2][1] = r[1];
                Bh[bt*2+1][0] = r[2]; Bh[bt*2+1][1] = r[3];
                if (terms == 3) {
                    ldm_x4(r, rb + TILEB);
                    Bl[bt*2][0] = r[0]; Bl[bt*2][1] = r[1];
                    Bl[bt*2+1][0] = r[2]; Bl[bt*2+1][1] = r[3];
                }
            }
            // term-major issue
            #pragma unroll
            for (int mi = 0; mi < 4; mi++)
                #pragma unroll
                for (int nt = 0; nt < 4; nt++)
                    mma_s8(acc0[mi][nt], Ah[mi], Bh[nt]);
            #pragma unroll
            for (int mi = 0; mi < 4; mi++)
                #pragma unroll
                for (int nt = 0; nt < 4; nt++)
                    mma_s8(acc1[mi][nt], Al[mi], Bh[nt]);
            if (terms == 3) {
                #pragma unroll
                for (int mi = 0; mi < 4; mi++)
                    #pragma unroll
                    for (int nt = 0; nt < 4; nt++)
                        mma_s8(acc1[mi][nt], Ah[mi], Bl[nt]);
            }
        }
        __syncthreads();
    }

    // epilogue: combine terms, scale, BN affine, store fp32
    const float RL = 1.f / 254.f;
    #pragma unroll
    for (int mi = 0; mi < 4; mi++) {
        const int rA = r0 + wm*64 + mi*16 + (lane >> 2);
        const int rB = rA + 8;
        const float srA = g_wscl[wsel*Cc + rA];
        const float srB = g_wscl[wsel*Cc + rB];
        const float invA  = bng[bnrow*Cc + rA] / sqrtf(bnv[bnrow*Cc + rA] + EPSBN);
        const float biasA = bnb[bnrow*Cc + rA] - bnm[bnrow*Cc + rA] * invA;
        const float invB  = bng[bnrow*Cc + rB] / sqrtf(bnv[bnrow*Cc + rB] + EPSBN);
        const float biasB = bnb[bnrow*Cc + rB] - bnm[bnrow*Cc + rB] * invB;
        const float sA = srA * invA, sB = srB * invB;
        float* pA = out + ((size_t)b * Cc + rA) * Nn + n0;
        float* pB = out + ((size_t)b * Cc + rB) * Nn + n0;
        #pragma unroll
        for (int nt = 0; nt < 4; nt++) {
            const int nc = wn*32 + nt*8 + (lane & 3)*2;
            float sc0 = 1.f, sc1 = 1.f;
            if (mode == 0) {
                sc0 = g_xscl[b*Nn + n0 + nc];
                sc1 = g_xscl[b*Nn + n0 + nc + 1];
            }
            const float f0 = (float)acc0[mi][nt][0] + (float)acc1[mi][nt][0] * RL;
            const float f1 = (float)acc0[mi][nt][1] + (float)acc1[mi][nt][1] * RL;
            const float f2 = (float)acc0[mi][nt][2] + (float)acc1[mi][nt][2] * RL;
            const float f3 = (float)acc0[mi][nt][3] + (float)acc1[mi][nt][3] * RL;
            float2 v0, v1;
            v0.x = f0 * sA * sc0 + biasA;
            v0.y = f1 * sA * sc1 + biasA;
            v1.x = f2 * sB * sc0 + biasB;
            v1.y = f3 * sB * sc1 + biasB;
            *(float2*)&pA[nc] = v0;
            *(float2*)&pB[nc] = v1;
        }
    }
}

// =====================================================================
// LIF over T for q/k/v pre-activations
// =====================================================================
__global__ __launch_bounds__(256) void lif_qkv_kernel()
{
    const int idx = blockIdx.x * 256 + threadIdx.x;
    const int q   = idx & 127;
    const int c   = (idx >> 7) & 511;
    const int bp  = (idx >> 16) & 15;
    const int sel = idx >> 20;

    const float* pre = g_pre + (size_t)sel * SZ;
    float*       spk = g_spk + (size_t)sel * SZ;

    float4 mem = {0.f, 0.f, 0.f, 0.f};
    #pragma unroll
    for (int t = 0; t < 4; t++) {
        const size_t off = (((size_t)(t*BpC + bp) * Cc + c) * Nn) + q*4;
        float4 v = *(const float4*)&pre[off];
        float4 s;
        mem.x = mem.x*TAU + v.x; s.x = (mem.x > THRESH) ? 1.f : 0.f; if (mem.x > THRESH) mem.x = 0.f;
        mem.y = mem.y*TAU + v.y; s.y = (mem.y > THRESH) ? 1.f : 0.f; if (mem.y > THRESH) mem.y = 0.f;
        mem.z = mem.z*TAU + v.z; s.z = (mem.z > THRESH) ? 1.f : 0.f; if (mem.z > THRESH) mem.z = 0.f;
        mem.w = mem.w*TAU + v.w; s.w = (mem.w > THRESH) ? 1.f : 0.f; if (mem.w > THRESH) mem.w = 0.f;
        *(float4*)&spk[off] = s;
    }
}

// =====================================================================
// Attention (reassociated) + LIF, fused per (b', h)
// =====================================================================
__global__ __launch_bounds__(256) void attn_kernel()
{
    extern __shared__ __align__(16) float sm[];
    float* Ms = sm;
    float* Sa = sm + 4*64*64;
    float* Sb = Sa + 64*68;

    const int bp = blockIdx.x;
    const int h  = blockIdx.y;
    const int tid = threadIdx.x;
    const int ty = tid >> 4, tx = tid & 15;
    const int sRow = tid >> 2;
    const int sCol = (tid & 3) * 4;

    for (int t = 0; t < 4; t++) {
        const int b = t*BpC + bp;
        const float* K = g_spk + (size_t)SZ   + ((size_t)b*Cc + h*GD) * Nn;
        const float* V = g_spk + (size_t)2*SZ + ((size_t)b*Cc + h*GD) * Nn;

        ull accM[4][2];
        #pragma unroll
        for (int i = 0; i < 4; i++) { accM[i][0] = 0ull; accM[i][1] = 0ull; }

        for (int m0 = 0; m0 < Nn; m0 += 64) {
            float4 kv[4], vv[4];
            #pragma unroll
            for (int j = 0; j < 4; j++) {
                kv[j] = *(const float4*)&K[(size_t)sRow * Nn + m0 + sCol + 16*j];
                vv[j] = *(const float4*)&V[(size_t)sRow * Nn + m0 + sCol + 16*j];
            }
            __syncthreads();
            #pragma unroll
            for (int j = 0; j < 4; j++) {
                const int m = sCol + 16*j;
                Sa[(m+0)*68 + sRow] = kv[j].x; Sa[(m+1)*68 + sRow] = kv[j].y;
                Sa[(m+2)*68 + sRow] = kv[j].z; Sa[(m+3)*68 + sRow] = kv[j].w;
                Sb[(m+0)*68 + sRow] = vv[j].x; Sb[(m+1)*68 + sRow] = vv[j].y;
                Sb[(m+2)*68 + sRow] = vv[j].z; Sb[(m+3)*68 + sRow] = vv[j].w;
            }
            __syncthreads();
            #pragma unroll 8
            for (int mm = 0; mm < 64; mm++) {
                float4 ka = *(const float4*)&Sa[mm*68 + ty*4];
                ulonglong2 vp = *(const ulonglong2*)&Sb[mm*68 + tx*4];
                const float kf[4] = {ka.x, ka.y, ka.z, ka.w};
                #pragma unroll
                for (int i = 0; i < 4; i++) {
                    ull kb = bcast2(kf[i]);
                    ffma2(accM[i][0], kb, vp.x);
                    ffma2(accM[i][1], kb, vp.y);
                }
            }
        }
        #pragma unroll
        for (int i = 0; i < 4; i++) {
            float2 a = unpack2(accM[i][0]);
            float2 c2 = unpack2(accM[i][1]);
            float4 mo; mo.x = a.x; mo.y = a.y; mo.z = c2.x; mo.w = c2.y;
            *(float4*)&Ms[t*4096 + (ty*4 + i)*64 + tx*4] = mo;
        }
    }
    __syncthreads();

    for (int n0 = 0; n0 < Nn; n0 += 64) {
        float mem[4][4];
        #pragma unroll
        for (int i = 0; i < 4; i++)
            #pragma unroll
            for (int j = 0; j < 4; j++) mem[i][j] = 0.f;

        for (int t = 0; t < 4; t++) {
            const int b = t*BpC + bp;
            const float* Q = g_spk + ((size_t)b*Cc + h*GD) * Nn;
            float4 qv[4];
            #pragma unroll
            for (int j = 0; j < 4; j++)
                qv[j] = *(const float4*)&Q[(size_t)sRow * Nn + n0 + sCol + 16*j];
            __syncthreads();
            #pragma unroll
            for (int j = 0; j < 4; j++)
                *(float4*)&Sa[sRow*68 + sCol + 16*j] = qv[j];
            __syncthreads();

            ull acc[4][2];
            #pragma unroll
            for (int i = 0; i < 4; i++) { acc[i][0] = 0ull; acc[i][1] = 0ull; }

            #pragma unroll 8
            for (int dk = 0; dk < 64; dk++) {
                float4 mv = *(const float4*)&Ms[t*4096 + dk*64 + ty*4];
                ulonglong2 qp = *(const ulonglong2*)&Sa[dk*68 + tx*4];
                const float mf[4] = {mv.x, mv.y, mv.z, mv.w};
                #pragma unroll
                for (int i = 0; i < 4; i++) {
                    ull mb = bcast2(mf[i]);
                    ffma2(acc[i][0], mb, qp.x);
                    ffma2(acc[i][1], mb, qp.y);
                }
            }

            float* so = g_so + ((size_t)b*Cc + h*GD) * Nn;
            #pragma unroll
            for (int i = 0; i < 4; i++) {
                float2 a = unpack2(acc[i][0]);
                float2 c2 = unpack2(acc[i][1]);
                float o[4] = {a.x, a.y, c2.x, c2.y};
                float s[4];
                #pragma unroll
                for (int j = 0; j < 4; j++) {
                    mem[i][j] = mem[i][j]*TAU + o[j]*SCALE;
                    s[j] = (mem[i][j] > THRESH) ? 1.f : 0.f;
                    if (mem[i][j] > THRESH) mem[i][j] = 0.f;
                }
                float4 sv; sv.x = s[0]; sv.y = s[1]; sv.z = s[2]; sv.w = s[3];
                *(float4*)&so[(size_t)(ty*4 + i) * Nn + n0 + tx*4] = sv;
            }
        }
    }
}

// =====================================================================
// launch
// =====================================================================
extern "C" void kernel_launch(void* const* d_in, const int* in_sizes, int n_in,
                              void* d_out, int out_size)
{
    const float* x     = (const float*)d_in[0];
    const float* wq    = (const float*)d_in[1];
    const float* wk    = (const float*)d_in[2];
    const float* wv    = (const float*)d_in[3];
    const float* wproj = (const float*)d_in[4];
    const float* bng   = (const float*)d_in[5];
    const float* bnb   = (const float*)d_in[6];
    const float* bnm   = (const float*)d_in[7];
    const float* bnv   = (const float*)d_in[8];
    float* out = (float*)d_out;

    const int conv_smem = 2 * STAGEB;   // 147,456 B
    cudaFuncSetAttribute(i8_conv, cudaFuncAttributeMaxDynamicSharedMemorySize, conv_smem);
    const int attn_smem = (4*64*64 + 2*64*68) * (int)sizeof(float);  // 100,352 B
    cudaFuncSetAttribute(attn_kernel, cudaFuncAttributeMaxDynamicSharedMemorySize, attn_smem);

    wquant_kernel<<<dim3(512, 4), 128>>>(wq, wk, wv, wproj);
    colmax_kernel<<<dim3(4, 64), 128>>>(x);
    xquant_t_kernel<<<dim3(16, 16, 64), 256>>>(x);

    // merged q,k,v conv_bn (M = 1536 stacked)
    i8_conv<<<dim3(4, 12, 64), 256, conv_smem>>>(out, bng, bnb, bnm, bnv, 0);

    lif_qkv_kernel<<<12288, 256>>>();

    attn_kernel<<<dim3(BpC, Hh), 256, attn_smem>>>();

    squant_t_kernel<<<dim3(16, 16, 64), 256>>>();

    // proj conv_bn
    i8_conv<<<dim3(4, 4, 64), 256, conv_smem>>>(out, bng, bnb, bnm, bnv, 1);
}

// round 10
// speedup vs baseline: 1.5292x; 1.5292x over previous
#include <cuda_runtime.h>
#include <cuda_bf16.h>
#include <cstdint>
#include <cstddef>

// ---------------- problem constants ----------------
#define Tt      4
#define Bt      64
#define BpC     16
#define Cc      512
#define Nn      512
#define Hh      8
#define GD      64
#define TAU     0.5f
#define THRESH  1.0f
#define SCALE   0.125f
#define EPSBN   1e-5f
#define SZ      (Bt*Cc*Nn)      // 16,777,216
#define CN      (Cc*Nn)

typedef unsigned long long ull;

// ---------------- scratch (device globals) ----------------
__device__ __align__(128) float g_pre[3ll*SZ];
__device__ __align__(128) float g_spk[3ll*SZ];
__device__ __align__(128) float g_so [SZ];
__device__ __align__(128) __nv_bfloat16 g_xhi[SZ];   // [b][n][c]
__device__ __align__(128) __nv_bfloat16 g_xlo[SZ];
__device__ __align__(128) __nv_bfloat16 g_shi[SZ];
__device__ __align__(128) __nv_bfloat16 g_whi[4ll*CN];
__device__ __align__(128) __nv_bfloat16 g_wlo[4ll*CN];

// ---------------- PTX helpers ----------------
static __device__ __forceinline__ uint32_t smem_u32(const void* p) {
    uint32_t a;
    asm("{ .reg .u64 t; cvta.to.shared.u64 t, %1; cvt.u32.u64 %0, t; }" : "=r"(a) : "l"(p));
    return a;
}
static __device__ __forceinline__ void cpasync16(uint32_t dst, const void* src) {
    asm volatile("cp.async.cg.shared.global [%0], [%1], 16;" :: "r"(dst), "l"(src));
}
#define CP_COMMIT()  asm volatile("cp.async.commit_group;" ::: "memory")
#define CP_WAIT(n)   asm volatile("cp.async.wait_group %0;" :: "n"(n) : "memory")

static __device__ __forceinline__ void ldm_x4(uint32_t* r, uint32_t addr) {
    asm volatile("ldmatrix.sync.aligned.m8n8.x4.shared.b16 {%0,%1,%2,%3}, [%4];"
        : "=r"(r[0]), "=r"(r[1]), "=r"(r[2]), "=r"(r[3]) : "r"(addr));
}
static __device__ __forceinline__ void mma16816(float* c, const uint32_t* a, const uint32_t* b) {
    asm volatile("mma.sync.aligned.m16n8k16.row.col.f32.bf16.bf16.f32 "
        "{%0,%1,%2,%3}, {%4,%5,%6,%7}, {%8,%9}, {%0,%1,%2,%3};"
        : "+f"(c[0]), "+f"(c[1]), "+f"(c[2]), "+f"(c[3])
        : "r"(a[0]), "r"(a[1]), "r"(a[2]), "r"(a[3]), "r"(b[0]), "r"(b[1]));
}

// ---------------- fp32x2 helpers ----------------
static __device__ __forceinline__ void ffma2(ull& d, ull a, ull b) {
    asm("fma.rn.f32x2 %0, %1, %2, %0;" : "+l"(d) : "l"(a), "l"(b));
}
static __device__ __forceinline__ ull bcast2(float w) {
    ull r; asm("mov.b64 %0, {%1, %1};" : "=l"(r) : "f"(w)); return r;
}
static __device__ __forceinline__ float2 unpack2(ull v) {
    float2 f; asm("mov.b64 {%0, %1}, %2;" : "=f"(f.x), "=f"(f.y) : "l"(v)); return f;
}

// =====================================================================
// weight split: fp32 [o][c] -> bf16 hi/lo
// =====================================================================
__global__ __launch_bounds__(256) void wsplit_kernel(
    const float* __restrict__ wq, const float* __restrict__ wk,
    const float* __restrict__ wv, const float* __restrict__ wp)
{
    const int which = blockIdx.y;
    const float* w = (which == 0) ? wq : (which == 1) ? wk : (which == 2) ? wv : wp;
    const int i = blockIdx.x * 256 + threadIdx.x;
    float v = w[i];
    __nv_bfloat16 h = __float2bfloat16(v);
    g_whi[(size_t)which * CN + i] = h;
    g_wlo[(size_t)which * CN + i] = __float2bfloat16(v - __bfloat162float(h));
}

// =====================================================================
// transpose + split: fp32 [b][c][n] -> bf16 [b][n][c]
// mode 0: x -> g_xhi/g_xlo.   mode 1: g_so -> g_shi (exact)
// =====================================================================
__global__ __launch_bounds__(256) void split_t_kernel(const float* __restrict__ in, int mode)
{
    __shared__ float t[32][33];
    const int b = blockIdx.z, c0 = blockIdx.y * 32, n0 = blockIdx.x * 32;
    const int tx = threadIdx.x, ty = threadIdx.y;
    const float* ib = (mode ? (const float*)g_so : in) + (size_t)b * CN;
    #pragma unroll
    for (int j = 0; j < 4; j++)
        t[ty + 8*j][tx] = ib[(size_t)(c0 + ty + 8*j) * Nn + n0 + tx];
    __syncthreads();
    #pragma unroll
    for (int j = 0; j < 4; j++) {
        const int n = ty + 8*j;
        const float v = t[tx][n];
        const __nv_bfloat16 h = __float2bfloat16(v);
        const size_t o = ((size_t)b * Nn + n0 + n) * Cc + c0 + tx;
        if (mode == 0) {
            g_xhi[o] = h;
            g_xlo[o] = __float2bfloat16(v - __bfloat162float(h));
        } else {
            g_shi[o] = h;
        }
    }
}

// =====================================================================
// DUAL-PIPE conv_bn: 128x128 output tile per CTA, K=512, + BN.
// Type selected per y-slab: HMMA (bf16 3/2-term, tensor pipe, KC=32
// double-buffered, term-major mma) or FFMA (exact fp32, fma pipe).
// smem request 81920B -> exactly 2 CTAs/SM; interleaved slab types give
// co-resident pairs opposite pipes.
// =====================================================================
#define AROWB   80                      // 32 bf16 = 64B + 16B pad
#define ATILE   (128*AROWB)             // 10240
#define ASTG    (4*ATILE)               // 40960 per stage
#define CONV_SMEM (2*ASTG)              // 81920

__global__ __launch_bounds__(256, 2) void conv_dual(
    float* __restrict__ extout, const float* __restrict__ x,
    const float* __restrict__ wq, const float* __restrict__ wk,
    const float* __restrict__ wv, const float* __restrict__ wp,
    const float* __restrict__ bng, const float* __restrict__ bnb,
    const float* __restrict__ bnm, const float* __restrict__ bnv,
    int mode)
{
    extern __shared__ char smem[];
    const int tid = threadIdx.x;
    const int y   = blockIdx.y;
    const int n0  = blockIdx.x * 128;
    const int b   = blockIdx.z;

    int wsel, r0;
    if (mode == 0) { wsel = y >> 2; r0 = (y & 3) * 128; }
    else           { wsel = 3;      r0 = y * 128; }
    const int terms = (mode == 0) ? 3 : 2;
    const bool isF  = (mode == 0) ? ((y % 3) == 1) : (y == 2);
    float* out = (mode == 0) ? (g_pre + (size_t)wsel * SZ) : extout;
    const int bnrow = wsel;

    if (!isF) {
        // ================= HMMA path (tensor pipe) =================
        const uint32_t sb = smem_u32(smem);
        const int wid = tid >> 5, lane = tid & 31;
        const int wm = wid & 1, wn = wid >> 1;
        const int grp = lane >> 3, wi = lane & 7;

        const __nv_bfloat16* wh = g_whi + (size_t)wsel * CN + (size_t)r0 * Cc;
        const __nv_bfloat16* wl = g_wlo + (size_t)wsel * CN + (size_t)r0 * Cc;
        const __nv_bfloat16* bh = ((mode == 0) ? g_xhi : g_shi) + ((size_t)b * Nn + n0) * Cc;
        const __nv_bfloat16* bl = g_xlo + ((size_t)b * Nn + n0) * Cc;

        const int lrow = tid >> 1;
        const int cb0  = (tid & 1) * 2;
        const uint32_t rowOff = (uint32_t)lrow * AROWB;
        const __nv_bfloat16* gAh = wh + (size_t)lrow * Cc;
        const __nv_bfloat16* gAl = wl + (size_t)lrow * Cc;
        const __nv_bfloat16* gBh = bh + (size_t)lrow * Cc;
        const __nv_bfloat16* gBl = bl + (size_t)lrow * Cc;

        float acc[4][4][4];
        #pragma unroll
        for (int i = 0; i < 4; i++)
            #pragma unroll
            for (int j = 0; j < 4; j++)
                #pragma unroll
                for (int q = 0; q < 4; q++) acc[i][j][q] = 0.f;

        auto load_stage = [&](uint32_t st, int k0) {
            #pragma unroll
            for (int j = 0; j < 2; j++) {
                const int c = cb0 + j;
                const uint32_t off = rowOff + c * 16;
                cpasync16(st + off,           gAh + k0 + c*8);
                cpasync16(st + ATILE + off,   gAl + k0 + c*8);
                cpasync16(st + 2*ATILE + off, gBh + k0 + c*8);
                if (terms == 3) cpasync16(st + 3*ATILE + off, gBl + k0 + c*8);
            }
        };

        load_stage(sb, 0);
        CP_COMMIT();

        for (int kc = 0; kc < 16; kc++) {      // K = 16 * 32
            const int s = kc & 1;
            if (kc < 15) {
                load_stage(sb + (s^1)*ASTG, (kc + 1) * 32);
                CP_COMMIT();
                CP_WAIT(1);
            } else {
                CP_WAIT(0);
            }
            __syncthreads();

            const uint32_t st = sb + s * ASTG;
            #pragma unroll
            for (int ks = 0; ks < 2; ks++) {   // 2 x k16 per stage
                uint32_t Ah[4][4], Al[4][4], Bh[4][2], Bl[4][2];
                #pragma unroll
                for (int mi = 0; mi < 4; mi++) {
                    const uint32_t ra = st
                        + (uint32_t)(wm*64 + mi*16 + wi + (grp&1)*8) * AROWB
                        + (uint32_t)(ks*32 + (grp>>1)*16);
                    ldm_x4(Ah[mi], ra);
                    ldm_x4(Al[mi], ra + ATILE);
                }
                #pragma unroll
                for (int bt = 0; bt < 2; bt++) {
                    const uint32_t rb = st + 2*ATILE
                        + (uint32_t)(wn*32 + bt*16 + wi + (grp>>1)*8) * AROWB
                        + (uint32_t)(ks*32 + (grp&1)*16);
                    uint32_t r[4];
                    ldm_x4(r, rb);
                    Bh[bt*2][0] = r[0]; Bh[bt*2][1] = r[1];
                    Bh[bt*2+1][0] = r[2]; Bh[bt*2+1][1] = r[3];
                    if (terms == 3) {
                        ldm_x4(r, rb + ATILE);
                        Bl[bt*2][0] = r[0]; Bl[bt*2][1] = r[1];
                        Bl[bt*2+1][0] = r[2]; Bl[bt*2+1][1] = r[3];
                    }
                }
                // term-major issue
                #pragma unroll
                for (int mi = 0; mi < 4; mi++)
                    #pragma unroll
                    for (int nt = 0; nt < 4; nt++)
                        mma16816(acc[mi][nt], Ah[mi], Bh[nt]);
                #pragma unroll
                for (int mi = 0; mi < 4; mi++)
                    #pragma unroll
                    for (int nt = 0; nt < 4; nt++)
                        mma16816(acc[mi][nt], Al[mi], Bh[nt]);
                if (terms == 3) {
                    #pragma unroll
                    for (int mi = 0; mi < 4; mi++)
                        #pragma unroll
                        for (int nt = 0; nt < 4; nt++)
                            mma16816(acc[mi][nt], Ah[mi], Bl[nt]);
                }
            }
            __syncthreads();
        }

        // epilogue: BN affine + fp32 store
        #pragma unroll
        for (int mi = 0; mi < 4; mi++) {
            const int rA = r0 + wm*64 + mi*16 + (lane >> 2);
            const int rB = rA + 8;
            const float invA  = bng[bnrow*Cc + rA] / sqrtf(bnv[bnrow*Cc + rA] + EPSBN);
            const float biasA = bnb[bnrow*Cc + rA] - bnm[bnrow*Cc + rA] * invA;
            const float invB  = bng[bnrow*Cc + rB] / sqrtf(bnv[bnrow*Cc + rB] + EPSBN);
            const float biasB = bnb[bnrow*Cc + rB] - bnm[bnrow*Cc + rB] * invB;
            float* pA = out + ((size_t)b * Cc + rA) * Nn + n0;
            float* pB = out + ((size_t)b * Cc + rB) * Nn + n0;
            #pragma unroll
            for (int nt = 0; nt < 4; nt++) {
                const int nc = wn*32 + nt*8 + (lane & 3)*2;
                float2 v0, v1;
                v0.x = acc[mi][nt][0]*invA + biasA;
                v0.y = acc[mi][nt][1]*invA + biasA;
                v1.x = acc[mi][nt][2]*invB + biasB;
                v1.y = acc[mi][nt][3]*invB + biasB;
                *(float2*)&pA[nc] = v0;
                *(float2*)&pB[nc] = v1;
            }
        }
    } else {
        // ================= FFMA path (fma pipe, exact fp32) =================
        float* Ws = (float*)smem;                 // [2][8][132]
        float* Xs = Ws + 2*8*132;                 // [2][8][128]
        const float* wf = (wsel == 0) ? wq : (wsel == 1) ? wk : (wsel == 2) ? wv : wp;
        const float* inb = ((mode == 0) ? x : (const float*)g_so) + (size_t)b * CN;

        const int ty = tid >> 4, tx = tid & 15;
        const int wm = tid >> 1, wk4 = (tid & 1) * 4;
        const int xk = tid >> 5, xq = (tid & 31) * 4;

        ull acc[8][4];
        #pragma unroll
        for (int i = 0; i < 8; i++)
            #pragma unroll
            for (int p = 0; p < 4; p++) acc[i][p] = 0ull;

        float4 rW = *(const float4*)&wf[(size_t)(r0 + wm) * Cc + wk4];
        float4 rX = *(const float4*)&inb[(size_t)xk * Nn + n0 + xq];
        Ws[(wk4+0)*132 + wm] = rW.x; Ws[(wk4+1)*132 + wm] = rW.y;
        Ws[(wk4+2)*132 + wm] = rW.z; Ws[(wk4+3)*132 + wm] = rW.w;
        *(float4*)&Xs[xk*128 + xq] = rX;

        for (int it = 0; it < 64; it++) {
            __syncthreads();
            const int s = it & 1;
            if (it + 1 < 64) {
                const int k0 = (it + 1) * 8;
                rW = *(const float4*)&wf[(size_t)(r0 + wm) * Cc + k0 + wk4];
                rX = *(const float4*)&inb[(size_t)(k0 + xk) * Nn + n0 + xq];
            }
            float* Wss = Ws + s*8*132;
            float* Xss = Xs + s*8*128;
            #pragma unroll
            for (int kk = 0; kk < 8; kk++) {
                float4 wa = *(const float4*)&Wss[kk*132 + ty*8];
                float4 wb = *(const float4*)&Wss[kk*132 + ty*8 + 4];
                ulonglong2 xA = *(const ulonglong2*)&Xss[kk*128 + tx*8];
                ulonglong2 xB = *(const ulonglong2*)&Xss[kk*128 + tx*8 + 4];
                const ull xs0 = xA.x, xs1 = xA.y, xs2 = xB.x, xs3 = xB.y;
                float wr[8] = {wa.x, wa.y, wa.z, wa.w, wb.x, wb.y, wb.z, wb.w};
                #pragma unroll
                for (int i = 0; i < 8; i++) {
                    ull wb2 = bcast2(wr[i]);
                    ffma2(acc[i][0], wb2, xs0);
                    ffma2(acc[i][1], wb2, xs1);
                    ffma2(acc[i][2], wb2, xs2);
                    ffma2(acc[i][3], wb2, xs3);
                }
            }
            if (it + 1 < 64) {
                float* Wsd = Ws + (s^1)*8*132;
                float* Xsd = Xs + (s^1)*8*128;
                Wsd[(wk4+0)*132 + wm] = rW.x; Wsd[(wk4+1)*132 + wm] = rW.y;
                Wsd[(wk4+2)*132 + wm] = rW.z; Wsd[(wk4+3)*132 + wm] = rW.w;
                *(float4*)&Xsd[xk*128 + xq] = rX;
            }
        }

        #pragma unroll
        for (int i = 0; i < 8; i++) {
            const int r = r0 + ty*8 + i;
            const float inv  = bng[bnrow*Cc + r] / sqrtf(bnv[bnrow*Cc + r] + EPSBN);
            const float bias = bnb[bnrow*Cc + r] - bnm[bnrow*Cc + r] * inv;
            float2 p0 = unpack2(acc[i][0]), p1 = unpack2(acc[i][1]);
            float2 p2 = unpack2(acc[i][2]), p3 = unpack2(acc[i][3]);
            float4 o0, o1;
            o0.x = p0.x*inv + bias; o0.y = p0.y*inv + bias;
            o0.z = p1.x*inv + bias; o0.w = p1.y*inv + bias;
            o1.x = p2.x*inv + bias; o1.y = p2.y*inv + bias;
            o1.z = p3.x*inv + bias; o1.w = p3.y*inv + bias;
            *(float4*)&out[((size_t)b * Cc + r) * Nn + n0 + tx*8]     = o0;
            *(float4*)&out[((size_t)b * Cc + r) * Nn + n0 + tx*8 + 4] = o1;
        }
    }
}

// =====================================================================
// LIF over T for q/k/v pre-activations
// =====================================================================
__global__ __launch_bounds__(256) void lif_qkv_kernel()
{
    const int idx = blockIdx.x * 256 + threadIdx.x;
    const int q   = idx & 127;
    const int c   = (idx >> 7) & 511;
    const int bp  = (idx >> 16) & 15;
    const int sel = idx >> 20;

    const float* pre = g_pre + (size_t)sel * SZ;
    float*       spk = g_spk + (size_t)sel * SZ;

    float4 mem = {0.f, 0.f, 0.f, 0.f};
    #pragma unroll
    for (int t = 0; t < 4; t++) {
        const size_t off = (((size_t)(t*BpC + bp) * Cc + c) * Nn) + q*4;
        float4 v = *(const float4*)&pre[off];
        float4 s;
        mem.x = mem.x*TAU + v.x; s.x = (mem.x > THRESH) ? 1.f : 0.f; if (mem.x > THRESH) mem.x = 0.f;
        mem.y = mem.y*TAU + v.y; s.y = (mem.y > THRESH) ? 1.f : 0.f; if (mem.y > THRESH) mem.y = 0.f;
        mem.z = mem.z*TAU + v.z; s.z = (mem.z > THRESH) ? 1.f : 0.f; if (mem.z > THRESH) mem.z = 0.f;
        mem.w = mem.w*TAU + v.w; s.w = (mem.w > THRESH) ? 1.f : 0.f; if (mem.w > THRESH) mem.w = 0.f;
        *(float4*)&spk[off] = s;
    }
}

// =====================================================================
// Attention (reassociated) + LIF, fused per (b', h)
// =====================================================================
__global__ __launch_bounds__(256) void attn_kernel()
{
    extern __shared__ __align__(16) float sm[];
    float* Ms = sm;
    float* Sa = sm + 4*64*64;
    float* Sb = Sa + 64*68;

    const int bp = blockIdx.x;
    const int h  = blockIdx.y;
    const int tid = threadIdx.x;
    const int ty = tid >> 4, tx = tid & 15;
    const int sRow = tid >> 2;
    const int sCol = (tid & 3) * 4;

    for (int t = 0; t < 4; t++) {
        const int b = t*BpC + bp;
        const float* K = g_spk + (size_t)SZ   + ((size_t)b*Cc + h*GD) * Nn;
        const float* V = g_spk + (size_t)2*SZ + ((size_t)b*Cc + h*GD) * Nn;

        ull accM[4][2];
        #pragma unroll
        for (int i = 0; i < 4; i++) { accM[i][0] = 0ull; accM[i][1] = 0ull; }

        for (int m0 = 0; m0 < Nn; m0 += 64) {
            float4 kv[4], vv[4];
            #pragma unroll
            for (int j = 0; j < 4; j++) {
                kv[j] = *(const float4*)&K[(size_t)sRow * Nn + m0 + sCol + 16*j];
                vv[j] = *(const float4*)&V[(size_t)sRow * Nn + m0 + sCol + 16*j];
            }
            __syncthreads();
            #pragma unroll
            for (int j = 0; j < 4; j++) {
                const int m = sCol + 16*j;
                Sa[(m+0)*68 + sRow] = kv[j].x; Sa[(m+1)*68 + sRow] = kv[j].y;
                Sa[(m+2)*68 + sRow] = kv[j].z; Sa[(m+3)*68 + sRow] = kv[j].w;
                Sb[(m+0)*68 + sRow] = vv[j].x; Sb[(m+1)*68 + sRow] = vv[j].y;
                Sb[(m+2)*68 + sRow] = vv[j].z; Sb[(m+3)*68 + sRow] = vv[j].w;
            }
            __syncthreads();
            #pragma unroll 8
            for (int mm = 0; mm < 64; mm++) {
                float4 ka = *(const float4*)&Sa[mm*68 + ty*4];
                ulonglong2 vp = *(const ulonglong2*)&Sb[mm*68 + tx*4];
                const float kf[4] = {ka.x, ka.y, ka.z, ka.w};
                #pragma unroll
                for (int i = 0; i < 4; i++) {
                    ull kb = bcast2(kf[i]);
                    ffma2(accM[i][0], kb, vp.x);
                    ffma2(accM[i][1], kb, vp.y);
                }
            }
        }
        #pragma unroll
        for (int i = 0; i < 4; i++) {
            float2 a = unpack2(accM[i][0]);
            float2 c2 = unpack2(accM[i][1]);
            float4 mo; mo.x = a.x; mo.y = a.y; mo.z = c2.x; mo.w = c2.y;
            *(float4*)&Ms[t*4096 + (ty*4 + i)*64 + tx*4] = mo;
        }
    }
    __syncthreads();

    for (int n0 = 0; n0 < Nn; n0 += 64) {
        float mem[4][4];
        #pragma unroll
        for (int i = 0; i < 4; i++)
            #pragma unroll
            for (int j = 0; j < 4; j++) mem[i][j] = 0.f;

        for (int t = 0; t < 4; t++) {
            const int b = t*BpC + bp;
            const float* Q = g_spk + ((size_t)b*Cc + h*GD) * Nn;
            float4 qv[4];
            #pragma unroll
            for (int j = 0; j < 4; j++)
                qv[j] = *(const float4*)&Q[(size_t)sRow * Nn + n0 + sCol + 16*j];
            __syncthreads();
            #pragma unroll
            for (int j = 0; j < 4; j++)
                *(float4*)&Sa[sRow*68 + sCol + 16*j] = qv[j];
            __syncthreads();

            ull acc[4][2];
            #pragma unroll
            for (int i = 0; i < 4; i++) { acc[i][0] = 0ull; acc[i][1] = 0ull; }

            #pragma unroll 8
            for (int dk = 0; dk < 64; dk++) {
                float4 mv = *(const float4*)&Ms[t*4096 + dk*64 + ty*4];
                ulonglong2 qp = *(const ulonglong2*)&Sa[dk*68 + tx*4];
                const float mf[4] = {mv.x, mv.y, mv.z, mv.w};
                #pragma unroll
                for (int i = 0; i < 4; i++) {
                    ull mb = bcast2(mf[i]);
                    ffma2(acc[i][0], mb, qp.x);
                    ffma2(acc[i][1], mb, qp.y);
                }
            }

            float* so = g_so + ((size_t)b*Cc + h*GD) * Nn;
            #pragma unroll
            for (int i = 0; i < 4; i++) {
                float2 a = unpack2(acc[i][0]);
                float2 c2 = unpack2(acc[i][1]);
                float o[4] = {a.x, a.y, c2.x, c2.y};
                float s[4];
                #pragma unroll
                for (int j = 0; j < 4; j++) {
                    mem[i][j] = mem[i][j]*TAU + o[j]*SCALE;
                    s[j] = (mem[i][j] > THRESH) ? 1.f : 0.f;
                    if (mem[i][j] > THRESH) mem[i][j] = 0.f;
                }
                float4 sv; sv.x = s[0]; sv.y = s[1]; sv.z = s[2]; sv.w = s[3];
                *(float4*)&so[(size_t)(ty*4 + i) * Nn + n0 + tx*4] = sv;
            }
        }
    }
}

// =====================================================================
// launch
// =====================================================================
extern "C" void kernel_launch(void* const* d_in, const int* in_sizes, int n_in,
                              void* d_out, int out_size)
{
    const float* x     = (const float*)d_in[0];
    const float* wq    = (const float*)d_in[1];
    const float* wk    = (const float*)d_in[2];
    const float* wv    = (const float*)d_in[3];
    const float* wproj = (const float*)d_in[4];
    const float* bng   = (const float*)d_in[5];
    const float* bnb   = (const float*)d_in[6];
    const float* bnm   = (const float*)d_in[7];
    const float* bnv   = (const float*)d_in[8];
    float* out = (float*)d_out;

    cudaFuncSetAttribute(conv_dual, cudaFuncAttributeMaxDynamicSharedMemorySize, CONV_SMEM);
    const int attn_smem = (4*64*64 + 2*64*68) * (int)sizeof(float);  // 100,352 B
    cudaFuncSetAttribute(attn_kernel, cudaFuncAttributeMaxDynamicSharedMemorySize, attn_smem);

    wsplit_kernel<<<dim3(1024, 4), 256>>>(wq, wk, wv, wproj);
    split_t_kernel<<<dim3(16, 16, 64), dim3(32, 8)>>>(x, 0);

    // merged q,k,v conv_bn (M = 1536 stacked), dual-pipe by y-slab
    conv_dual<<<dim3(4, 12, 64), 256, CONV_SMEM>>>(out, x, wq, wk, wv, wproj,
                                                   bng, bnb, bnm, bnv, 0);

    lif_qkv_kernel<<<12288, 256>>>();

    attn_kernel<<<dim3(BpC, Hh), 256, attn_smem>>>();

    split_t_kernel<<<dim3(16, 16, 64), dim3(32, 8)>>>(x, 1);   // g_so -> g_shi

    // proj conv_bn, dual-pipe
    conv_dual<<<dim3(4, 4, 64), 256, CONV_SMEM>>>(out, x, wq, wk, wv, wproj,
                                                  bng, bnb, bnm, bnv, 1);
}

// round 11
// speedup vs baseline: 1.6671x; 1.0902x over previous
#include <cuda_runtime.h>
#include <cuda_bf16.h>
#include <cuda_fp16.h>
#include <cstdint>
#include <cstddef>

// ---------------- problem constants ----------------
#define Tt      4
#define Bt      64
#define BpC     16
#define Cc      512
#define Nn      512
#define Hh      8
#define GD      64
#define TAU     0.5f
#define THRESH  1.0f
#define SCALE   0.125f
#define EPSBN   1e-5f
#define SZ      (Bt*Cc*Nn)      // 16,777,216
#define CN      (Cc*Nn)

typedef unsigned long long ull;

// ---------------- scratch (device globals) ----------------
__device__ __align__(128) float g_pre[3ll*SZ];
__device__ __align__(128) float g_spk[3ll*SZ];
__device__ __align__(128) float g_so [SZ];
__device__ __align__(128) __nv_bfloat16 g_xhi[SZ];   // [b][n][c]
__device__ __align__(128) __nv_bfloat16 g_xlo[SZ];
__device__ __align__(128) __half        g_s16[SZ];   // spikes fp16 [b][n][c]
__device__ __align__(128) __nv_bfloat16 g_whi[3ll*CN];
__device__ __align__(128) __nv_bfloat16 g_wlo[3ll*CN];
__device__ __align__(128) __half        g_wp16[CN];  // proj weights fp16

// ---------------- PTX helpers ----------------
static __device__ __forceinline__ uint32_t smem_u32(const void* p) {
    uint32_t a;
    asm("{ .reg .u64 t; cvta.to.shared.u64 t, %1; cvt.u32.u64 %0, t; }" : "=r"(a) : "l"(p));
    return a;
}
static __device__ __forceinline__ void cpasync16(uint32_t dst, const void* src) {
    asm volatile("cp.async.cg.shared.global [%0], [%1], 16;" :: "r"(dst), "l"(src));
}
#define CP_COMMIT()  asm volatile("cp.async.commit_group;" ::: "memory")
#define CP_WAIT(n)   asm volatile("cp.async.wait_group %0;" :: "n"(n) : "memory")

static __device__ __forceinline__ void ldm_x4(uint32_t* r, uint32_t addr) {
    asm volatile("ldmatrix.sync.aligned.m8n8.x4.shared.b16 {%0,%1,%2,%3}, [%4];"
        : "=r"(r[0]), "=r"(r[1]), "=r"(r[2]), "=r"(r[3]) : "r"(addr));
}
static __device__ __forceinline__ void mma_bf16(float* c, const uint32_t* a, const uint32_t* b) {
    asm volatile("mma.sync.aligned.m16n8k16.row.col.f32.bf16.bf16.f32 "
        "{%0,%1,%2,%3}, {%4,%5,%6,%7}, {%8,%9}, {%0,%1,%2,%3};"
        : "+f"(c[0]), "+f"(c[1]), "+f"(c[2]), "+f"(c[3])
        : "r"(a[0]), "r"(a[1]), "r"(a[2]), "r"(a[3]), "r"(b[0]), "r"(b[1]));
}
static __device__ __forceinline__ void mma_f16(float* c, const uint32_t* a, const uint32_t* b) {
    asm volatile("mma.sync.aligned.m16n8k16.row.col.f32.f16.f16.f32 "
        "{%0,%1,%2,%3}, {%4,%5,%6,%7}, {%8,%9}, {%0,%1,%2,%3};"
        : "+f"(c[0]), "+f"(c[1]), "+f"(c[2]), "+f"(c[3])
        : "r"(a[0]), "r"(a[1]), "r"(a[2]), "r"(a[3]), "r"(b[0]), "r"(b[1]));
}

// ---------------- fp32x2 helpers (attn kernel) ----------------
static __device__ __forceinline__ void ffma2(ull& d, ull a, ull b) {
    asm("fma.rn.f32x2 %0, %1, %2, %0;" : "+l"(d) : "l"(a), "l"(b));
}
static __device__ __forceinline__ ull bcast2(float w) {
    ull r; asm("mov.b64 %0, {%1, %1};" : "=l"(r) : "f"(w)); return r;
}
static __device__ __forceinline__ float2 unpack2(ull v) {
    float2 f; asm("mov.b64 {%0, %1}, %2;" : "=f"(f.x), "=f"(f.y) : "l"(v)); return f;
}

// =====================================================================
// weight split: qkv -> bf16 hi/lo; proj -> fp16 single
// =====================================================================
__global__ __launch_bounds__(256) void wsplit_kernel(
    const float* __restrict__ wq, const float* __restrict__ wk,
    const float* __restrict__ wv, const float* __restrict__ wp)
{
    const int which = blockIdx.y;
    const float* w = (which == 0) ? wq : (which == 1) ? wk : (which == 2) ? wv : wp;
    const int i = blockIdx.x * 256 + threadIdx.x;
    float v = w[i];
    if (which < 3) {
        __nv_bfloat16 h = __float2bfloat16(v);
        g_whi[(size_t)which * CN + i] = h;
        g_wlo[(size_t)which * CN + i] = __float2bfloat16(v - __bfloat162float(h));
    } else {
        g_wp16[i] = __float2half(v);
    }
}

// =====================================================================
// transpose + split: fp32 [b][c][n] -> [b][n][c]
// mode 0: x -> g_xhi/g_xlo (bf16).  mode 1: g_so spikes -> g_s16 (fp16, exact)
// =====================================================================
__global__ __launch_bounds__(256) void split_t_kernel(const float* __restrict__ in, int mode)
{
    __shared__ float t[32][33];
    const int b = blockIdx.z, c0 = blockIdx.y * 32, n0 = blockIdx.x * 32;
    const int tx = threadIdx.x, ty = threadIdx.y;
    const float* ib = (mode ? (const float*)g_so : in) + (size_t)b * CN;
    #pragma unroll
    for (int j = 0; j < 4; j++)
        t[ty + 8*j][tx] = ib[(size_t)(c0 + ty + 8*j) * Nn + n0 + tx];
    __syncthreads();
    #pragma unroll
    for (int j = 0; j < 4; j++) {
        const int n = ty + 8*j;
        const float v = t[tx][n];
        const size_t o = ((size_t)b * Nn + n0 + n) * Cc + c0 + tx;
        if (mode == 0) {
            const __nv_bfloat16 h = __float2bfloat16(v);
            g_xhi[o] = h;
            g_xlo[o] = __float2bfloat16(v - __bfloat162float(h));
        } else {
            g_s16[o] = __float2half(v);
        }
    }
}

// =====================================================================
// qkv HMMA conv_bn (R8 proven): D[128m x 128n] = W @ X^T, K=512, + BN
// bf16 3-term split, term-major mma issue, cp.async double buffer
// grid (4 ntiles, 12 slabs, 64 b)
// =====================================================================
#define ROWB   144
#define TILEB  (128*ROWB)
#define STAGEB (4*TILEB)

__global__ __launch_bounds__(256) void hmma_conv(
    const float* __restrict__ bng, const float* __restrict__ bnb,
    const float* __restrict__ bnm, const float* __restrict__ bnv)
{
    extern __shared__ char smem[];
    const uint32_t sb = smem_u32(smem);
    const int tid  = threadIdx.x;
    const int wid  = tid >> 5, lane = tid & 31;
    const int n0   = blockIdx.x * 128;
    const int b    = blockIdx.z;
    const int wsel = blockIdx.y >> 2;
    const int r0   = (blockIdx.y & 3) * 128;

    float* out = g_pre + (size_t)wsel * SZ;
    const __nv_bfloat16* wh = g_whi + (size_t)wsel * CN + (size_t)r0 * Cc;
    const __nv_bfloat16* wl = g_wlo + (size_t)wsel * CN + (size_t)r0 * Cc;
    const __nv_bfloat16* bh = g_xhi + ((size_t)b * Nn + n0) * Cc;
    const __nv_bfloat16* bl = g_xlo + ((size_t)b * Nn + n0) * Cc;

    const int lrow = tid >> 1;
    const int cb0  = (tid & 1) * 4;
    const uint32_t rowOff = (uint32_t)lrow * ROWB;
    const __nv_bfloat16* gAh = wh + (size_t)lrow * Cc;
    const __nv_bfloat16* gAl = wl + (size_t)lrow * Cc;
    const __nv_bfloat16* gBh = bh + (size_t)lrow * Cc;
    const __nv_bfloat16* gBl = bl + (size_t)lrow * Cc;

    float acc[4][4][4];
    #pragma unroll
    for (int i = 0; i < 4; i++)
        #pragma unroll
        for (int j = 0; j < 4; j++)
            #pragma unroll
            for (int q = 0; q < 4; q++) acc[i][j][q] = 0.f;

    const int wm = wid & 1, wn = wid >> 1;
    const int grp = lane >> 3, wi = lane & 7;

    auto load_stage = [&](uint32_t st, int k0) {
        #pragma unroll
        for (int j = 0; j < 4; j++) {
            const int c = cb0 + j;
            const uint32_t off = rowOff + c * 16;
            cpasync16(st + off,           gAh + k0 + c*8);
            cpasync16(st + TILEB + off,   gAl + k0 + c*8);
            cpasync16(st + 2*TILEB + off, gBh + k0 + c*8);
            cpasync16(st + 3*TILEB + off, gBl + k0 + c*8);
        }
    };

    load_stage(sb, 0);
    CP_COMMIT();

    for (int kc = 0; kc < 8; kc++) {
        const int s = kc & 1;
        if (kc < 7) {
            load_stage(sb + (s^1)*STAGEB, (kc + 1) * 64);
            CP_COMMIT();
            CP_WAIT(1);
        } else {
            CP_WAIT(0);
        }
        __syncthreads();

        const uint32_t st = sb + s * STAGEB;
        #pragma unroll
        for (int ks = 0; ks < 4; ks++) {
            uint32_t Ah[4][4], Al[4][4], Bh[4][2], Bl[4][2];
            #pragma unroll
            for (int mi = 0; mi < 4; mi++) {
                const uint32_t ra = st
                    + (uint32_t)(wm*64 + mi*16 + wi + (grp&1)*8) * ROWB
                    + (uint32_t)(ks*32 + (grp>>1)*16);
                ldm_x4(Ah[mi], ra);
                ldm_x4(Al[mi], ra + TILEB);
            }
            #pragma unroll
            for (int bt = 0; bt < 2; bt++) {
                const uint32_t rb = st + 2*TILEB
                    + (uint32_t)(wn*32 + bt*16 + wi + (grp>>1)*8) * ROWB
                    + (uint32_t)(ks*32 + (grp&1)*16);
                uint32_t r[4];
                ldm_x4(r, rb);
                Bh[bt*2][0] = r[0]; Bh[bt*2][1] = r[1];
                Bh[bt*2+1][0] = r[2]; Bh[bt*2+1][1] = r[3];
                ldm_x4(r, rb + TILEB);
                Bl[bt*2][0] = r[0]; Bl[bt*2][1] = r[1];
                Bl[bt*2+1][0] = r[2]; Bl[bt*2+1][1] = r[3];
            }
            // term-major issue: 16 independent mmas per pass
            #pragma unroll
            for (int mi = 0; mi < 4; mi++)
                #pragma unroll
                for (int nt = 0; nt < 4; nt++)
                    mma_bf16(acc[mi][nt], Ah[mi], Bh[nt]);
            #pragma unroll
            for (int mi = 0; mi < 4; mi++)
                #pragma unroll
                for (int nt = 0; nt < 4; nt++)
                    mma_bf16(acc[mi][nt], Al[mi], Bh[nt]);
            #pragma unroll
            for (int mi = 0; mi < 4; mi++)
                #pragma unroll
                for (int nt = 0; nt < 4; nt++)
                    mma_bf16(acc[mi][nt], Ah[mi], Bl[nt]);
        }
        __syncthreads();
    }

    // epilogue: BN affine + fp32 store
    #pragma unroll
    for (int mi = 0; mi < 4; mi++) {
        const int rA = r0 + wm*64 + mi*16 + (lane >> 2);
        const int rB = rA + 8;
        const float invA  = bng[wsel*Cc + rA] / sqrtf(bnv[wsel*Cc + rA] + EPSBN);
        const float biasA = bnb[wsel*Cc + rA] - bnm[wsel*Cc + rA] * invA;
        const float invB  = bng[wsel*Cc + rB] / sqrtf(bnv[wsel*Cc + rB] + EPSBN);
        const float biasB = bnb[wsel*Cc + rB] - bnm[wsel*Cc + rB] * invB;
        float* pA = out + ((size_t)b * Cc + rA) * Nn + n0;
        float* pB = out + ((size_t)b * Cc + rB) * Nn + n0;
        #pragma unroll
        for (int nt = 0; nt < 4; nt++) {
            const int nc = wn*32 + nt*8 + (lane & 3)*2;
            float2 v0, v1;
            v0.x = acc[mi][nt][0]*invA + biasA;
            v0.y = acc[mi][nt][1]*invA + biasA;
            v1.x = acc[mi][nt][2]*invB + biasB;
            v1.y = acc[mi][nt][3]*invB + biasB;
            *(float2*)&pA[nc] = v0;
            *(float2*)&pB[nc] = v1;
        }
    }
}

// =====================================================================
// proj conv_bn: fp16 SINGLE-term (spikes exact in fp16; W error 2^-12,
// no downstream LIF). 2 smem planes, 2 CTAs/SM. grid (4, 4, 64)
// =====================================================================
#define PTILE  (128*ROWB)               // 18432
#define PSTG   (2*PTILE)                // 36864
#define PROJ_SMEM (2*PSTG)              // 73728

__global__ __launch_bounds__(256, 2) void proj_conv(
    float* __restrict__ extout,
    const float* __restrict__ bng, const float* __restrict__ bnb,
    const float* __restrict__ bnm, const float* __restrict__ bnv)
{
    extern __shared__ char smem[];
    const uint32_t sb = smem_u32(smem);
    const int tid  = threadIdx.x;
    const int wid  = tid >> 5, lane = tid & 31;
    const int n0   = blockIdx.x * 128;
    const int r0   = blockIdx.y * 128;
    const int b    = blockIdx.z;

    const __half* wp = g_wp16 + (size_t)r0 * Cc;
    const __half* sp = g_s16 + ((size_t)b * Nn + n0) * Cc;

    const int lrow = tid >> 1;
    const int cb0  = (tid & 1) * 4;
    const uint32_t rowOff = (uint32_t)lrow * ROWB;
    const __half* gA = wp + (size_t)lrow * Cc;
    const __half* gB = sp + (size_t)lrow * Cc;

    float acc[4][4][4];
    #pragma unroll
    for (int i = 0; i < 4; i++)
        #pragma unroll
        for (int j = 0; j < 4; j++)
            #pragma unroll
            for (int q = 0; q < 4; q++) acc[i][j][q] = 0.f;

    const int wm = wid & 1, wn = wid >> 1;
    const int grp = lane >> 3, wi = lane & 7;

    auto load_stage = [&](uint32_t st, int k0) {
        #pragma unroll
        for (int j = 0; j < 4; j++) {
            const int c = cb0 + j;
            const uint32_t off = rowOff + c * 16;
            cpasync16(st + off,         gA + k0 + c*8);
            cpasync16(st + PTILE + off, gB + k0 + c*8);
        }
    };

    load_stage(sb, 0);
    CP_COMMIT();

    for (int kc = 0; kc < 8; kc++) {
        const int s = kc & 1;
        if (kc < 7) {
            load_stage(sb + (s^1)*PSTG, (kc + 1) * 64);
            CP_COMMIT();
            CP_WAIT(1);
        } else {
            CP_WAIT(0);
        }
        __syncthreads();

        const uint32_t st = sb + s * PSTG;
        #pragma unroll
        for (int ks = 0; ks < 4; ks++) {
            uint32_t A[4][4], B[4][2];
            #pragma unroll
            for (int mi = 0; mi < 4; mi++) {
                const uint32_t ra = st
                    + (uint32_t)(wm*64 + mi*16 + wi + (grp&1)*8) * ROWB
                    + (uint32_t)(ks*32 + (grp>>1)*16);
                ldm_x4(A[mi], ra);
            }
            #pragma unroll
            for (int bt = 0; bt < 2; bt++) {
                const uint32_t rb = st + PTILE
                    + (uint32_t)(wn*32 + bt*16 + wi + (grp>>1)*8) * ROWB
                    + (uint32_t)(ks*32 + (grp&1)*16);
                uint32_t r[4];
                ldm_x4(r, rb);
                B[bt*2][0] = r[0]; B[bt*2][1] = r[1];
                B[bt*2+1][0] = r[2]; B[bt*2+1][1] = r[3];
            }
            #pragma unroll
            for (int mi = 0; mi < 4; mi++)
                #pragma unroll
                for (int nt = 0; nt < 4; nt++)
                    mma_f16(acc[mi][nt], A[mi], B[nt]);
        }
        __syncthreads();
    }

    // epilogue: BN affine + fp32 store (bn row 3)
    #pragma unroll
    for (int mi = 0; mi < 4; mi++) {
        const int rA = r0 + wm*64 + mi*16 + (lane >> 2);
        const int rB = rA + 8;
        const float invA  = bng[3*Cc + rA] / sqrtf(bnv[3*Cc + rA] + EPSBN);
        const float biasA = bnb[3*Cc + rA] - bnm[3*Cc + rA] * invA;
        const float invB  = bng[3*Cc + rB] / sqrtf(bnv[3*Cc + rB] + EPSBN);
        const float biasB = bnb[3*Cc + rB] - bnm[3*Cc + rB] * invB;
        float* pA = extout + ((size_t)b * Cc + rA) * Nn + n0;
        float* pB = extout + ((size_t)b * Cc + rB) * Nn + n0;
        #pragma unroll
        for (int nt = 0; nt < 4; nt++) {
            const int nc = wn*32 + nt*8 + (lane & 3)*2;
            float2 v0, v1;
            v0.x = acc[mi][nt][0]*invA + biasA;
            v0.y = acc[mi][nt][1]*invA + biasA;
            v1.x = acc[mi][nt][2]*invB + biasB;
            v1.y = acc[mi][nt][3]*invB + biasB;
            *(float2*)&pA[nc] = v0;
            *(float2*)&pB[nc] = v1;
        }
    }
}

// =====================================================================
// LIF over T for q/k/v pre-activations
// =====================================================================
__global__ __launch_bounds__(256) void lif_qkv_kernel()
{
    const int idx = blockIdx.x * 256 + threadIdx.x;
    const int q   = idx & 127;
    const int c   = (idx >> 7) & 511;
    const int bp  = (idx >> 16) & 15;
    const int sel = idx >> 20;

    const float* pre = g_pre + (size_t)sel * SZ;
    float*       spk = g_spk + (size_t)sel * SZ;

    float4 mem = {0.f, 0.f, 0.f, 0.f};
    #pragma unroll
    for (int t = 0; t < 4; t++) {
        const size_t off = (((size_t)(t*BpC + bp) * Cc + c) * Nn) + q*4;
        float4 v = *(const float4*)&pre[off];
        float4 s;
        mem.x = mem.x*TAU + v.x; s.x = (mem.x > THRESH) ? 1.f : 0.f; if (mem.x > THRESH) mem.x = 0.f;
        mem.y = mem.y*TAU + v.y; s.y = (mem.y > THRESH) ? 1.f : 0.f; if (mem.y > THRESH) mem.y = 0.f;
        mem.z = mem.z*TAU + v.z; s.z = (mem.z > THRESH) ? 1.f : 0.f; if (mem.z > THRESH) mem.z = 0.f;
        mem.w = mem.w*TAU + v.w; s.w = (mem.w > THRESH) ? 1.f : 0.f; if (mem.w > THRESH) mem.w = 0.f;
        *(float4*)&spk[off] = s;
    }
}

// =====================================================================
// Attention (reassociated) + LIF, fused per (b', h, nquarter)
// grid (16, 8, 4): each CTA recomputes M (cheap) and handles 128 n
// =====================================================================
__global__ __launch_bounds__(256) void attn_kernel()
{
    extern __shared__ __align__(16) float sm[];
    float* Ms = sm;
    float* Sa = sm + 4*64*64;
    float* Sb = Sa + 64*68;

    const int bp = blockIdx.x;
    const int h  = blockIdx.y;
    const int nzq = blockIdx.z;          // 0..3 -> n range [nzq*128, +128)
    const int tid = threadIdx.x;
    const int ty = tid >> 4, tx = tid & 15;
    const int sRow = tid >> 2;
    const int sCol = (tid & 3) * 4;

    for (int t = 0; t < 4; t++) {
        const int b = t*BpC + bp;
        const float* K = g_spk + (size_t)SZ   + ((size_t)b*Cc + h*GD) * Nn;
        const float* V = g_spk + (size_t)2*SZ + ((size_t)b*Cc + h*GD) * Nn;

        ull accM[4][2];
        #pragma unroll
        for (int i = 0; i < 4; i++) { accM[i][0] = 0ull; accM[i][1] = 0ull; }

        for (int m0 = 0; m0 < Nn; m0 += 64) {
            float4 kv[4], vv[4];
            #pragma unroll
            for (int j = 0; j < 4; j++) {
                kv[j] = *(const float4*)&K[(size_t)sRow * Nn + m0 + sCol + 16*j];
                vv[j] = *(const float4*)&V[(size_t)sRow * Nn + m0 + sCol + 16*j];
            }
            __syncthreads();
            #pragma unroll
            for (int j = 0; j < 4; j++) {
                const int m = sCol + 16*j;
                Sa[(m+0)*68 + sRow] = kv[j].x; Sa[(m+1)*68 + sRow] = kv[j].y;
                Sa[(m+2)*68 + sRow] = kv[j].z; Sa[(m+3)*68 + sRow] = kv[j].w;
                Sb[(m+0)*68 + sRow] = vv[j].x; Sb[(m+1)*68 + sRow] = vv[j].y;
                Sb[(m+2)*68 + sRow] = vv[j].z; Sb[(m+3)*68 + sRow] = vv[j].w;
            }
            __syncthreads();
            #pragma unroll 8
            for (int mm = 0; mm < 64; mm++) {
                float4 ka = *(const float4*)&Sa[mm*68 + ty*4];
                ulonglong2 vp = *(const ulonglong2*)&Sb[mm*68 + tx*4];
                const float kf[4] = {ka.x, ka.y, ka.z, ka.w};
                #pragma unroll
                for (int i = 0; i < 4; i++) {
                    ull kb = bcast2(kf[i]);
                    ffma2(accM[i][0], kb, vp.x);
                    ffma2(accM[i][1], kb, vp.y);
                }
            }
        }
        #pragma unroll
        for (int i = 0; i < 4; i++) {
            float2 a = unpack2(accM[i][0]);
            float2 c2 = unpack2(accM[i][1]);
            float4 mo; mo.x = a.x; mo.y = a.y; mo.z = c2.x; mo.w = c2.y;
            *(float4*)&Ms[t*4096 + (ty*4 + i)*64 + tx*4] = mo;
        }
    }
    __syncthreads();

    for (int n0 = nzq*128; n0 < nzq*128 + 128; n0 += 64) {
        float mem[4][4];
        #pragma unroll
        for (int i = 0; i < 4; i++)
            #pragma unroll
            for (int j = 0; j < 4; j++) mem[i][j] = 0.f;

        for (int t = 0; t < 4; t++) {
            const int b = t*BpC + bp;
            const float* Q = g_spk + ((size_t)b*Cc + h*GD) * Nn;
            float4 qv[4];
            #pragma unroll
            for (int j = 0; j < 4; j++)
                qv[j] = *(const float4*)&Q[(size_t)sRow * Nn + n0 + sCol + 16*j];
            __syncthreads();
            #pragma unroll
            for (int j = 0; j < 4; j++)
                *(float4*)&Sa[sRow*68 + sCol + 16*j] = qv[j];
            __syncthreads();

            ull acc[4][2];
            #pragma unroll
            for (int i = 0; i < 4; i++) { acc[i][0] = 0ull; acc[i][1] = 0ull; }

            #pragma unroll 8
            for (int dk = 0; dk < 64; dk++) {
                float4 mv = *(const float4*)&Ms[t*4096 + dk*64 + ty*4];
                ulonglong2 qp = *(const ulonglong2*)&Sa[dk*68 + tx*4];
                const float mf[4] = {mv.x, mv.y, mv.z, mv.w};
                #pragma unroll
                for (int i = 0; i < 4; i++) {
                    ull mb = bcast2(mf[i]);
                    ffma2(acc[i][0], mb, qp.x);
                    ffma2(acc[i][1], mb, qp.y);
                }
            }

            float* so = g_so + ((size_t)b*Cc + h*GD) * Nn;
            #pragma unroll
            for (int i = 0; i < 4; i++) {
                float2 a = unpack2(acc[i][0]);
                float2 c2 = unpack2(acc[i][1]);
                float o[4] = {a.x, a.y, c2.x, c2.y};
                float s[4];
                #pragma unroll
                for (int j = 0; j < 4; j++) {
                    mem[i][j] = mem[i][j]*TAU + o[j]*SCALE;
                    s[j] = (mem[i][j] > THRESH) ? 1.f : 0.f;
                    if (mem[i][j] > THRESH) mem[i][j] = 0.f;
                }
                float4 sv; sv.x = s[0]; sv.y = s[1]; sv.z = s[2]; sv.w = s[3];
                *(float4*)&so[(size_t)(ty*4 + i) * Nn + n0 + tx*4] = sv;
            }
        }
    }
}

// =====================================================================
// launch
// =====================================================================
extern "C" void kernel_launch(void* const* d_in, const int* in_sizes, int n_in,
                              void* d_out, int out_size)
{
    const float* x     = (const float*)d_in[0];
    const float* wq    = (const float*)d_in[1];
    const float* wk    = (const float*)d_in[2];
    const float* wv    = (const float*)d_in[3];
    const float* wproj = (const float*)d_in[4];
    const float* bng   = (const float*)d_in[5];
    const float* bnb   = (const float*)d_in[6];
    const float* bnm   = (const float*)d_in[7];
    const float* bnv   = (const float*)d_in[8];
    float* out = (float*)d_out;

    const int conv_smem = 2 * STAGEB;   // 147,456 B
    cudaFuncSetAttribute(hmma_conv, cudaFuncAttributeMaxDynamicSharedMemorySize, conv_smem);
    cudaFuncSetAttribute(proj_conv, cudaFuncAttributeMaxDynamicSharedMemorySize, PROJ_SMEM);
    const int attn_smem = (4*64*64 + 2*64*68) * (int)sizeof(float);  // 100,352 B
    cudaFuncSetAttribute(attn_kernel, cudaFuncAttributeMaxDynamicSharedMemorySize, attn_smem);

    wsplit_kernel<<<dim3(1024, 4), 256>>>(wq, wk, wv, wproj);
    split_t_kernel<<<dim3(16, 16, 64), dim3(32, 8)>>>(x, 0);

    // merged q,k,v conv_bn (M = 1536 stacked)
    hmma_conv<<<dim3(4, 12, 64), 256, conv_smem>>>(bng, bnb, bnm, bnv);

    lif_qkv_kernel<<<12288, 256>>>();

    attn_kernel<<<dim3(BpC, Hh, 4), 256, attn_smem>>>();

    split_t_kernel<<<dim3(16, 16, 64), dim3(32, 8)>>>(x, 1);   // g_so -> g_s16

    // proj conv_bn (fp16 single-term)
    proj_conv<<<dim3(4, 4, 64), 256, PROJ_SMEM>>>(out, bng, bnb, bnm, bnv);
}

// round 12
// speedup vs baseline: 1.9447x; 1.1665x over previous
#include <cuda_runtime.h>
#include <cuda_bf16.h>
#include <cuda_fp16.h>
#include <cstdint>
#include <cstddef>

// ---------------- problem constants ----------------
#define Tt      4
#define Bt      64
#define BpC     16
#define Cc      512
#define Nn      512
#define Hh      8
#define GD      64
#define TAU     0.5f
#define THRESH  1.0f
#define SCALE   0.125f
#define EPSBN   1e-5f
#define SZ      (Bt*Cc*Nn)      // 16,777,216
#define CN      (Cc*Nn)

typedef unsigned long long ull;

// ---------------- scratch (device globals) ----------------
__device__ __align__(128) float g_pre[3ll*SZ];
__device__ __align__(128) float g_spk[3ll*SZ];
__device__ __align__(128) float g_so [SZ];
__device__ __align__(128) __nv_bfloat16 g_xhi[SZ];   // [b][n][c]
__device__ __align__(128) __nv_bfloat16 g_xlo[SZ];
__device__ __align__(128) __half        g_s16[SZ];   // spikes fp16 [b][n][c]
__device__ __align__(128) __nv_bfloat16 g_whi[3ll*CN];
__device__ __align__(128) __nv_bfloat16 g_wlo[3ll*CN];
__device__ __align__(128) __half        g_wp16[CN];  // proj weights fp16

// ---------------- PTX helpers ----------------
static __device__ __forceinline__ uint32_t smem_u32(const void* p) {
    uint32_t a;
    asm("{ .reg .u64 t; cvta.to.shared.u64 t, %1; cvt.u32.u64 %0, t; }" : "=r"(a) : "l"(p));
    return a;
}
static __device__ __forceinline__ void cpasync16(uint32_t dst, const void* src) {
    asm volatile("cp.async.cg.shared.global [%0], [%1], 16;" :: "r"(dst), "l"(src));
}
#define CP_COMMIT()  asm volatile("cp.async.commit_group;" ::: "memory")
#define CP_WAIT(n)   asm volatile("cp.async.wait_group %0;" :: "n"(n) : "memory")

static __device__ __forceinline__ void ldm_x4(uint32_t* r, uint32_t addr) {
    asm volatile("ldmatrix.sync.aligned.m8n8.x4.shared.b16 {%0,%1,%2,%3}, [%4];"
        : "=r"(r[0]), "=r"(r[1]), "=r"(r[2]), "=r"(r[3]) : "r"(addr));
}
static __device__ __forceinline__ void mma_bf16(float* c, const uint32_t* a, const uint32_t* b) {
    asm volatile("mma.sync.aligned.m16n8k16.row.col.f32.bf16.bf16.f32 "
        "{%0,%1,%2,%3}, {%4,%5,%6,%7}, {%8,%9}, {%0,%1,%2,%3};"
        : "+f"(c[0]), "+f"(c[1]), "+f"(c[2]), "+f"(c[3])
        : "r"(a[0]), "r"(a[1]), "r"(a[2]), "r"(a[3]), "r"(b[0]), "r"(b[1]));
}
static __device__ __forceinline__ void mma_f16(float* c, const uint32_t* a, const uint32_t* b) {
    asm volatile("mma.sync.aligned.m16n8k16.row.col.f32.f16.f16.f32 "
        "{%0,%1,%2,%3}, {%4,%5,%6,%7}, {%8,%9}, {%0,%1,%2,%3};"
        : "+f"(c[0]), "+f"(c[1]), "+f"(c[2]), "+f"(c[3])
        : "r"(a[0]), "r"(a[1]), "r"(a[2]), "r"(a[3]), "r"(b[0]), "r"(b[1]));
}

// ---------------- fp32x2 helpers (attn kernel) ----------------
static __device__ __forceinline__ void ffma2(ull& d, ull a, ull b) {
    asm("fma.rn.f32x2 %0, %1, %2, %0;" : "+l"(d) : "l"(a), "l"(b));
}
static __device__ __forceinline__ ull bcast2(float w) {
    ull r; asm("mov.b64 %0, {%1, %1};" : "=l"(r) : "f"(w)); return r;
}
static __device__ __forceinline__ float2 unpack2(ull v) {
    float2 f; asm("mov.b64 {%0, %1}, %2;" : "=f"(f.x), "=f"(f.y) : "l"(v)); return f;
}

// =====================================================================
// weight split: qkv -> bf16 hi/lo; proj -> fp16 single
// =====================================================================
__global__ __launch_bounds__(256) void wsplit_kernel(
    const float* __restrict__ wq, const float* __restrict__ wk,
    const float* __restrict__ wv, const float* __restrict__ wp)
{
    const int which = blockIdx.y;
    const float* w = (which == 0) ? wq : (which == 1) ? wk : (which == 2) ? wv : wp;
    const int i = blockIdx.x * 256 + threadIdx.x;
    float v = w[i];
    if (which < 3) {
        __nv_bfloat16 h = __float2bfloat16(v);
        g_whi[(size_t)which * CN + i] = h;
        g_wlo[(size_t)which * CN + i] = __float2bfloat16(v - __bfloat162float(h));
    } else {
        g_wp16[i] = __float2half(v);
    }
}

// =====================================================================
// transpose + split: fp32 [b][c][n] -> [b][n][c]
// mode 0: x -> g_xhi/g_xlo (bf16).  mode 1: g_so spikes -> g_s16 (fp16, exact)
// =====================================================================
__global__ __launch_bounds__(256) void split_t_kernel(const float* __restrict__ in, int mode)
{
    __shared__ float t[32][33];
    const int b = blockIdx.z, c0 = blockIdx.y * 32, n0 = blockIdx.x * 32;
    const int tx = threadIdx.x, ty = threadIdx.y;
    const float* ib = (mode ? (const float*)g_so : in) + (size_t)b * CN;
    #pragma unroll
    for (int j = 0; j < 4; j++)
        t[ty + 8*j][tx] = ib[(size_t)(c0 + ty + 8*j) * Nn + n0 + tx];
    __syncthreads();
    #pragma unroll
    for (int j = 0; j < 4; j++) {
        const int n = ty + 8*j;
        const float v = t[tx][n];
        const size_t o = ((size_t)b * Nn + n0 + n) * Cc + c0 + tx;
        if (mode == 0) {
            const __nv_bfloat16 h = __float2bfloat16(v);
            g_xhi[o] = h;
            g_xlo[o] = __float2bfloat16(v - __bfloat162float(h));
        } else {
            g_s16[o] = __float2half(v);
        }
    }
}

// =====================================================================
// qkv HMMA conv_bn (R8 proven): D[128m x 128n] = W @ X^T, K=512, + BN
// bf16 3-term split, term-major mma issue, cp.async double buffer
// =====================================================================
#define ROWB   144
#define TILEB  (128*ROWB)
#define STAGEB (4*TILEB)

__global__ __launch_bounds__(256) void hmma_conv(
    const float* __restrict__ bng, const float* __restrict__ bnb,
    const float* __restrict__ bnm, const float* __restrict__ bnv)
{
    extern __shared__ char smem[];
    const uint32_t sb = smem_u32(smem);
    const int tid  = threadIdx.x;
    const int wid  = tid >> 5, lane = tid & 31;
    const int n0   = blockIdx.x * 128;
    const int b    = blockIdx.z;
    const int wsel = blockIdx.y >> 2;
    const int r0   = (blockIdx.y & 3) * 128;

    float* out = g_pre + (size_t)wsel * SZ;
    const __nv_bfloat16* wh = g_whi + (size_t)wsel * CN + (size_t)r0 * Cc;
    const __nv_bfloat16* wl = g_wlo + (size_t)wsel * CN + (size_t)r0 * Cc;
    const __nv_bfloat16* bh = g_xhi + ((size_t)b * Nn + n0) * Cc;
    const __nv_bfloat16* bl = g_xlo + ((size_t)b * Nn + n0) * Cc;

    const int lrow = tid >> 1;
    const int cb0  = (tid & 1) * 4;
    const uint32_t rowOff = (uint32_t)lrow * ROWB;
    const __nv_bfloat16* gAh = wh + (size_t)lrow * Cc;
    const __nv_bfloat16* gAl = wl + (size_t)lrow * Cc;
    const __nv_bfloat16* gBh = bh + (size_t)lrow * Cc;
    const __nv_bfloat16* gBl = bl + (size_t)lrow * Cc;

    float acc[4][4][4];
    #pragma unroll
    for (int i = 0; i < 4; i++)
        #pragma unroll
        for (int j = 0; j < 4; j++)
            #pragma unroll
            for (int q = 0; q < 4; q++) acc[i][j][q] = 0.f;

    const int wm = wid & 1, wn = wid >> 1;
    const int grp = lane >> 3, wi = lane & 7;

    auto load_stage = [&](uint32_t st, int k0) {
        #pragma unroll
        for (int j = 0; j < 4; j++) {
            const int c = cb0 + j;
            const uint32_t off = rowOff + c * 16;
            cpasync16(st + off,           gAh + k0 + c*8);
            cpasync16(st + TILEB + off,   gAl + k0 + c*8);
            cpasync16(st + 2*TILEB + off, gBh + k0 + c*8);
            cpasync16(st + 3*TILEB + off, gBl + k0 + c*8);
        }
    };

    load_stage(sb, 0);
    CP_COMMIT();

    for (int kc = 0; kc < 8; kc++) {
        const int s = kc & 1;
        if (kc < 7) {
            load_stage(sb + (s^1)*STAGEB, (kc + 1) * 64);
            CP_COMMIT();
            CP_WAIT(1);
        } else {
            CP_WAIT(0);
        }
        __syncthreads();

        const uint32_t st = sb + s * STAGEB;
        #pragma unroll
        for (int ks = 0; ks < 4; ks++) {
            uint32_t Ah[4][4], Al[4][4], Bh[4][2], Bl[4][2];
            #pragma unroll
            for (int mi = 0; mi < 4; mi++) {
                const uint32_t ra = st
                    + (uint32_t)(wm*64 + mi*16 + wi + (grp&1)*8) * ROWB
                    + (uint32_t)(ks*32 + (grp>>1)*16);
                ldm_x4(Ah[mi], ra);
                ldm_x4(Al[mi], ra + TILEB);
            }
            #pragma unroll
            for (int bt = 0; bt < 2; bt++) {
                const uint32_t rb = st + 2*TILEB
                    + (uint32_t)(wn*32 + bt*16 + wi + (grp>>1)*8) * ROWB
                    + (uint32_t)(ks*32 + (grp&1)*16);
                uint32_t r[4];
                ldm_x4(r, rb);
                Bh[bt*2][0] = r[0]; Bh[bt*2][1] = r[1];
                Bh[bt*2+1][0] = r[2]; Bh[bt*2+1][1] = r[3];
                ldm_x4(r, rb + TILEB);
                Bl[bt*2][0] = r[0]; Bl[bt*2][1] = r[1];
                Bl[bt*2+1][0] = r[2]; Bl[bt*2+1][1] = r[3];
            }
            // term-major issue: 16 independent mmas per pass
            #pragma unroll
            for (int mi = 0; mi < 4; mi++)
                #pragma unroll
                for (int nt = 0; nt < 4; nt++)
                    mma_bf16(acc[mi][nt], Ah[mi], Bh[nt]);
            #pragma unroll
            for (int mi = 0; mi < 4; mi++)
                #pragma unroll
                for (int nt = 0; nt < 4; nt++)
                    mma_bf16(acc[mi][nt], Al[mi], Bh[nt]);
            #pragma unroll
            for (int mi = 0; mi < 4; mi++)
                #pragma unroll
                for (int nt = 0; nt < 4; nt++)
                    mma_bf16(acc[mi][nt], Ah[mi], Bl[nt]);
        }
        __syncthreads();
    }

    // epilogue: BN affine + fp32 store
    #pragma unroll
    for (int mi = 0; mi < 4; mi++) {
        const int rA = r0 + wm*64 + mi*16 + (lane >> 2);
        const int rB = rA + 8;
        const float invA  = bng[wsel*Cc + rA] / sqrtf(bnv[wsel*Cc + rA] + EPSBN);
        const float biasA = bnb[wsel*Cc + rA] - bnm[wsel*Cc + rA] * invA;
        const float invB  = bng[wsel*Cc + rB] / sqrtf(bnv[wsel*Cc + rB] + EPSBN);
        const float biasB = bnb[wsel*Cc + rB] - bnm[wsel*Cc + rB] * invB;
        float* pA = out + ((size_t)b * Cc + rA) * Nn + n0;
        float* pB = out + ((size_t)b * Cc + rB) * Nn + n0;
        #pragma unroll
        for (int nt = 0; nt < 4; nt++) {
            const int nc = wn*32 + nt*8 + (lane & 3)*2;
            float2 v0, v1;
            v0.x = acc[mi][nt][0]*invA + biasA;
            v0.y = acc[mi][nt][1]*invA + biasA;
            v1.x = acc[mi][nt][2]*invB + biasB;
            v1.y = acc[mi][nt][3]*invB + biasB;
            *(float2*)&pA[nc] = v0;
            *(float2*)&pB[nc] = v1;
        }
    }
}

// =====================================================================
// proj conv_bn: fp16 SINGLE-term (spikes exact in fp16; W error 2^-12,
// no downstream LIF). 2 smem planes, 2 CTAs/SM. grid (4, 4, 64)
// =====================================================================
#define PTILE  (128*ROWB)               // 18432
#define PSTG   (2*PTILE)                // 36864
#define PROJ_SMEM (2*PSTG)              // 73728

__global__ __launch_bounds__(256, 2) void proj_conv(
    float* __restrict__ extout,
    const float* __restrict__ bng, const float* __restrict__ bnb,
    const float* __restrict__ bnm, const float* __restrict__ bnv)
{
    extern __shared__ char smem[];
    const uint32_t sb = smem_u32(smem);
    const int tid  = threadIdx.x;
    const int wid  = tid >> 5, lane = tid & 31;
    const int n0   = blockIdx.x * 128;
    const int r0   = blockIdx.y * 128;
    const int b    = blockIdx.z;

    const __half* wp = g_wp16 + (size_t)r0 * Cc;
    const __half* sp = g_s16 + ((size_t)b * Nn + n0) * Cc;

    const int lrow = tid >> 1;
    const int cb0  = (tid & 1) * 4;
    const uint32_t rowOff = (uint32_t)lrow * ROWB;
    const __half* gA = wp + (size_t)lrow * Cc;
    const __half* gB = sp + (size_t)lrow * Cc;

    float acc[4][4][4];
    #pragma unroll
    for (int i = 0; i < 4; i++)
        #pragma unroll
        for (int j = 0; j < 4; j++)
            #pragma unroll
            for (int q = 0; q < 4; q++) acc[i][j][q] = 0.f;

    const int wm = wid & 1, wn = wid >> 1;
    const int grp = lane >> 3, wi = lane & 7;

    auto load_stage = [&](uint32_t st, int k0) {
        #pragma unroll
        for (int j = 0; j < 4; j++) {
            const int c = cb0 + j;
            const uint32_t off = rowOff + c * 16;
            cpasync16(st + off,         gA + k0 + c*8);
            cpasync16(st + PTILE + off, gB + k0 + c*8);
        }
    };

    load_stage(sb, 0);
    CP_COMMIT();

    for (int kc = 0; kc < 8; kc++) {
        const int s = kc & 1;
        if (kc < 7) {
            load_stage(sb + (s^1)*PSTG, (kc + 1) * 64);
            CP_COMMIT();
            CP_WAIT(1);
        } else {
            CP_WAIT(0);
        }
        __syncthreads();

        const uint32_t st = sb + s * PSTG;
        #pragma unroll
        for (int ks = 0; ks < 4; ks++) {
            uint32_t A[4][4], B[4][2];
            #pragma unroll
            for (int mi = 0; mi < 4; mi++) {
                const uint32_t ra = st
                    + (uint32_t)(wm*64 + mi*16 + wi + (grp&1)*8) * ROWB
                    + (uint32_t)(ks*32 + (grp>>1)*16);
                ldm_x4(A[mi], ra);
            }
            #pragma unroll
            for (int bt = 0; bt < 2; bt++) {
                const uint32_t rb = st + PTILE
                    + (uint32_t)(wn*32 + bt*16 + wi + (grp>>1)*8) * ROWB
                    + (uint32_t)(ks*32 + (grp&1)*16);
                uint32_t r[4];
                ldm_x4(r, rb);
                B[bt*2][0] = r[0]; B[bt*2][1] = r[1];
                B[bt*2+1][0] = r[2]; B[bt*2+1][1] = r[3];
            }
            #pragma unroll
            for (int mi = 0; mi < 4; mi++)
                #pragma unroll
                for (int nt = 0; nt < 4; nt++)
                    mma_f16(acc[mi][nt], A[mi], B[nt]);
        }
        __syncthreads();
    }

    // epilogue: BN affine + fp32 store (bn row 3)
    #pragma unroll
    for (int mi = 0; mi < 4; mi++) {
        const int rA = r0 + wm*64 + mi*16 + (lane >> 2);
        const int rB = rA + 8;
        const float invA  = bng[3*Cc + rA] / sqrtf(bnv[3*Cc + rA] + EPSBN);
        const float biasA = bnb[3*Cc + rA] - bnm[3*Cc + rA] * invA;
        const float invB  = bng[3*Cc + rB] / sqrtf(bnv[3*Cc + rB] + EPSBN);
        const float biasB = bnb[3*Cc + rB] - bnm[3*Cc + rB] * invB;
        float* pA = extout + ((size_t)b * Cc + rA) * Nn + n0;
        float* pB = extout + ((size_t)b * Cc + rB) * Nn + n0;
        #pragma unroll
        for (int nt = 0; nt < 4; nt++) {
            const int nc = wn*32 + nt*8 + (lane & 3)*2;
            float2 v0, v1;
            v0.x = acc[mi][nt][0]*invA + biasA;
            v0.y = acc[mi][nt][1]*invA + biasA;
            v1.x = acc[mi][nt][2]*invB + biasB;
            v1.y = acc[mi][nt][3]*invB + biasB;
            *(float2*)&pA[nc] = v0;
            *(float2*)&pB[nc] = v1;
        }
    }
}

// =====================================================================
// LIF over T for q/k/v pre-activations
// =====================================================================
__global__ __launch_bounds__(256) void lif_qkv_kernel()
{
    const int idx = blockIdx.x * 256 + threadIdx.x;
    const int q   = idx & 127;
    const int c   = (idx >> 7) & 511;
    const int bp  = (idx >> 16) & 15;
    const int sel = idx >> 20;

    const float* pre = g_pre + (size_t)sel * SZ;
    float*       spk = g_spk + (size_t)sel * SZ;

    float4 mem = {0.f, 0.f, 0.f, 0.f};
    #pragma unroll
    for (int t = 0; t < 4; t++) {
        const size_t off = (((size_t)(t*BpC + bp) * Cc + c) * Nn) + q*4;
        float4 v = *(const float4*)&pre[off];
        float4 s;
        mem.x = mem.x*TAU + v.x; s.x = (mem.x > THRESH) ? 1.f : 0.f; if (mem.x > THRESH) mem.x = 0.f;
        mem.y = mem.y*TAU + v.y; s.y = (mem.y > THRESH) ? 1.f : 0.f; if (mem.y > THRESH) mem.y = 0.f;
        mem.z = mem.z*TAU + v.z; s.z = (mem.z > THRESH) ? 1.f : 0.f; if (mem.z > THRESH) mem.z = 0.f;
        mem.w = mem.w*TAU + v.w; s.w = (mem.w > THRESH) ? 1.f : 0.f; if (mem.w > THRESH) mem.w = 0.f;
        *(float4*)&spk[off] = s;
    }
}

// =====================================================================
// Attention (reassociated) + LIF, fused per (b', h)  — R8 proven version
// =====================================================================
__global__ __launch_bounds__(256) void attn_kernel()
{
    extern __shared__ __align__(16) float sm[];
    float* Ms = sm;
    float* Sa = sm + 4*64*64;
    float* Sb = Sa + 64*68;

    const int bp = blockIdx.x;
    const int h  = blockIdx.y;
    const int tid = threadIdx.x;
    const int ty = tid >> 4, tx = tid & 15;
    const int sRow = tid >> 2;
    const int sCol = (tid & 3) * 4;

    for (int t = 0; t < 4; t++) {
        const int b = t*BpC + bp;
        const float* K = g_spk + (size_t)SZ   + ((size_t)b*Cc + h*GD) * Nn;
        const float* V = g_spk + (size_t)2*SZ + ((size_t)b*Cc + h*GD) * Nn;

        ull accM[4][2];
        #pragma unroll
        for (int i = 0; i < 4; i++) { accM[i][0] = 0ull; accM[i][1] = 0ull; }

        for (int m0 = 0; m0 < Nn; m0 += 64) {
            float4 kv[4], vv[4];
            #pragma unroll
            for (int j = 0; j < 4; j++) {
                kv[j] = *(const float4*)&K[(size_t)sRow * Nn + m0 + sCol + 16*j];
                vv[j] = *(const float4*)&V[(size_t)sRow * Nn + m0 + sCol + 16*j];
            }
            __syncthreads();
            #pragma unroll
            for (int j = 0; j < 4; j++) {
                const int m = sCol + 16*j;
                Sa[(m+0)*68 + sRow] = kv[j].x; Sa[(m+1)*68 + sRow] = kv[j].y;
                Sa[(m+2)*68 + sRow] = kv[j].z; Sa[(m+3)*68 + sRow] = kv[j].w;
                Sb[(m+0)*68 + sRow] = vv[j].x; Sb[(m+1)*68 + sRow] = vv[j].y;
                Sb[(m+2)*68 + sRow] = vv[j].z; Sb[(m+3)*68 + sRow] = vv[j].w;
            }
            __syncthreads();
            #pragma unroll 8
            for (int mm = 0; mm < 64; mm++) {
                float4 ka = *(const float4*)&Sa[mm*68 + ty*4];
                ulonglong2 vp = *(const ulonglong2*)&Sb[mm*68 + tx*4];
                const float kf[4] = {ka.x, ka.y, ka.z, ka.w};
                #pragma unroll
                for (int i = 0; i < 4; i++) {
                    ull kb = bcast2(kf[i]);
                    ffma2(accM[i][0], kb, vp.x);
                    ffma2(accM[i][1], kb, vp.y);
                }
            }
        }
        #pragma unroll
        for (int i = 0; i < 4; i++) {
            float2 a = unpack2(accM[i][0]);
            float2 c2 = unpack2(accM[i][1]);
            float4 mo; mo.x = a.x; mo.y = a.y; mo.z = c2.x; mo.w = c2.y;
            *(float4*)&Ms[t*4096 + (ty*4 + i)*64 + tx*4] = mo;
        }
    }
    __syncthreads();

    for (int n0 = 0; n0 < Nn; n0 += 64) {
        float mem[4][4];
        #pragma unroll
        for (int i = 0; i < 4; i++)
            #pragma unroll
            for (int j = 0; j < 4; j++) mem[i][j] = 0.f;

        for (int t = 0; t < 4; t++) {
            const int b = t*BpC + bp;
            const float* Q = g_spk + ((size_t)b*Cc + h*GD) * Nn;
            float4 qv[4];
            #pragma unroll
            for (int j = 0; j < 4; j++)
                qv[j] = *(const float4*)&Q[(size_t)sRow * Nn + n0 + sCol + 16*j];
            __syncthreads();
            #pragma unroll
            for (int j = 0; j < 4; j++)
                *(float4*)&Sa[sRow*68 + sCol + 16*j] = qv[j];
            __syncthreads();

            ull acc[4][2];
            #pragma unroll
            for (int i = 0; i < 4; i++) { acc[i][0] = 0ull; acc[i][1] = 0ull; }

            #pragma unroll 8
            for (int dk = 0; dk < 64; dk++) {
                float4 mv = *(const float4*)&Ms[t*4096 + dk*64 + ty*4];
                ulonglong2 qp = *(const ulonglong2*)&Sa[dk*68 + tx*4];
                const float mf[4] = {mv.x, mv.y, mv.z, mv.w};
                #pragma unroll
                for (int i = 0; i < 4; i++) {
                    ull mb = bcast2(mf[i]);
                    ffma2(acc[i][0], mb, qp.x);
                    ffma2(acc[i][1], mb, qp.y);
                }
            }

            float* so = g_so + ((size_t)b*Cc + h*GD) * Nn;
            #pragma unroll
            for (int i = 0; i < 4; i++) {
                float2 a = unpack2(acc[i][0]);
                float2 c2 = unpack2(acc[i][1]);
                float o[4] = {a.x, a.y, c2.x, c2.y};
                float s[4];
                #pragma unroll
                for (int j = 0; j < 4; j++) {
                    mem[i][j] = mem[i][j]*TAU + o[j]*SCALE;
                    s[j] = (mem[i][j] > THRESH) ? 1.f : 0.f;
                    if (mem[i][j] > THRESH) mem[i][j] = 0.f;
                }
                float4 sv; sv.x = s[0]; sv.y = s[1]; sv.z = s[2]; sv.w = s[3];
                *(float4*)&so[(size_t)(ty*4 + i) * Nn + n0 + tx*4] = sv;
            }
        }
    }
}

// =====================================================================
// launch
// =====================================================================
extern "C" void kernel_launch(void* const* d_in, const int* in_sizes, int n_in,
                              void* d_out, int out_size)
{
    const float* x     = (const float*)d_in[0];
    const float* wq    = (const float*)d_in[1];
    const float* wk    = (const float*)d_in[2];
    const float* wv    = (const float*)d_in[3];
    const float* wproj = (const float*)d_in[4];
    const float* bng   = (const float*)d_in[5];
    const float* bnb   = (const float*)d_in[6];
    const float* bnm   = (const float*)d_in[7];
    const float* bnv   = (const float*)d_in[8];
    float* out = (float*)d_out;

    const int conv_smem = 2 * STAGEB;   // 147,456 B
    cudaFuncSetAttribute(hmma_conv, cudaFuncAttributeMaxDynamicSharedMemorySize, conv_smem);
    cudaFuncSetAttribute(proj_conv, cudaFuncAttributeMaxDynamicSharedMemorySize, PROJ_SMEM);
    const int attn_smem = (4*64*64 + 2*64*68) * (int)sizeof(float);  // 100,352 B
    cudaFuncSetAttribute(attn_kernel, cudaFuncAttributeMaxDynamicSharedMemorySize, attn_smem);

    wsplit_kernel<<<dim3(1024, 4), 256>>>(wq, wk, wv, wproj);
    split_t_kernel<<<dim3(16, 16, 64), dim3(32, 8)>>>(x, 0);

    // merged q,k,v conv_bn (M = 1536 stacked)
    hmma_conv<<<dim3(4, 12, 64), 256, conv_smem>>>(bng, bnb, bnm, bnv);

    lif_qkv_kernel<<<12288, 256>>>();

    attn_kernel<<<dim3(BpC, Hh), 256, attn_smem>>>();

    split_t_kernel<<<dim3(16, 16, 64), dim3(32, 8)>>>(x, 1);   // g_so -> g_s16

    // proj conv_bn (fp16 single-term)
    proj_conv<<<dim3(4, 4, 64), 256, PROJ_SMEM>>>(out, bng, bnb, bnm, bnv);
}

// round 13
// speedup vs baseline: 1.9459x; 1.0006x over previous
#include <cuda_runtime.h>
#include <cuda_bf16.h>
#include <cuda_fp16.h>
#include <cstdint>
#include <cstddef>

// ---------------- problem constants ----------------
#define Tt      4
#define Bt      64
#define BpC     16
#define Cc      512
#define Nn      512
#define Hh      8
#define GD      64
#define TAU     0.5f
#define THRESH  1.0f
#define SCALE   0.125f
#define EPSBN   1e-5f
#define SZ      (Bt*Cc*Nn)      // 16,777,216
#define CN      (Cc*Nn)

typedef unsigned long long ull;

// ---------------- scratch (device globals) ----------------
__device__ __align__(128) float g_spk[3ll*SZ];
__device__ __align__(128) float g_so [SZ];
__device__ __align__(128) __nv_bfloat16 g_xhi[SZ];   // [b][n][c]
__device__ __align__(128) __nv_bfloat16 g_xlo[SZ];
__device__ __align__(128) __half        g_s16[SZ];   // spikes fp16 [b][n][c]
__device__ __align__(128) __nv_bfloat16 g_whi[3ll*CN];
__device__ __align__(128) __nv_bfloat16 g_wlo[3ll*CN];
__device__ __align__(128) __half        g_wp16[CN];  // proj weights fp16

// ---------------- PTX helpers ----------------
static __device__ __forceinline__ uint32_t smem_u32(const void* p) {
    uint32_t a;
    asm("{ .reg .u64 t; cvta.to.shared.u64 t, %1; cvt.u32.u64 %0, t; }" : "=r"(a) : "l"(p));
    return a;
}
static __device__ __forceinline__ void cpasync16(uint32_t dst, const void* src) {
    asm volatile("cp.async.cg.shared.global [%0], [%1], 16;" :: "r"(dst), "l"(src));
}
#define CP_COMMIT()  asm volatile("cp.async.commit_group;" ::: "memory")
#define CP_WAIT(n)   asm volatile("cp.async.wait_group %0;" :: "n"(n) : "memory")

static __device__ __forceinline__ void ldm_x4(uint32_t* r, uint32_t addr) {
    asm volatile("ldmatrix.sync.aligned.m8n8.x4.shared.b16 {%0,%1,%2,%3}, [%4];"
        : "=r"(r[0]), "=r"(r[1]), "=r"(r[2]), "=r"(r[3]) : "r"(addr));
}
static __device__ __forceinline__ void mma_bf16(float* c, const uint32_t* a, const uint32_t* b) {
    asm volatile("mma.sync.aligned.m16n8k16.row.col.f32.bf16.bf16.f32 "
        "{%0,%1,%2,%3}, {%4,%5,%6,%7}, {%8,%9}, {%0,%1,%2,%3};"
        : "+f"(c[0]), "+f"(c[1]), "+f"(c[2]), "+f"(c[3])
        : "r"(a[0]), "r"(a[1]), "r"(a[2]), "r"(a[3]), "r"(b[0]), "r"(b[1]));
}
static __device__ __forceinline__ void mma_f16(float* c, const uint32_t* a, const uint32_t* b) {
    asm volatile("mma.sync.aligned.m16n8k16.row.col.f32.f16.f16.f32 "
        "{%0,%1,%2,%3}, {%4,%5,%6,%7}, {%8,%9}, {%0,%1,%2,%3};"
        : "+f"(c[0]), "+f"(c[1]), "+f"(c[2]), "+f"(c[3])
        : "r"(a[0]), "r"(a[1]), "r"(a[2]), "r"(a[3]), "r"(b[0]), "r"(b[1]));
}

// ---------------- fp32x2 helpers (attn kernel) ----------------
static __device__ __forceinline__ void ffma2(ull& d, ull a, ull b) {
    asm("fma.rn.f32x2 %0, %1, %2, %0;" : "+l"(d) : "l"(a), "l"(b));
}
static __device__ __forceinline__ ull bcast2(float w) {
    ull r; asm("mov.b64 %0, {%1, %1};" : "=l"(r) : "f"(w)); return r;
}
static __device__ __forceinline__ float2 unpack2(ull v) {
    float2 f; asm("mov.b64 {%0, %1}, %2;" : "=f"(f.x), "=f"(f.y) : "l"(v)); return f;
}

// =====================================================================
// weight split: qkv -> bf16 hi/lo; proj -> fp16 single
// =====================================================================
__global__ __launch_bounds__(256) void wsplit_kernel(
    const float* __restrict__ wq, const float* __restrict__ wk,
    const float* __restrict__ wv, const float* __restrict__ wp)
{
    const int which = blockIdx.y;
    const float* w = (which == 0) ? wq : (which == 1) ? wk : (which == 2) ? wv : wp;
    const int i = blockIdx.x * 256 + threadIdx.x;
    float v = w[i];
    if (which < 3) {
        __nv_bfloat16 h = __float2bfloat16(v);
        g_whi[(size_t)which * CN + i] = h;
        g_wlo[(size_t)which * CN + i] = __float2bfloat16(v - __bfloat162float(h));
    } else {
        g_wp16[i] = __float2half(v);
    }
}

// =====================================================================
// transpose + split: fp32 [b][c][n] -> [b][n][c]
// mode 0: x -> g_xhi/g_xlo (bf16).  mode 1: g_so spikes -> g_s16 (fp16, exact)
// =====================================================================
__global__ __launch_bounds__(256) void split_t_kernel(const float* __restrict__ in, int mode)
{
    __shared__ float t[32][33];
    const int b = blockIdx.z, c0 = blockIdx.y * 32, n0 = blockIdx.x * 32;
    const int tx = threadIdx.x, ty = threadIdx.y;
    const float* ib = (mode ? (const float*)g_so : in) + (size_t)b * CN;
    #pragma unroll
    for (int j = 0; j < 4; j++)
        t[ty + 8*j][tx] = ib[(size_t)(c0 + ty + 8*j) * Nn + n0 + tx];
    __syncthreads();
    #pragma unroll
    for (int j = 0; j < 4; j++) {
        const int n = ty + 8*j;
        const float v = t[tx][n];
        const size_t o = ((size_t)b * Nn + n0 + n) * Cc + c0 + tx;
        if (mode == 0) {
            const __nv_bfloat16 h = __float2bfloat16(v);
            g_xhi[o] = h;
            g_xlo[o] = __float2bfloat16(v - __bfloat162float(h));
        } else {
            g_s16[o] = __float2half(v);
        }
    }
}

// =====================================================================
// qkv HMMA conv_bn + FUSED LIF: each CTA loops t=0..3 (b = t*16+bp),
// runs the full K=512 GEMM per t, applies BN + LIF (membrane in regs),
// writes spikes directly to g_spk. No g_pre round-trip.
// grid (4 ntiles, 12 slabs, 16 bp)
// =====================================================================
#define ROWB   144
#define TILEB  (128*ROWB)
#define STAGEB (4*TILEB)

__global__ __launch_bounds__(256) void hmma_conv_lif(
    const float* __restrict__ bng, const float* __restrict__ bnb,
    const float* __restrict__ bnm, const float* __restrict__ bnv)
{
    extern __shared__ char smem[];
    const uint32_t sb = smem_u32(smem);
    const int tid  = threadIdx.x;
    const int wid  = tid >> 5, lane = tid & 31;
    const int n0   = blockIdx.x * 128;
    const int bp   = blockIdx.z;
    const int wsel = blockIdx.y >> 2;
    const int r0   = (blockIdx.y & 3) * 128;

    float* spk = g_spk + (size_t)wsel * SZ;
    const __nv_bfloat16* wh = g_whi + (size_t)wsel * CN + (size_t)r0 * Cc;
    const __nv_bfloat16* wl = g_wlo + (size_t)wsel * CN + (size_t)r0 * Cc;

    const int lrow = tid >> 1;
    const int cb0  = (tid & 1) * 4;
    const uint32_t rowOff = (uint32_t)lrow * ROWB;
    const __nv_bfloat16* gAh = wh + (size_t)lrow * Cc;
    const __nv_bfloat16* gAl = wl + (size_t)lrow * Cc;

    const int wm = wid & 1, wn = wid >> 1;
    const int grp = lane >> 3, wi = lane & 7;

    // BN constants per thread (rows rA = base, rB = base+8, for 4 mi)
    float invA[4], biasA[4], invB[4], biasB[4];
    #pragma unroll
    for (int mi = 0; mi < 4; mi++) {
        const int rA = r0 + wm*64 + mi*16 + (lane >> 2);
        const int rB = rA + 8;
        invA[mi]  = bng[wsel*Cc + rA] / sqrtf(bnv[wsel*Cc + rA] + EPSBN);
        biasA[mi] = bnb[wsel*Cc + rA] - bnm[wsel*Cc + rA] * invA[mi];
        invB[mi]  = bng[wsel*Cc + rB] / sqrtf(bnv[wsel*Cc + rB] + EPSBN);
        biasB[mi] = bnb[wsel*Cc + rB] - bnm[wsel*Cc + rB] * invB[mi];
    }

    // LIF membrane state (mirrors acc layout), persists across t
    float mem[4][4][4];
    #pragma unroll
    for (int i = 0; i < 4; i++)
        #pragma unroll
        for (int j = 0; j < 4; j++)
            #pragma unroll
            for (int q = 0; q < 4; q++) mem[i][j][q] = 0.f;

    for (int t = 0; t < 4; t++) {
        const int b = t*BpC + bp;
        const __nv_bfloat16* gBh = g_xhi + ((size_t)b * Nn + n0) * Cc + (size_t)lrow * Cc;
        const __nv_bfloat16* gBl = g_xlo + ((size_t)b * Nn + n0) * Cc + (size_t)lrow * Cc;

        float acc[4][4][4];
        #pragma unroll
        for (int i = 0; i < 4; i++)
            #pragma unroll
            for (int j = 0; j < 4; j++)
                #pragma unroll
                for (int q = 0; q < 4; q++) acc[i][j][q] = 0.f;

        auto load_stage = [&](uint32_t st, int k0) {
            #pragma unroll
            for (int j = 0; j < 4; j++) {
                const int c = cb0 + j;
                const uint32_t off = rowOff + c * 16;
                cpasync16(st + off,           gAh + k0 + c*8);
                cpasync16(st + TILEB + off,   gAl + k0 + c*8);
                cpasync16(st + 2*TILEB + off, gBh + k0 + c*8);
                cpasync16(st + 3*TILEB + off, gBl + k0 + c*8);
            }
        };

        load_stage(sb, 0);
        CP_COMMIT();

        for (int kc = 0; kc < 8; kc++) {
            const int s = kc & 1;
            if (kc < 7) {
                load_stage(sb + (s^1)*STAGEB, (kc + 1) * 64);
                CP_COMMIT();
                CP_WAIT(1);
            } else {
                CP_WAIT(0);
            }
            __syncthreads();

            const uint32_t st = sb + s * STAGEB;
            #pragma unroll
            for (int ks = 0; ks < 4; ks++) {
                uint32_t Ah[4][4], Al[4][4], Bh[4][2], Bl[4][2];
                #pragma unroll
                for (int mi = 0; mi < 4; mi++) {
                    const uint32_t ra = st
                        + (uint32_t)(wm*64 + mi*16 + wi + (grp&1)*8) * ROWB
                        + (uint32_t)(ks*32 + (grp>>1)*16);
                    ldm_x4(Ah[mi], ra);
                    ldm_x4(Al[mi], ra + TILEB);
                }
                #pragma unroll
                for (int bt = 0; bt < 2; bt++) {
                    const uint32_t rb = st + 2*TILEB
                        + (uint32_t)(wn*32 + bt*16 + wi + (grp>>1)*8) * ROWB
                        + (uint32_t)(ks*32 + (grp&1)*16);
                    uint32_t r[4];
                    ldm_x4(r, rb);
                    Bh[bt*2][0] = r[0]; Bh[bt*2][1] = r[1];
                    Bh[bt*2+1][0] = r[2]; Bh[bt*2+1][1] = r[3];
                    ldm_x4(r, rb + TILEB);
                    Bl[bt*2][0] = r[0]; Bl[bt*2][1] = r[1];
                    Bl[bt*2+1][0] = r[2]; Bl[bt*2+1][1] = r[3];
                }
                // term-major issue: 16 independent mmas per pass
                #pragma unroll
                for (int mi = 0; mi < 4; mi++)
                    #pragma unroll
                    for (int nt = 0; nt < 4; nt++)
                        mma_bf16(acc[mi][nt], Ah[mi], Bh[nt]);
                #pragma unroll
                for (int mi = 0; mi < 4; mi++)
                    #pragma unroll
                    for (int nt = 0; nt < 4; nt++)
                        mma_bf16(acc[mi][nt], Al[mi], Bh[nt]);
                #pragma unroll
                for (int mi = 0; mi < 4; mi++)
                    #pragma unroll
                    for (int nt = 0; nt < 4; nt++)
                        mma_bf16(acc[mi][nt], Ah[mi], Bl[nt]);
            }
            __syncthreads();
        }

        // epilogue t: BN affine, LIF update, spike store
        #pragma unroll
        for (int mi = 0; mi < 4; mi++) {
            const int rA = r0 + wm*64 + mi*16 + (lane >> 2);
            const int rB = rA + 8;
            float* pA = spk + ((size_t)b * Cc + rA) * Nn + n0;
            float* pB = spk + ((size_t)b * Cc + rB) * Nn + n0;
            #pragma unroll
            for (int nt = 0; nt < 4; nt++) {
                const int nc = wn*32 + nt*8 + (lane & 3)*2;
                float pre[4];
                pre[0] = acc[mi][nt][0]*invA[mi] + biasA[mi];
                pre[1] = acc[mi][nt][1]*invA[mi] + biasA[mi];
                pre[2] = acc[mi][nt][2]*invB[mi] + biasB[mi];
                pre[3] = acc[mi][nt][3]*invB[mi] + biasB[mi];
                float s[4];
                #pragma unroll
                for (int q = 0; q < 4; q++) {
                    mem[mi][nt][q] = mem[mi][nt][q]*TAU + pre[q];
                    s[q] = (mem[mi][nt][q] > THRESH) ? 1.f : 0.f;
                    if (mem[mi][nt][q] > THRESH) mem[mi][nt][q] = 0.f;
                }
                float2 v0, v1;
                v0.x = s[0]; v0.y = s[1];
                v1.x = s[2]; v1.y = s[3];
                *(float2*)&pA[nc] = v0;
                *(float2*)&pB[nc] = v1;
            }
        }
    }
}

// =====================================================================
// proj conv_bn: fp16 SINGLE-term. grid (4, 4, 64), 2 CTAs/SM
// =====================================================================
#define PTILE  (128*ROWB)               // 18432
#define PSTG   (2*PTILE)                // 36864
#define PROJ_SMEM (2*PSTG)              // 73728

__global__ __launch_bounds__(256, 2) void proj_conv(
    float* __restrict__ extout,
    const float* __restrict__ bng, const float* __restrict__ bnb,
    const float* __restrict__ bnm, const float* __restrict__ bnv)
{
    extern __shared__ char smem[];
    const uint32_t sb = smem_u32(smem);
    const int tid  = threadIdx.x;
    const int wid  = tid >> 5, lane = tid & 31;
    const int n0   = blockIdx.x * 128;
    const int r0   = blockIdx.y * 128;
    const int b    = blockIdx.z;

    const __half* wp = g_wp16 + (size_t)r0 * Cc;
    const __half* sp = g_s16 + ((size_t)b * Nn + n0) * Cc;

    const int lrow = tid >> 1;
    const int cb0  = (tid & 1) * 4;
    const uint32_t rowOff = (uint32_t)lrow * ROWB;
    const __half* gA = wp + (size_t)lrow * Cc;
    const __half* gB = sp + (size_t)lrow * Cc;

    float acc[4][4][4];
    #pragma unroll
    for (int i = 0; i < 4; i++)
        #pragma unroll
        for (int j = 0; j < 4; j++)
            #pragma unroll
            for (int q = 0; q < 4; q++) acc[i][j][q] = 0.f;

    const int wm = wid & 1, wn = wid >> 1;
    const int grp = lane >> 3, wi = lane & 7;

    auto load_stage = [&](uint32_t st, int k0) {
        #pragma unroll
        for (int j = 0; j < 4; j++) {
            const int c = cb0 + j;
            const uint32_t off = rowOff + c * 16;
            cpasync16(st + off,         gA + k0 + c*8);
            cpasync16(st + PTILE + off, gB + k0 + c*8);
        }
    };

    load_stage(sb, 0);
    CP_COMMIT();

    for (int kc = 0; kc < 8; kc++) {
        const int s = kc & 1;
        if (kc < 7) {
            load_stage(sb + (s^1)*PSTG, (kc + 1) * 64);
            CP_COMMIT();
            CP_WAIT(1);
        } else {
            CP_WAIT(0);
        }
        __syncthreads();

        const uint32_t st = sb + s * PSTG;
        #pragma unroll
        for (int ks = 0; ks < 4; ks++) {
            uint32_t A[4][4], B[4][2];
            #pragma unroll
            for (int mi = 0; mi < 4; mi++) {
                const uint32_t ra = st
                    + (uint32_t)(wm*64 + mi*16 + wi + (grp&1)*8) * ROWB
                    + (uint32_t)(ks*32 + (grp>>1)*16);
                ldm_x4(A[mi], ra);
            }
            #pragma unroll
            for (int bt = 0; bt < 2; bt++) {
                const uint32_t rb = st + PTILE
                    + (uint32_t)(wn*32 + bt*16 + wi + (grp>>1)*8) * ROWB
                    + (uint32_t)(ks*32 + (grp&1)*16);
                uint32_t r[4];
                ldm_x4(r, rb);
                B[bt*2][0] = r[0]; B[bt*2][1] = r[1];
                B[bt*2+1][0] = r[2]; B[bt*2+1][1] = r[3];
            }
            #pragma unroll
            for (int mi = 0; mi < 4; mi++)
                #pragma unroll
                for (int nt = 0; nt < 4; nt++)
                    mma_f16(acc[mi][nt], A[mi], B[nt]);
        }
        __syncthreads();
    }

    // epilogue: BN affine + fp32 store (bn row 3)
    #pragma unroll
    for (int mi = 0; mi < 4; mi++) {
        const int rA = r0 + wm*64 + mi*16 + (lane >> 2);
        const int rB = rA + 8;
        const float invA  = bng[3*Cc + rA] / sqrtf(bnv[3*Cc + rA] + EPSBN);
        const float biasA = bnb[3*Cc + rA] - bnm[3*Cc + rA] * invA;
        const float invB  = bng[3*Cc + rB] / sqrtf(bnv[3*Cc + rB] + EPSBN);
        const float biasB = bnb[3*Cc + rB] - bnm[3*Cc + rB] * invB;
        float* pA = extout + ((size_t)b * Cc + rA) * Nn + n0;
        float* pB = extout + ((size_t)b * Cc + rB) * Nn + n0;
        #pragma unroll
        for (int nt = 0; nt < 4; nt++) {
            const int nc = wn*32 + nt*8 + (lane & 3)*2;
            float2 v0, v1;
            v0.x = acc[mi][nt][0]*invA + biasA;
            v0.y = acc[mi][nt][1]*invA + biasA;
            v1.x = acc[mi][nt][2]*invB + biasB;
            v1.y = acc[mi][nt][3]*invB + biasB;
            *(float2*)&pA[nc] = v0;
            *(float2*)&pB[nc] = v1;
        }
    }
}

// =====================================================================
// Attention (reassociated) + LIF, fused per (b', h)  — R8 proven version
// =====================================================================
__global__ __launch_bounds__(256) void attn_kernel()
{
    extern __shared__ __align__(16) float sm[];
    float* Ms = sm;
    float* Sa = sm + 4*64*64;
    float* Sb = Sa + 64*68;

    const int bp = blockIdx.x;
    const int h  = blockIdx.y;
    const int tid = threadIdx.x;
    const int ty = tid >> 4, tx = tid & 15;
    const int sRow = tid >> 2;
    const int sCol = (tid & 3) * 4;

    for (int t = 0; t < 4; t++) {
        const int b = t*BpC + bp;
        const float* K = g_spk + (size_t)SZ   + ((size_t)b*Cc + h*GD) * Nn;
        const float* V = g_spk + (size_t)2*SZ + ((size_t)b*Cc + h*GD) * Nn;

        ull accM[4][2];
        #pragma unroll
        for (int i = 0; i < 4; i++) { accM[i][0] = 0ull; accM[i][1] = 0ull; }

        for (int m0 = 0; m0 < Nn; m0 += 64) {
            float4 kv[4], vv[4];
            #pragma unroll
            for (int j = 0; j < 4; j++) {
                kv[j] = *(const float4*)&K[(size_t)sRow * Nn + m0 + sCol + 16*j];
                vv[j] = *(const float4*)&V[(size_t)sRow * Nn + m0 + sCol + 16*j];
            }
            __syncthreads();
            #pragma unroll
            for (int j = 0; j < 4; j++) {
                const int m = sCol + 16*j;
                Sa[(m+0)*68 + sRow] = kv[j].x; Sa[(m+1)*68 + sRow] = kv[j].y;
                Sa[(m+2)*68 + sRow] = kv[j].z; Sa[(m+3)*68 + sRow] = kv[j].w;
                Sb[(m+0)*68 + sRow] = vv[j].x; Sb[(m+1)*68 + sRow] = vv[j].y;
                Sb[(m+2)*68 + sRow] = vv[j].z; Sb[(m+3)*68 + sRow] = vv[j].w;
            }
            __syncthreads();
            #pragma unroll 8
            for (int mm = 0; mm < 64; mm++) {
                float4 ka = *(const float4*)&Sa[mm*68 + ty*4];
                ulonglong2 vp = *(const ulonglong2*)&Sb[mm*68 + tx*4];
                const float kf[4] = {ka.x, ka.y, ka.z, ka.w};
                #pragma unroll
                for (int i = 0; i < 4; i++) {
                    ull kb = bcast2(kf[i]);
                    ffma2(accM[i][0], kb, vp.x);
                    ffma2(accM[i][1], kb, vp.y);
                }
            }
        }
        #pragma unroll
        for (int i = 0; i < 4; i++) {
            float2 a = unpack2(accM[i][0]);
            float2 c2 = unpack2(accM[i][1]);
            float4 mo; mo.x = a.x; mo.y = a.y; mo.z = c2.x; mo.w = c2.y;
            *(float4*)&Ms[t*4096 + (ty*4 + i)*64 + tx*4] = mo;
        }
    }
    __syncthreads();

    for (int n0 = 0; n0 < Nn; n0 += 64) {
        float mem[4][4];
        #pragma unroll
        for (int i = 0; i < 4; i++)
            #pragma unroll
            for (int j = 0; j < 4; j++) mem[i][j] = 0.f;

        for (int t = 0; t < 4; t++) {
            const int b = t*BpC + bp;
            const float* Q = g_spk + ((size_t)b*Cc + h*GD) * Nn;
            float4 qv[4];
            #pragma unroll
            for (int j = 0; j < 4; j++)
                qv[j] = *(const float4*)&Q[(size_t)sRow * Nn + n0 + sCol + 16*j];
            __syncthreads();
            #pragma unroll
            for (int j = 0; j < 4; j++)
                *(float4*)&Sa[sRow*68 + sCol + 16*j] = qv[j];
            __syncthreads();

            ull acc[4][2];
            #pragma unroll
            for (int i = 0; i < 4; i++) { acc[i][0] = 0ull; acc[i][1] = 0ull; }

            #pragma unroll 8
            for (int dk = 0; dk < 64; dk++) {
                float4 mv = *(const float4*)&Ms[t*4096 + dk*64 + ty*4];
                ulonglong2 qp = *(const ulonglong2*)&Sa[dk*68 + tx*4];
                const float mf[4] = {mv.x, mv.y, mv.z, mv.w};
                #pragma unroll
                for (int i = 0; i < 4; i++) {
                    ull mb = bcast2(mf[i]);
                    ffma2(acc[i][0], mb, qp.x);
                    ffma2(acc[i][1], mb, qp.y);
                }
            }

            float* so = g_so + ((size_t)b*Cc + h*GD) * Nn;
            #pragma unroll
            for (int i = 0; i < 4; i++) {
                float2 a = unpack2(acc[i][0]);
                float2 c2 = unpack2(acc[i][1]);
                float o[4] = {a.x, a.y, c2.x, c2.y};
                float s[4];
                #pragma unroll
                for (int j = 0; j < 4; j++) {
                    mem[i][j] = mem[i][j]*TAU + o[j]*SCALE;
                    s[j] = (mem[i][j] > THRESH) ? 1.f : 0.f;
                    if (mem[i][j] > THRESH) mem[i][j] = 0.f;
                }
                float4 sv; sv.x = s[0]; sv.y = s[1]; sv.z = s[2]; sv.w = s[3];
                *(float4*)&so[(size_t)(ty*4 + i) * Nn + n0 + tx*4] = sv;
            }
        }
    }
}

// =====================================================================
// launch
// =====================================================================
extern "C" void kernel_launch(void* const* d_in, const int* in_sizes, int n_in,
                              void* d_out, int out_size)
{
    const float* x     = (const float*)d_in[0];
    const float* wq    = (const float*)d_in[1];
    const float* wk    = (const float*)d_in[2];
    const float* wv    = (const float*)d_in[3];
    const float* wproj = (const float*)d_in[4];
    const float* bng   = (const float*)d_in[5];
    const float* bnb   = (const float*)d_in[6];
    const float* bnm   = (const float*)d_in[7];
    const float* bnv   = (const float*)d_in[8];
    float* out = (float*)d_out;

    const int conv_smem = 2 * STAGEB;   // 147,456 B
    cudaFuncSetAttribute(hmma_conv_lif, cudaFuncAttributeMaxDynamicSharedMemorySize, conv_smem);
    cudaFuncSetAttribute(proj_conv, cudaFuncAttributeMaxDynamicSharedMemorySize, PROJ_SMEM);
    const int attn_smem = (4*64*64 + 2*64*68) * (int)sizeof(float);  // 100,352 B
    cudaFuncSetAttribute(attn_kernel, cudaFuncAttributeMaxDynamicSharedMemorySize, attn_smem);

    wsplit_kernel<<<dim3(1024, 4), 256>>>(wq, wk, wv, wproj);
    split_t_kernel<<<dim3(16, 16, 64), dim3(32, 8)>>>(x, 0);

    // merged q,k,v conv_bn + fused LIF (grid z = bp, t-loop inside)
    hmma_conv_lif<<<dim3(4, 12, 16), 256, conv_smem>>>(bng, bnb, bnm, bnv);

    attn_kernel<<<dim3(BpC, Hh), 256, attn_smem>>>();

    split_t_kernel<<<dim3(16, 16, 64), dim3(32, 8)>>>(x, 1);   // g_so -> g_s16

    // proj conv_bn (fp16 single-term)
    proj_conv<<<dim3(4, 4, 64), 256, PROJ_SMEM>>>(out, bng, bnb, bnm, bnv);
}

// round 14
// speedup vs baseline: 2.0698x; 1.0637x over previous
#include <cuda_runtime.h>
#include <cuda_bf16.h>
#include <cuda_fp16.h>
#include <cstdint>
#include <cstddef>

// ---------------- problem constants ----------------
#define Tt      4
#define Bt      64
#define BpC     16
#define Cc      512
#define Nn      512
#define Hh      8
#define GD      64
#define TAU     0.5f
#define THRESH  1.0f
#define SCALE   0.125f
#define EPSBN   1e-5f
#define SZ      (Bt*Cc*Nn)      // 16,777,216
#define CN      (Cc*Nn)

typedef unsigned long long ull;

// ---------------- scratch (device globals) ----------------
__device__ __align__(128) float g_spk[3ll*SZ];
__device__ __align__(128) float g_so [SZ];
__device__ __align__(128) float g_M  [16*8*4*4096];   // M_t per (bp,h,t): 8 MB
__device__ __align__(128) __nv_bfloat16 g_xhi[SZ];    // [b][n][c]
__device__ __align__(128) __nv_bfloat16 g_xlo[SZ];
__device__ __align__(128) __half        g_s16[SZ];    // spikes fp16 [b][n][c]
__device__ __align__(128) __nv_bfloat16 g_whi[3ll*CN];
__device__ __align__(128) __nv_bfloat16 g_wlo[3ll*CN];
__device__ __align__(128) __half        g_wp16[CN];   // proj weights fp16

// ---------------- PTX helpers ----------------
static __device__ __forceinline__ uint32_t smem_u32(const void* p) {
    uint32_t a;
    asm("{ .reg .u64 t; cvta.to.shared.u64 t, %1; cvt.u32.u64 %0, t; }" : "=r"(a) : "l"(p));
    return a;
}
static __device__ __forceinline__ void cpasync16(uint32_t dst, const void* src) {
    asm volatile("cp.async.cg.shared.global [%0], [%1], 16;" :: "r"(dst), "l"(src));
}
#define CP_COMMIT()  asm volatile("cp.async.commit_group;" ::: "memory")
#define CP_WAIT(n)   asm volatile("cp.async.wait_group %0;" :: "n"(n) : "memory")

static __device__ __forceinline__ void ldm_x4(uint32_t* r, uint32_t addr) {
    asm volatile("ldmatrix.sync.aligned.m8n8.x4.shared.b16 {%0,%1,%2,%3}, [%4];"
        : "=r"(r[0]), "=r"(r[1]), "=r"(r[2]), "=r"(r[3]) : "r"(addr));
}
static __device__ __forceinline__ void mma_bf16(float* c, const uint32_t* a, const uint32_t* b) {
    asm volatile("mma.sync.aligned.m16n8k16.row.col.f32.bf16.bf16.f32 "
        "{%0,%1,%2,%3}, {%4,%5,%6,%7}, {%8,%9}, {%0,%1,%2,%3};"
        : "+f"(c[0]), "+f"(c[1]), "+f"(c[2]), "+f"(c[3])
        : "r"(a[0]), "r"(a[1]), "r"(a[2]), "r"(a[3]), "r"(b[0]), "r"(b[1]));
}
static __device__ __forceinline__ void mma_f16(float* c, const uint32_t* a, const uint32_t* b) {
    asm volatile("mma.sync.aligned.m16n8k16.row.col.f32.f16.f16.f32 "
        "{%0,%1,%2,%3}, {%4,%5,%6,%7}, {%8,%9}, {%0,%1,%2,%3};"
        : "+f"(c[0]), "+f"(c[1]), "+f"(c[2]), "+f"(c[3])
        : "r"(a[0]), "r"(a[1]), "r"(a[2]), "r"(a[3]), "r"(b[0]), "r"(b[1]));
}

// ---------------- fp32x2 helpers (attn kernels) ----------------
static __device__ __forceinline__ void ffma2(ull& d, ull a, ull b) {
    asm("fma.rn.f32x2 %0, %1, %2, %0;" : "+l"(d) : "l"(a), "l"(b));
}
static __device__ __forceinline__ ull bcast2(float w) {
    ull r; asm("mov.b64 %0, {%1, %1};" : "=l"(r) : "f"(w)); return r;
}
static __device__ __forceinline__ float2 unpack2(ull v) {
    float2 f; asm("mov.b64 {%0, %1}, %2;" : "=f"(f.x), "=f"(f.y) : "l"(v)); return f;
}

// =====================================================================
// weight split: qkv -> bf16 hi/lo; proj -> fp16 single
// =====================================================================
__global__ __launch_bounds__(256) void wsplit_kernel(
    const float* __restrict__ wq, const float* __restrict__ wk,
    const float* __restrict__ wv, const float* __restrict__ wp)
{
    const int which = blockIdx.y;
    const float* w = (which == 0) ? wq : (which == 1) ? wk : (which == 2) ? wv : wp;
    const int i = blockIdx.x * 256 + threadIdx.x;
    float v = w[i];
    if (which < 3) {
        __nv_bfloat16 h = __float2bfloat16(v);
        g_whi[(size_t)which * CN + i] = h;
        g_wlo[(size_t)which * CN + i] = __float2bfloat16(v - __bfloat162float(h));
    } else {
        g_wp16[i] = __float2half(v);
    }
}

// =====================================================================
// transpose + split: fp32 [b][c][n] -> [b][n][c]
// mode 0: x -> g_xhi/g_xlo (bf16).  mode 1: g_so spikes -> g_s16 (fp16, exact)
// =====================================================================
__global__ __launch_bounds__(256) void split_t_kernel(const float* __restrict__ in, int mode)
{
    __shared__ float t[32][33];
    const int b = blockIdx.z, c0 = blockIdx.y * 32, n0 = blockIdx.x * 32;
    const int tx = threadIdx.x, ty = threadIdx.y;
    const float* ib = (mode ? (const float*)g_so : in) + (size_t)b * CN;
    #pragma unroll
    for (int j = 0; j < 4; j++)
        t[ty + 8*j][tx] = ib[(size_t)(c0 + ty + 8*j) * Nn + n0 + tx];
    __syncthreads();
    #pragma unroll
    for (int j = 0; j < 4; j++) {
        const int n = ty + 8*j;
        const float v = t[tx][n];
        const size_t o = ((size_t)b * Nn + n0 + n) * Cc + c0 + tx;
        if (mode == 0) {
            const __nv_bfloat16 h = __float2bfloat16(v);
            g_xhi[o] = h;
            g_xlo[o] = __float2bfloat16(v - __bfloat162float(h));
        } else {
            g_s16[o] = __float2half(v);
        }
    }
}

// =====================================================================
// qkv HMMA conv_bn + FUSED LIF (R13): grid (4, 12, 16 bp), t-loop inside
// =====================================================================
#define ROWB   144
#define TILEB  (128*ROWB)
#define STAGEB (4*TILEB)

__global__ __launch_bounds__(256) void hmma_conv_lif(
    const float* __restrict__ bng, const float* __restrict__ bnb,
    const float* __restrict__ bnm, const float* __restrict__ bnv)
{
    extern __shared__ char smem[];
    const uint32_t sb = smem_u32(smem);
    const int tid  = threadIdx.x;
    const int wid  = tid >> 5, lane = tid & 31;
    const int n0   = blockIdx.x * 128;
    const int bp   = blockIdx.z;
    const int wsel = blockIdx.y >> 2;
    const int r0   = (blockIdx.y & 3) * 128;

    float* spk = g_spk + (size_t)wsel * SZ;
    const __nv_bfloat16* wh = g_whi + (size_t)wsel * CN + (size_t)r0 * Cc;
    const __nv_bfloat16* wl = g_wlo + (size_t)wsel * CN + (size_t)r0 * Cc;

    const int lrow = tid >> 1;
    const int cb0  = (tid & 1) * 4;
    const uint32_t rowOff = (uint32_t)lrow * ROWB;
    const __nv_bfloat16* gAh = wh + (size_t)lrow * Cc;
    const __nv_bfloat16* gAl = wl + (size_t)lrow * Cc;

    const int wm = wid & 1, wn = wid >> 1;
    const int grp = lane >> 3, wi = lane & 7;

    float invA[4], biasA[4], invB[4], biasB[4];
    #pragma unroll
    for (int mi = 0; mi < 4; mi++) {
        const int rA = r0 + wm*64 + mi*16 + (lane >> 2);
        const int rB = rA + 8;
        invA[mi]  = bng[wsel*Cc + rA] / sqrtf(bnv[wsel*Cc + rA] + EPSBN);
        biasA[mi] = bnb[wsel*Cc + rA] - bnm[wsel*Cc + rA] * invA[mi];
        invB[mi]  = bng[wsel*Cc + rB] / sqrtf(bnv[wsel*Cc + rB] + EPSBN);
        biasB[mi] = bnb[wsel*Cc + rB] - bnm[wsel*Cc + rB] * invB[mi];
    }

    float mem[4][4][4];
    #pragma unroll
    for (int i = 0; i < 4; i++)
        #pragma unroll
        for (int j = 0; j < 4; j++)
            #pragma unroll
            for (int q = 0; q < 4; q++) mem[i][j][q] = 0.f;

    for (int t = 0; t < 4; t++) {
        const int b = t*BpC + bp;
        const __nv_bfloat16* gBh = g_xhi + ((size_t)b * Nn + n0) * Cc + (size_t)lrow * Cc;
        const __nv_bfloat16* gBl = g_xlo + ((size_t)b * Nn + n0) * Cc + (size_t)lrow * Cc;

        float acc[4][4][4];
        #pragma unroll
        for (int i = 0; i < 4; i++)
            #pragma unroll
            for (int j = 0; j < 4; j++)
                #pragma unroll
                for (int q = 0; q < 4; q++) acc[i][j][q] = 0.f;

        auto load_stage = [&](uint32_t st, int k0) {
            #pragma unroll
            for (int j = 0; j < 4; j++) {
                const int c = cb0 + j;
                const uint32_t off = rowOff + c * 16;
                cpasync16(st + off,           gAh + k0 + c*8);
                cpasync16(st + TILEB + off,   gAl + k0 + c*8);
                cpasync16(st + 2*TILEB + off, gBh + k0 + c*8);
                cpasync16(st + 3*TILEB + off, gBl + k0 + c*8);
            }
        };

        load_stage(sb, 0);
        CP_COMMIT();

        for (int kc = 0; kc < 8; kc++) {
            const int s = kc & 1;
            if (kc < 7) {
                load_stage(sb + (s^1)*STAGEB, (kc + 1) * 64);
                CP_COMMIT();
                CP_WAIT(1);
            } else {
                CP_WAIT(0);
            }
            __syncthreads();

            const uint32_t st = sb + s * STAGEB;
            #pragma unroll
            for (int ks = 0; ks < 4; ks++) {
                uint32_t Ah[4][4], Al[4][4], Bh[4][2], Bl[4][2];
                #pragma unroll
                for (int mi = 0; mi < 4; mi++) {
                    const uint32_t ra = st
                        + (uint32_t)(wm*64 + mi*16 + wi + (grp&1)*8) * ROWB
                        + (uint32_t)(ks*32 + (grp>>1)*16);
                    ldm_x4(Ah[mi], ra);
                    ldm_x4(Al[mi], ra + TILEB);
                }
                #pragma unroll
                for (int bt = 0; bt < 2; bt++) {
                    const uint32_t rb = st + 2*TILEB
                        + (uint32_t)(wn*32 + bt*16 + wi + (grp>>1)*8) * ROWB
                        + (uint32_t)(ks*32 + (grp&1)*16);
                    uint32_t r[4];
                    ldm_x4(r, rb);
                    Bh[bt*2][0] = r[0]; Bh[bt*2][1] = r[1];
                    Bh[bt*2+1][0] = r[2]; Bh[bt*2+1][1] = r[3];
                    ldm_x4(r, rb + TILEB);
                    Bl[bt*2][0] = r[0]; Bl[bt*2][1] = r[1];
                    Bl[bt*2+1][0] = r[2]; Bl[bt*2+1][1] = r[3];
                }
                #pragma unroll
                for (int mi = 0; mi < 4; mi++)
                    #pragma unroll
                    for (int nt = 0; nt < 4; nt++)
                        mma_bf16(acc[mi][nt], Ah[mi], Bh[nt]);
                #pragma unroll
                for (int mi = 0; mi < 4; mi++)
                    #pragma unroll
                    for (int nt = 0; nt < 4; nt++)
                        mma_bf16(acc[mi][nt], Al[mi], Bh[nt]);
                #pragma unroll
                for (int mi = 0; mi < 4; mi++)
                    #pragma unroll
                    for (int nt = 0; nt < 4; nt++)
                        mma_bf16(acc[mi][nt], Ah[mi], Bl[nt]);
            }
            __syncthreads();
        }

        #pragma unroll
        for (int mi = 0; mi < 4; mi++) {
            const int rA = r0 + wm*64 + mi*16 + (lane >> 2);
            const int rB = rA + 8;
            float* pA = spk + ((size_t)b * Cc + rA) * Nn + n0;
            float* pB = spk + ((size_t)b * Cc + rB) * Nn + n0;
            #pragma unroll
            for (int nt = 0; nt < 4; nt++) {
                const int nc = wn*32 + nt*8 + (lane & 3)*2;
                float pre[4];
                pre[0] = acc[mi][nt][0]*invA[mi] + biasA[mi];
                pre[1] = acc[mi][nt][1]*invA[mi] + biasA[mi];
                pre[2] = acc[mi][nt][2]*invB[mi] + biasB[mi];
                pre[3] = acc[mi][nt][3]*invB[mi] + biasB[mi];
                float s[4];
                #pragma unroll
                for (int q = 0; q < 4; q++) {
                    mem[mi][nt][q] = mem[mi][nt][q]*TAU + pre[q];
                    s[q] = (mem[mi][nt][q] > THRESH) ? 1.f : 0.f;
                    if (mem[mi][nt][q] > THRESH) mem[mi][nt][q] = 0.f;
                }
                float2 v0, v1;
                v0.x = s[0]; v0.y = s[1];
                v1.x = s[2]; v1.y = s[3];
                *(float2*)&pA[nc] = v0;
                *(float2*)&pB[nc] = v1;
            }
        }
    }
}

// =====================================================================
// proj conv_bn: fp16 SINGLE-term. grid (4, 4, 64), 2 CTAs/SM
// =====================================================================
#define PTILE  (128*ROWB)               // 18432
#define PSTG   (2*PTILE)                // 36864
#define PROJ_SMEM (2*PSTG)              // 73728

__global__ __launch_bounds__(256, 2) void proj_conv(
    float* __restrict__ extout,
    const float* __restrict__ bng, const float* __restrict__ bnb,
    const float* __restrict__ bnm, const float* __restrict__ bnv)
{
    extern __shared__ char smem[];
    const uint32_t sb = smem_u32(smem);
    const int tid  = threadIdx.x;
    const int wid  = tid >> 5, lane = tid & 31;
    const int n0   = blockIdx.x * 128;
    const int r0   = blockIdx.y * 128;
    const int b    = blockIdx.z;

    const __half* wp = g_wp16 + (size_t)r0 * Cc;
    const __half* sp = g_s16 + ((size_t)b * Nn + n0) * Cc;

    const int lrow = tid >> 1;
    const int cb0  = (tid & 1) * 4;
    const uint32_t rowOff = (uint32_t)lrow * ROWB;
    const __half* gA = wp + (size_t)lrow * Cc;
    const __half* gB = sp + (size_t)lrow * Cc;

    float acc[4][4][4];
    #pragma unroll
    for (int i = 0; i < 4; i++)
        #pragma unroll
        for (int j = 0; j < 4; j++)
            #pragma unroll
            for (int q = 0; q < 4; q++) acc[i][j][q] = 0.f;

    const int wm = wid & 1, wn = wid >> 1;
    const int grp = lane >> 3, wi = lane & 7;

    auto load_stage = [&](uint32_t st, int k0) {
        #pragma unroll
        for (int j = 0; j < 4; j++) {
            const int c = cb0 + j;
            const uint32_t off = rowOff + c * 16;
            cpasync16(st + off,         gA + k0 + c*8);
            cpasync16(st + PTILE + off, gB + k0 + c*8);
        }
    };

    load_stage(sb, 0);
    CP_COMMIT();

    for (int kc = 0; kc < 8; kc++) {
        const int s = kc & 1;
        if (kc < 7) {
            load_stage(sb + (s^1)*PSTG, (kc + 1) * 64);
            CP_COMMIT();
            CP_WAIT(1);
        } else {
            CP_WAIT(0);
        }
        __syncthreads();

        const uint32_t st = sb + s * PSTG;
        #pragma unroll
        for (int ks = 0; ks < 4; ks++) {
            uint32_t A[4][4], B[4][2];
            #pragma unroll
            for (int mi = 0; mi < 4; mi++) {
                const uint32_t ra = st
                    + (uint32_t)(wm*64 + mi*16 + wi + (grp&1)*8) * ROWB
                    + (uint32_t)(ks*32 + (grp>>1)*16);
                ldm_x4(A[mi], ra);
            }
            #pragma unroll
            for (int bt = 0; bt < 2; bt++) {
                const uint32_t rb = st + PTILE
                    + (uint32_t)(wn*32 + bt*16 + wi + (grp>>1)*8) * ROWB
                    + (uint32_t)(ks*32 + (grp&1)*16);
                uint32_t r[4];
                ldm_x4(r, rb);
                B[bt*2][0] = r[0]; B[bt*2][1] = r[1];
                B[bt*2+1][0] = r[2]; B[bt*2+1][1] = r[3];
            }
            #pragma unroll
            for (int mi = 0; mi < 4; mi++)
                #pragma unroll
                for (int nt = 0; nt < 4; nt++)
                    mma_f16(acc[mi][nt], A[mi], B[nt]);
        }
        __syncthreads();
    }

    #pragma unroll
    for (int mi = 0; mi < 4; mi++) {
        const int rA = r0 + wm*64 + mi*16 + (lane >> 2);
        const int rB = rA + 8;
        const float invA  = bng[3*Cc + rA] / sqrtf(bnv[3*Cc + rA] + EPSBN);
        const float biasA = bnb[3*Cc + rA] - bnm[3*Cc + rA] * invA;
        const float invB  = bng[3*Cc + rB] / sqrtf(bnv[3*Cc + rB] + EPSBN);
        const float biasB = bnb[3*Cc + rB] - bnm[3*Cc + rB] * invB;
        float* pA = extout + ((size_t)b * Cc + rA) * Nn + n0;
        float* pB = extout + ((size_t)b * Cc + rB) * Nn + n0;
        #pragma unroll
        for (int nt = 0; nt < 4; nt++) {
            const int nc = wn*32 + nt*8 + (lane & 3)*2;
            float2 v0, v1;
            v0.x = acc[mi][nt][0]*invA + biasA;
            v0.y = acc[mi][nt][1]*invA + biasA;
            v1.x = acc[mi][nt][2]*invB + biasB;
            v1.y = acc[mi][nt][3]*invB + biasB;
            *(float2*)&pA[nc] = v0;
            *(float2*)&pB[nc] = v1;
        }
    }
}

// =====================================================================
// attn_m: M_t = K_t V_t^T (64x64, inner 512) per (bp, h, t) -> g_M
// grid (16, 8, 4), 256 threads. Same arithmetic as R8 M-phase.
// =====================================================================
__global__ __launch_bounds__(256) void attn_m_kernel()
{
    __shared__ __align__(16) float Sa[64*68];
    __shared__ __align__(16) float Sb[64*68];

    const int bp = blockIdx.x;
    const int h  = blockIdx.y;
    const int t  = blockIdx.z;
    const int tid = threadIdx.x;
    const int ty = tid >> 4, tx = tid & 15;
    const int sRow = tid >> 2;
    const int sCol = (tid & 3) * 4;

    const int b = t*BpC + bp;
    const float* K = g_spk + (size_t)SZ   + ((size_t)b*Cc + h*GD) * Nn;
    const float* V = g_spk + (size_t)2*SZ + ((size_t)b*Cc + h*GD) * Nn;

    ull accM[4][2];
    #pragma unroll
    for (int i = 0; i < 4; i++) { accM[i][0] = 0ull; accM[i][1] = 0ull; }

    for (int m0 = 0; m0 < Nn; m0 += 64) {
        float4 kv[4], vv[4];
        #pragma unroll
        for (int j = 0; j < 4; j++) {
            kv[j] = *(const float4*)&K[(size_t)sRow * Nn + m0 + sCol + 16*j];
            vv[j] = *(const float4*)&V[(size_t)sRow * Nn + m0 + sCol + 16*j];
        }
        __syncthreads();
        #pragma unroll
        for (int j = 0; j < 4; j++) {
            const int m = sCol + 16*j;
            Sa[(m+0)*68 + sRow] = kv[j].x; Sa[(m+1)*68 + sRow] = kv[j].y;
            Sa[(m+2)*68 + sRow] = kv[j].z; Sa[(m+3)*68 + sRow] = kv[j].w;
            Sb[(m+0)*68 + sRow] = vv[j].x; Sb[(m+1)*68 + sRow] = vv[j].y;
            Sb[(m+2)*68 + sRow] = vv[j].z; Sb[(m+3)*68 + sRow] = vv[j].w;
        }
        __syncthreads();
        #pragma unroll 8
        for (int mm = 0; mm < 64; mm++) {
            float4 ka = *(const float4*)&Sa[mm*68 + ty*4];
            ulonglong2 vp = *(const ulonglong2*)&Sb[mm*68 + tx*4];
            const float kf[4] = {ka.x, ka.y, ka.z, ka.w};
            #pragma unroll
            for (int i = 0; i < 4; i++) {
                ull kb = bcast2(kf[i]);
                ffma2(accM[i][0], kb, vp.x);
                ffma2(accM[i][1], kb, vp.y);
            }
        }
    }

    float* Mout = g_M + (((size_t)(bp*Hh + h) * 4) + t) * 4096;
    #pragma unroll
    for (int i = 0; i < 4; i++) {
        float2 a = unpack2(accM[i][0]);
        float2 c2 = unpack2(accM[i][1]);
        float4 mo; mo.x = a.x; mo.y = a.y; mo.z = c2.x; mo.w = c2.y;
        *(float4*)&Mout[(ty*4 + i)*64 + tx*4] = mo;
    }
}

// =====================================================================
// attn_out: out = SCALE * M_t^T Q_t + LIF over t, per (bp, h, nq)
// grid (16, 8, 4), 256 threads. Each CTA handles 128 n-columns.
// smem: Ms 64KB + Sa 17.4KB
// =====================================================================
__global__ __launch_bounds__(256) void attn_out_kernel()
{
    extern __shared__ __align__(16) float sm[];
    float* Ms = sm;                      // [4][64][64]
    float* Sa = sm + 4*4096;             // [64][68]

    const int bp = blockIdx.x;
    const int h  = blockIdx.y;
    const int nq = blockIdx.z;
    const int tid = threadIdx.x;
    const int ty = tid >> 4, tx = tid & 15;
    const int sRow = tid >> 2;
    const int sCol = (tid & 3) * 4;

    // load all 4 M_t into smem (contiguous copy)
    const float* Min = g_M + ((size_t)(bp*Hh + h) * 4) * 4096;
    #pragma unroll
    for (int j = 0; j < 16; j++)
        *(float4*)&Ms[(tid + j*256) * 4] = *(const float4*)&Min[(tid + j*256) * 4];
    __syncthreads();

    for (int n0 = nq*128; n0 < nq*128 + 128; n0 += 64) {
        float mem[4][4];
        #pragma unroll
        for (int i = 0; i < 4; i++)
            #pragma unroll
            for (int j = 0; j < 4; j++) mem[i][j] = 0.f;

        for (int t = 0; t < 4; t++) {
            const int b = t*BpC + bp;
            const float* Q = g_spk + ((size_t)b*Cc + h*GD) * Nn;
            float4 qv[4];
            #pragma unroll
            for (int j = 0; j < 4; j++)
                qv[j] = *(const float4*)&Q[(size_t)sRow * Nn + n0 + sCol + 16*j];
            __syncthreads();
            #pragma unroll
            for (int j = 0; j < 4; j++)
                *(float4*)&Sa[sRow*68 + sCol + 16*j] = qv[j];
            __syncthreads();

            ull acc[4][2];
            #pragma unroll
            for (int i = 0; i < 4; i++) { acc[i][0] = 0ull; acc[i][1] = 0ull; }

            #pragma unroll 8
            for (int dk = 0; dk < 64; dk++) {
                float4 mv = *(const float4*)&Ms[t*4096 + dk*64 + ty*4];
                ulonglong2 qp = *(const ulonglong2*)&Sa[dk*68 + tx*4];
                const float mf[4] = {mv.x, mv.y, mv.z, mv.w};
                #pragma unroll
                for (int i = 0; i < 4; i++) {
                    ull mb = bcast2(mf[i]);
                    ffma2(acc[i][0], mb, qp.x);
                    ffma2(acc[i][1], mb, qp.y);
                }
            }

            float* so = g_so + ((size_t)b*Cc + h*GD) * Nn;
            #pragma unroll
            for (int i = 0; i < 4; i++) {
                float2 a = unpack2(acc[i][0]);
                float2 c2 = unpack2(acc[i][1]);
                float o[4] = {a.x, a.y, c2.x, c2.y};
                float s[4];
                #pragma unroll
                for (int j = 0; j < 4; j++) {
                    mem[i][j] = mem[i][j]*TAU + o[j]*SCALE;
                    s[j] = (mem[i][j] > THRESH) ? 1.f : 0.f;
                    if (mem[i][j] > THRESH) mem[i][j] = 0.f;
                }
                float4 sv; sv.x = s[0]; sv.y = s[1]; sv.z = s[2]; sv.w = s[3];
                *(float4*)&so[(size_t)(ty*4 + i) * Nn + n0 + tx*4] = sv;
            }
        }
    }
}

// =====================================================================
// launch
// =====================================================================
extern "C" void kernel_launch(void* const* d_in, const int* in_sizes, int n_in,
                              void* d_out, int out_size)
{
    const float* x     = (const float*)d_in[0];
    const float* wq    = (const float*)d_in[1];
    const float* wk    = (const float*)d_in[2];
    const float* wv    = (const float*)d_in[3];
    const float* wproj = (const float*)d_in[4];
    const float* bng   = (const float*)d_in[5];
    const float* bnb   = (const float*)d_in[6];
    const float* bnm   = (const float*)d_in[7];
    const float* bnv   = (const float*)d_in[8];
    float* out = (float*)d_out;

    const int conv_smem = 2 * STAGEB;   // 147,456 B
    cudaFuncSetAttribute(hmma_conv_lif, cudaFuncAttributeMaxDynamicSharedMemorySize, conv_smem);
    cudaFuncSetAttribute(proj_conv, cudaFuncAttributeMaxDynamicSharedMemorySize, PROJ_SMEM);
    const int aout_smem = (4*4096 + 64*68) * (int)sizeof(float);   // 82,944 B
    cudaFuncSetAttribute(attn_out_kernel, cudaFuncAttributeMaxDynamicSharedMemorySize, aout_smem);

    wsplit_kernel<<<dim3(1024, 4), 256>>>(wq, wk, wv, wproj);
    split_t_kernel<<<dim3(16, 16, 64), dim3(32, 8)>>>(x, 0);

    // merged q,k,v conv_bn + fused LIF
    hmma_conv_lif<<<dim3(4, 12, 16), 256, conv_smem>>>(bng, bnb, bnm, bnv);

    // attention: M-phase (512 CTAs) then out-phase (512 CTAs)
    attn_m_kernel<<<dim3(BpC, Hh, 4), 256>>>();
    attn_out_kernel<<<dim3(BpC, Hh, 4), 256, aout_smem>>>();

    split_t_kernel<<<dim3(16, 16, 64), dim3(32, 8)>>>(x, 1);   // g_so -> g_s16

    // proj conv_bn (fp16 single-term)
    proj_conv<<<dim3(4, 4, 64), 256, PROJ_SMEM>>>(out, bng, bnb, bnm, bnv);
}

// round 15
// speedup vs baseline: 2.2609x; 1.0923x over previous
#include <cuda_runtime.h>
#include <cuda_bf16.h>
#include <cuda_fp16.h>
#include <cstdint>
#include <cstddef>

// ---------------- problem constants ----------------
#define Tt      4
#define Bt      64
#define BpC     16
#define Cc      512
#define Nn      512
#define Hh      8
#define GD      64
#define TAU     0.5f
#define THRESH  1.0f
#define SCALE   0.125f
#define EPSBN   1e-5f
#define SZ      (Bt*Cc*Nn)      // 16,777,216
#define CN      (Cc*Nn)

typedef unsigned long long ull;

// ---------------- scratch (device globals) ----------------
__device__ __align__(128) __half g_spkh[3ll*SZ];      // q,k,v spikes fp16 [b][c][n]
__device__ __align__(128) __half g_qT  [SZ];          // q spikes fp16 [b][n][c]
__device__ __align__(128) __half g_soh [SZ];          // attn spikes fp16 [b][c][n]
__device__ __align__(128) __half g_P   [16*8*4*4096]; // P per (bp,h,t) fp16: 4 MB
__device__ __align__(128) __nv_bfloat16 g_xhi[SZ];    // [b][n][c]
__device__ __align__(128) __nv_bfloat16 g_xlo[SZ];
__device__ __align__(128) __half        g_s16[SZ];    // attn spikes fp16 [b][n][c]
__device__ __align__(128) __nv_bfloat16 g_whi[3ll*CN];
__device__ __align__(128) __nv_bfloat16 g_wlo[3ll*CN];
__device__ __align__(128) __half        g_wp16[CN];

// ---------------- PTX helpers ----------------
static __device__ __forceinline__ uint32_t smem_u32(const void* p) {
    uint32_t a;
    asm("{ .reg .u64 t; cvta.to.shared.u64 t, %1; cvt.u32.u64 %0, t; }" : "=r"(a) : "l"(p));
    return a;
}
static __device__ __forceinline__ void cpasync16(uint32_t dst, const void* src) {
    asm volatile("cp.async.cg.shared.global [%0], [%1], 16;" :: "r"(dst), "l"(src));
}
#define CP_COMMIT()  asm volatile("cp.async.commit_group;" ::: "memory")
#define CP_WAIT(n)   asm volatile("cp.async.wait_group %0;" :: "n"(n) : "memory")

static __device__ __forceinline__ void ldm_x4(uint32_t* r, uint32_t addr) {
    asm volatile("ldmatrix.sync.aligned.m8n8.x4.shared.b16 {%0,%1,%2,%3}, [%4];"
        : "=r"(r[0]), "=r"(r[1]), "=r"(r[2]), "=r"(r[3]) : "r"(addr));
}
static __device__ __forceinline__ void mma_bf16(float* c, const uint32_t* a, const uint32_t* b) {
    asm volatile("mma.sync.aligned.m16n8k16.row.col.f32.bf16.bf16.f32 "
        "{%0,%1,%2,%3}, {%4,%5,%6,%7}, {%8,%9}, {%0,%1,%2,%3};"
        : "+f"(c[0]), "+f"(c[1]), "+f"(c[2]), "+f"(c[3])
        : "r"(a[0]), "r"(a[1]), "r"(a[2]), "r"(a[3]), "r"(b[0]), "r"(b[1]));
}
static __device__ __forceinline__ void mma_f16(float* c, const uint32_t* a, const uint32_t* b) {
    asm volatile("mma.sync.aligned.m16n8k16.row.col.f32.f16.f16.f32 "
        "{%0,%1,%2,%3}, {%4,%5,%6,%7}, {%8,%9}, {%0,%1,%2,%3};"
        : "+f"(c[0]), "+f"(c[1]), "+f"(c[2]), "+f"(c[3])
        : "r"(a[0]), "r"(a[1]), "r"(a[2]), "r"(a[3]), "r"(b[0]), "r"(b[1]));
}

// =====================================================================
// weight split: qkv -> bf16 hi/lo; proj -> fp16 single
// =====================================================================
__global__ __launch_bounds__(256) void wsplit_kernel(
    const float* __restrict__ wq, const float* __restrict__ wk,
    const float* __restrict__ wv, const float* __restrict__ wp)
{
    const int which = blockIdx.y;
    const float* w = (which == 0) ? wq : (which == 1) ? wk : (which == 2) ? wv : wp;
    const int i = blockIdx.x * 256 + threadIdx.x;
    float v = w[i];
    if (which < 3) {
        __nv_bfloat16 h = __float2bfloat16(v);
        g_whi[(size_t)which * CN + i] = h;
        g_wlo[(size_t)which * CN + i] = __float2bfloat16(v - __bfloat162float(h));
    } else {
        g_wp16[i] = __float2half(v);
    }
}

// =====================================================================
// x transpose + split: fp32 [b][c][n] -> bf16 hi/lo [b][n][c]
// =====================================================================
__global__ __launch_bounds__(256) void split_t_kernel(const float* __restrict__ in)
{
    __shared__ float t[32][33];
    const int b = blockIdx.z, c0 = blockIdx.y * 32, n0 = blockIdx.x * 32;
    const int tx = threadIdx.x, ty = threadIdx.y;
    const float* ib = in + (size_t)b * CN;
    #pragma unroll
    for (int j = 0; j < 4; j++)
        t[ty + 8*j][tx] = ib[(size_t)(c0 + ty + 8*j) * Nn + n0 + tx];
    __syncthreads();
    #pragma unroll
    for (int j = 0; j < 4; j++) {
        const int n = ty + 8*j;
        const float v = t[tx][n];
        const size_t o = ((size_t)b * Nn + n0 + n) * Cc + c0 + tx;
        const __nv_bfloat16 h = __float2bfloat16(v);
        g_xhi[o] = h;
        g_xlo[o] = __float2bfloat16(v - __bfloat162float(h));
    }
}

// =====================================================================
// fp16 transpose: [b][c][n] -> [b][n][c]
// mode 0: g_spkh q-plane -> g_qT.   mode 1: g_soh -> g_s16
// =====================================================================
__global__ __launch_bounds__(256) void transpose_h_kernel(int mode)
{
    __shared__ __half t[32][34];
    const int b = blockIdx.z, c0 = blockIdx.y * 32, n0 = blockIdx.x * 32;
    const int tid = threadIdx.x;
    const int tx = tid & 31, ty = tid >> 5;
    const __half* src = (mode ? g_soh : g_spkh) + (size_t)b * CN;
    __half* dst = (mode ? g_s16 : g_qT);
    #pragma unroll
    for (int j = 0; j < 4; j++)
        t[ty + 8*j][tx] = src[(size_t)(c0 + ty + 8*j) * Nn + n0 + tx];
    __syncthreads();
    #pragma unroll
    for (int j = 0; j < 4; j++) {
        const int n = ty + 8*j;
        dst[((size_t)b * Nn + n0 + n) * Cc + c0 + tx] = t[tx][n];
    }
}

// =====================================================================
// qkv HMMA conv_bn + FUSED LIF: grid (4, 12, 16 bp), t-loop inside.
// Spikes written as fp16 to g_spkh.
// =====================================================================
#define ROWB   144
#define TILEB  (128*ROWB)
#define STAGEB (4*TILEB)

__global__ __launch_bounds__(256) void hmma_conv_lif(
    const float* __restrict__ bng, const float* __restrict__ bnb,
    const float* __restrict__ bnm, const float* __restrict__ bnv)
{
    extern __shared__ char smem[];
    const uint32_t sb = smem_u32(smem);
    const int tid  = threadIdx.x;
    const int wid  = tid >> 5, lane = tid & 31;
    const int n0   = blockIdx.x * 128;
    const int bp   = blockIdx.z;
    const int wsel = blockIdx.y >> 2;
    const int r0   = (blockIdx.y & 3) * 128;

    __half* spk = g_spkh + (size_t)wsel * SZ;
    const __nv_bfloat16* wh = g_whi + (size_t)wsel * CN + (size_t)r0 * Cc;
    const __nv_bfloat16* wl = g_wlo + (size_t)wsel * CN + (size_t)r0 * Cc;

    const int lrow = tid >> 1;
    const int cb0  = (tid & 1) * 4;
    const uint32_t rowOff = (uint32_t)lrow * ROWB;
    const __nv_bfloat16* gAh = wh + (size_t)lrow * Cc;
    const __nv_bfloat16* gAl = wl + (size_t)lrow * Cc;

    const int wm = wid & 1, wn = wid >> 1;
    const int grp = lane >> 3, wi = lane & 7;

    float invA[4], biasA[4], invB[4], biasB[4];
    #pragma unroll
    for (int mi = 0; mi < 4; mi++) {
        const int rA = r0 + wm*64 + mi*16 + (lane >> 2);
        const int rB = rA + 8;
        invA[mi]  = bng[wsel*Cc + rA] / sqrtf(bnv[wsel*Cc + rA] + EPSBN);
        biasA[mi] = bnb[wsel*Cc + rA] - bnm[wsel*Cc + rA] * invA[mi];
        invB[mi]  = bng[wsel*Cc + rB] / sqrtf(bnv[wsel*Cc + rB] + EPSBN);
        biasB[mi] = bnb[wsel*Cc + rB] - bnm[wsel*Cc + rB] * invB[mi];
    }

    float mem[4][4][4];
    #pragma unroll
    for (int i = 0; i < 4; i++)
        #pragma unroll
        for (int j = 0; j < 4; j++)
            #pragma unroll
            for (int q = 0; q < 4; q++) mem[i][j][q] = 0.f;

    for (int t = 0; t < 4; t++) {
        const int b = t*BpC + bp;
        const __nv_bfloat16* gBh = g_xhi + ((size_t)b * Nn + n0) * Cc + (size_t)lrow * Cc;
        const __nv_bfloat16* gBl = g_xlo + ((size_t)b * Nn + n0) * Cc + (size_t)lrow * Cc;

        float acc[4][4][4];
        #pragma unroll
        for (int i = 0; i < 4; i++)
            #pragma unroll
            for (int j = 0; j < 4; j++)
                #pragma unroll
                for (int q = 0; q < 4; q++) acc[i][j][q] = 0.f;

        auto load_stage = [&](uint32_t st, int k0) {
            #pragma unroll
            for (int j = 0; j < 4; j++) {
                const int c = cb0 + j;
                const uint32_t off = rowOff + c * 16;
                cpasync16(st + off,           gAh + k0 + c*8);
                cpasync16(st + TILEB + off,   gAl + k0 + c*8);
                cpasync16(st + 2*TILEB + off, gBh + k0 + c*8);
                cpasync16(st + 3*TILEB + off, gBl + k0 + c*8);
            }
        };

        load_stage(sb, 0);
        CP_COMMIT();

        for (int kc = 0; kc < 8; kc++) {
            const int s = kc & 1;
            if (kc < 7) {
                load_stage(sb + (s^1)*STAGEB, (kc + 1) * 64);
                CP_COMMIT();
                CP_WAIT(1);
            } else {
                CP_WAIT(0);
            }
            __syncthreads();

            const uint32_t st = sb + s * STAGEB;
            #pragma unroll
            for (int ks = 0; ks < 4; ks++) {
                uint32_t Ah[4][4], Al[4][4], Bh[4][2], Bl[4][2];
                #pragma unroll
                for (int mi = 0; mi < 4; mi++) {
                    const uint32_t ra = st
                        + (uint32_t)(wm*64 + mi*16 + wi + (grp&1)*8) * ROWB
                        + (uint32_t)(ks*32 + (grp>>1)*16);
                    ldm_x4(Ah[mi], ra);
                    ldm_x4(Al[mi], ra + TILEB);
                }
                #pragma unroll
                for (int bt = 0; bt < 2; bt++) {
                    const uint32_t rb = st + 2*TILEB
                        + (uint32_t)(wn*32 + bt*16 + wi + (grp>>1)*8) * ROWB
                        + (uint32_t)(ks*32 + (grp&1)*16);
                    uint32_t r[4];
                    ldm_x4(r, rb);
                    Bh[bt*2][0] = r[0]; Bh[bt*2][1] = r[1];
                    Bh[bt*2+1][0] = r[2]; Bh[bt*2+1][1] = r[3];
                    ldm_x4(r, rb + TILEB);
                    Bl[bt*2][0] = r[0]; Bl[bt*2][1] = r[1];
                    Bl[bt*2+1][0] = r[2]; Bl[bt*2+1][1] = r[3];
                }
                #pragma unroll
                for (int mi = 0; mi < 4; mi++)
                    #pragma unroll
                    for (int nt = 0; nt < 4; nt++)
                        mma_bf16(acc[mi][nt], Ah[mi], Bh[nt]);
                #pragma unroll
                for (int mi = 0; mi < 4; mi++)
                    #pragma unroll
                    for (int nt = 0; nt < 4; nt++)
                        mma_bf16(acc[mi][nt], Al[mi], Bh[nt]);
                #pragma unroll
                for (int mi = 0; mi < 4; mi++)
                    #pragma unroll
                    for (int nt = 0; nt < 4; nt++)
                        mma_bf16(acc[mi][nt], Ah[mi], Bl[nt]);
            }
            __syncthreads();
        }

        #pragma unroll
        for (int mi = 0; mi < 4; mi++) {
            const int rA = r0 + wm*64 + mi*16 + (lane >> 2);
            const int rB = rA + 8;
            __half* pA = spk + ((size_t)b * Cc + rA) * Nn + n0;
            __half* pB = spk + ((size_t)b * Cc + rB) * Nn + n0;
            #pragma unroll
            for (int nt = 0; nt < 4; nt++) {
                const int nc = wn*32 + nt*8 + (lane & 3)*2;
                float pre[4];
                pre[0] = acc[mi][nt][0]*invA[mi] + biasA[mi];
                pre[1] = acc[mi][nt][1]*invA[mi] + biasA[mi];
                pre[2] = acc[mi][nt][2]*invB[mi] + biasB[mi];
                pre[3] = acc[mi][nt][3]*invB[mi] + biasB[mi];
                float s[4];
                #pragma unroll
                for (int q = 0; q < 4; q++) {
                    mem[mi][nt][q] = mem[mi][nt][q]*TAU + pre[q];
                    s[q] = (mem[mi][nt][q] > THRESH) ? 1.f : 0.f;
                    if (mem[mi][nt][q] > THRESH) mem[mi][nt][q] = 0.f;
                }
                *(__half2*)&pA[nc] = __floats2half2_rn(s[0], s[1]);
                *(__half2*)&pB[nc] = __floats2half2_rn(s[2], s[3]);
            }
        }
    }
}

// =====================================================================
// proj conv_bn: fp16 SINGLE-term. grid (4, 4, 64), 2 CTAs/SM
// =====================================================================
#define PTILE  (128*ROWB)               // 18432
#define PSTG   (2*PTILE)                // 36864
#define PROJ_SMEM (2*PSTG)              // 73728

__global__ __launch_bounds__(256, 2) void proj_conv(
    float* __restrict__ extout,
    const float* __restrict__ bng, const float* __restrict__ bnb,
    const float* __restrict__ bnm, const float* __restrict__ bnv)
{
    extern __shared__ char smem[];
    const uint32_t sb = smem_u32(smem);
    const int tid  = threadIdx.x;
    const int wid  = tid >> 5, lane = tid & 31;
    const int n0   = blockIdx.x * 128;
    const int r0   = blockIdx.y * 128;
    const int b    = blockIdx.z;

    const __half* wp = g_wp16 + (size_t)r0 * Cc;
    const __half* sp = g_s16 + ((size_t)b * Nn + n0) * Cc;

    const int lrow = tid >> 1;
    const int cb0  = (tid & 1) * 4;
    const uint32_t rowOff = (uint32_t)lrow * ROWB;
    const __half* gA = wp + (size_t)lrow * Cc;
    const __half* gB = sp + (size_t)lrow * Cc;

    float acc[4][4][4];
    #pragma unroll
    for (int i = 0; i < 4; i++)
        #pragma unroll
        for (int j = 0; j < 4; j++)
            #pragma unroll
            for (int q = 0; q < 4; q++) acc[i][j][q] = 0.f;

    const int wm = wid & 1, wn = wid >> 1;
    const int grp = lane >> 3, wi = lane & 7;

    auto load_stage = [&](uint32_t st, int k0) {
        #pragma unroll
        for (int j = 0; j < 4; j++) {
            const int c = cb0 + j;
            const uint32_t off = rowOff + c * 16;
            cpasync16(st + off,         gA + k0 + c*8);
            cpasync16(st + PTILE + off, gB + k0 + c*8);
        }
    };

    load_stage(sb, 0);
    CP_COMMIT();

    for (int kc = 0; kc < 8; kc++) {
        const int s = kc & 1;
        if (kc < 7) {
            load_stage(sb + (s^1)*PSTG, (kc + 1) * 64);
            CP_COMMIT();
            CP_WAIT(1);
        } else {
            CP_WAIT(0);
        }
        __syncthreads();

        const uint32_t st = sb + s * PSTG;
        #pragma unroll
        for (int ks = 0; ks < 4; ks++) {
            uint32_t A[4][4], B[4][2];
            #pragma unroll
            for (int mi = 0; mi < 4; mi++) {
                const uint32_t ra = st
                    + (uint32_t)(wm*64 + mi*16 + wi + (grp&1)*8) * ROWB
                    + (uint32_t)(ks*32 + (grp>>1)*16);
                ldm_x4(A[mi], ra);
            }
            #pragma unroll
            for (int bt = 0; bt < 2; bt++) {
                const uint32_t rb = st + PTILE
                    + (uint32_t)(wn*32 + bt*16 + wi + (grp>>1)*8) * ROWB
                    + (uint32_t)(ks*32 + (grp&1)*16);
                uint32_t r[4];
                ldm_x4(r, rb);
                B[bt*2][0] = r[0]; B[bt*2][1] = r[1];
                B[bt*2+1][0] = r[2]; B[bt*2+1][1] = r[3];
            }
            #pragma unroll
            for (int mi = 0; mi < 4; mi++)
                #pragma unroll
                for (int nt = 0; nt < 4; nt++)
                    mma_f16(acc[mi][nt], A[mi], B[nt]);
        }
        __syncthreads();
    }

    #pragma unroll
    for (int mi = 0; mi < 4; mi++) {
        const int rA = r0 + wm*64 + mi*16 + (lane >> 2);
        const int rB = rA + 8;
        const float invA  = bng[3*Cc + rA] / sqrtf(bnv[3*Cc + rA] + EPSBN);
        const float biasA = bnb[3*Cc + rA] - bnm[3*Cc + rA] * invA;
        const float invB  = bng[3*Cc + rB] / sqrtf(bnv[3*Cc + rB] + EPSBN);
        const float biasB = bnb[3*Cc + rB] - bnm[3*Cc + rB] * invB;
        float* pA = extout + ((size_t)b * Cc + rA) * Nn + n0;
        float* pB = extout + ((size_t)b * Cc + rB) * Nn + n0;
        #pragma unroll
        for (int nt = 0; nt < 4; nt++) {
            const int nc = wn*32 + nt*8 + (lane & 3)*2;
            float2 v0, v1;
            v0.x = acc[mi][nt][0]*invA + biasA;
            v0.y = acc[mi][nt][1]*invA + biasA;
            v1.x = acc[mi][nt][2]*invB + biasB;
            v1.y = acc[mi][nt][3]*invB + biasB;
            *(float2*)&pA[nc] = v0;
            *(float2*)&pB[nc] = v1;
        }
    }
}

// =====================================================================
// attn_m_h: P = V·K^T (64x64, inner 512) per (bp, h, t), fp16 HMMA.
// Exact: spikes 0/1, fp32 accumulate, P ints <= 512. grid (16, 8, 4)
// =====================================================================
#define MROWB  144
#define MTILE  (64*MROWB)       // 9216

__global__ __launch_bounds__(256) void attn_m_h()
{
    __shared__ __align__(16) char smem[4*MTILE];     // 36,864 (2 stages x V|K)
    const uint32_t sb = smem_u32(smem);
    const int bp = blockIdx.x, h = blockIdx.y, t = blockIdx.z;
    const int tid = threadIdx.x;
    const int wid = tid >> 5, lane = tid & 31;
    const int b = t*BpC + bp;

    const __half* V = g_spkh + (size_t)2*SZ + ((size_t)b*Cc + h*GD) * Nn;
    const __half* K = g_spkh + (size_t)SZ   + ((size_t)b*Cc + h*GD) * Nn;

    const int lrow = tid >> 2;               // 64 rows, 4 thr/row
    const int cq2  = (tid & 3) * 2;          // 2 chunks each (8 chunks/row)
    const uint32_t rowOff = (uint32_t)lrow * MROWB;
    const __half* gV = V + (size_t)lrow * Nn;
    const __half* gK = K + (size_t)lrow * Nn;

    const int wm = wid & 1, wn = wid >> 1;
    const int grp = lane >> 3, wi = lane & 7;

    float acc[2][2][4];
    #pragma unroll
    for (int i = 0; i < 2; i++)
        #pragma unroll
        for (int j = 0; j < 2; j++)
            #pragma unroll
            for (int q = 0; q < 4; q++) acc[i][j][q] = 0.f;

    auto load_stage = [&](uint32_t st, int k0) {
        #pragma unroll
        for (int j = 0; j < 2; j++) {
            const int c = cq2 + j;
            const uint32_t off = rowOff + c * 16;
            cpasync16(st + off,         gV + k0 + c*8);
            cpasync16(st + MTILE + off, gK + k0 + c*8);
        }
    };

    load_stage(sb, 0);
    CP_COMMIT();

    for (int kc = 0; kc < 8; kc++) {         // 8 x KC=64
        const int s = kc & 1;
        if (kc < 7) {
            load_stage(sb + (s^1)*2*MTILE, (kc + 1) * 64);
            CP_COMMIT();
            CP_WAIT(1);
        } else {
            CP_WAIT(0);
        }
        __syncthreads();

        const uint32_t st = sb + s*2*MTILE;
        #pragma unroll
        for (int ks = 0; ks < 4; ks++) {
            uint32_t A[2][4], B[2][2];
            #pragma unroll
            for (int mi = 0; mi < 2; mi++) {
                const uint32_t ra = st
                    + (uint32_t)(wm*32 + mi*16 + wi + (grp&1)*8) * MROWB
                    + (uint32_t)(ks*32 + (grp>>1)*16);
                ldm_x4(A[mi], ra);
            }
            {
                const uint32_t rb = st + MTILE
                    + (uint32_t)(wn*16 + wi + (grp>>1)*8) * MROWB
                    + (uint32_t)(ks*32 + (grp&1)*16);
                uint32_t r[4];
                ldm_x4(r, rb);
                B[0][0] = r[0]; B[0][1] = r[1];
                B[1][0] = r[2]; B[1][1] = r[3];
            }
            #pragma unroll
            for (int mi = 0; mi < 2; mi++)
                #pragma unroll
                for (int nt = 0; nt < 2; nt++)
                    mma_f16(acc[mi][nt], A[mi], B[nt]);
        }
        __syncthreads();
    }

    // store P[d][dk] fp16 (exact ints <= 512)
    __half* Pout = g_P + (((size_t)(bp*Hh + h) * 4) + t) * 4096;
    #pragma unroll
    for (int mi = 0; mi < 2; mi++) {
        const int rA = wm*32 + mi*16 + (lane >> 2);
        const int rB = rA + 8;
        #pragma unroll
        for (int nt = 0; nt < 2; nt++) {
            const int nc = wn*16 + nt*8 + (lane & 3)*2;
            *(__half2*)&Pout[rA*64 + nc] = __floats2half2_rn(acc[mi][nt][0], acc[mi][nt][1]);
            *(__half2*)&Pout[rB*64 + nc] = __floats2half2_rn(acc[mi][nt][2], acc[mi][nt][3]);
        }
    }
}

// =====================================================================
// attn_out_h: out[d][n] = SCALE * sum_dk P[d][dk] Q^T[n][dk], + LIF over t
// per (bp, h, nq). A = P_t (smem), B = Q^T n-slice (smem). grid (16, 8, 4)
// =====================================================================
#define AOUT_SMEM (4*MTILE + 128*MROWB)   // 36864 + 18432 = 55296

__global__ __launch_bounds__(256) void attn_out_h()
{
    extern __shared__ char smem[];
    const uint32_t sb = smem_u32(smem);
    const uint32_t Ps = sb;
    const uint32_t Qs = sb + 4*MTILE;

    const int bp = blockIdx.x, h = blockIdx.y, nq = blockIdx.z;
    const int tid = threadIdx.x;
    const int wid = tid >> 5, lane = tid & 31;
    const int wm = wid & 1, wn = wid >> 1;
    const int grp = lane >> 3, wi = lane & 7;

    // load all 4 P_t: 2048 16B-chunks over 256 threads
    {
        const __half* Pin = g_P + ((size_t)(bp*Hh + h) * 4) * 4096;
        #pragma unroll
        for (int j = 0; j < 8; j++) {
            const int cid = tid*8 + j;
            const int tt = cid >> 9, row = (cid >> 3) & 63, c = cid & 7;
            cpasync16(Ps + tt*MTILE + row*MROWB + c*16, Pin + tt*4096 + row*64 + c*8);
        }
        CP_COMMIT();
    }

    // Q loader indices: 128 rows x 8 chunks over 256 threads
    const int qrow = tid >> 1;
    const int qc0  = (tid & 1) * 4;

    float mem[2][4][4];
    #pragma unroll
    for (int i = 0; i < 2; i++)
        #pragma unroll
        for (int j = 0; j < 4; j++)
            #pragma unroll
            for (int q = 0; q < 4; q++) mem[i][j][q] = 0.f;

    for (int t = 0; t < 4; t++) {
        const int b = t*BpC + bp;
        const __half* Qt = g_qT + ((size_t)b * Nn + nq*128 + qrow) * Cc + h*GD;
        #pragma unroll
        for (int j = 0; j < 4; j++) {
            const int c = qc0 + j;
            cpasync16(Qs + qrow*MROWB + c*16, Qt + c*8);
        }
        CP_COMMIT(); CP_WAIT(0);
        __syncthreads();

        float acc[2][4][4];
        #pragma unroll
        for (int i = 0; i < 2; i++)
            #pragma unroll
            for (int j = 0; j < 4; j++)
                #pragma unroll
                for (int q = 0; q < 4; q++) acc[i][j][q] = 0.f;

        #pragma unroll
        for (int ks = 0; ks < 4; ks++) {
            uint32_t A[2][4], B[4][2];
            #pragma unroll
            for (int mi = 0; mi < 2; mi++) {
                const uint32_t ra = Ps + t*MTILE
                    + (uint32_t)(wm*32 + mi*16 + wi + (grp&1)*8) * MROWB
                    + (uint32_t)(ks*32 + (grp>>1)*16);
                ldm_x4(A[mi], ra);
            }
            #pragma unroll
            for (int bt = 0; bt < 2; bt++) {
                const uint32_t rb = Qs
                    + (uint32_t)(wn*32 + bt*16 + wi + (grp>>1)*8) * MROWB
                    + (uint32_t)(ks*32 + (grp&1)*16);
                uint32_t r[4];
                ldm_x4(r, rb);
                B[bt*2][0] = r[0]; B[bt*2][1] = r[1];
                B[bt*2+1][0] = r[2]; B[bt*2+1][1] = r[3];
            }
            #pragma unroll
            for (int mi = 0; mi < 2; mi++)
                #pragma unroll
                for (int nt = 0; nt < 4; nt++)
                    mma_f16(acc[mi][nt], A[mi], B[nt]);
        }

        // LIF epilogue for this t
        #pragma unroll
        for (int mi = 0; mi < 2; mi++) {
            const int rA = wm*32 + mi*16 + (lane >> 2);
            const int rB = rA + 8;
            __half* pA = g_soh + ((size_t)b*Cc + h*GD + rA) * Nn + nq*128;
            __half* pB = g_soh + ((size_t)b*Cc + h*GD + rB) * Nn + nq*128;
            #pragma unroll
            for (int nt = 0; nt < 4; nt++) {
                const int nc = wn*32 + nt*8 + (lane & 3)*2;
                float o[4];
                o[0] = acc[mi][nt][0]*SCALE; o[1] = acc[mi][nt][1]*SCALE;
                o[2] = acc[mi][nt][2]*SCALE; o[3] = acc[mi][nt][3]*SCALE;
                float s[4];
                #pragma unroll
                for (int q = 0; q < 4; q++) {
                    mem[mi][nt][q] = mem[mi][nt][q]*TAU + o[q];
                    s[q] = (mem[mi][nt][q] > THRESH) ? 1.f : 0.f;
                    if (mem[mi][nt][q] > THRESH) mem[mi][nt][q] = 0.f;
                }
                *(__half2*)&pA[nc] = __floats2half2_rn(s[0], s[1]);
                *(__half2*)&pB[nc] = __floats2half2_rn(s[2], s[3]);
            }
        }
        __syncthreads();   // protect Qs before next t overwrite
    }
}

// =====================================================================
// launch
// =====================================================================
extern "C" void kernel_launch(void* const* d_in, const int* in_sizes, int n_in,
                              void* d_out, int out_size)
{
    const float* x     = (const float*)d_in[0];
    const float* wq    = (const float*)d_in[1];
    const float* wk    = (const float*)d_in[2];
    const float* wv    = (const float*)d_in[3];
    const float* wproj = (const float*)d_in[4];
    const float* bng   = (const float*)d_in[5];
    const float* bnb   = (const float*)d_in[6];
    const float* bnm   = (const float*)d_in[7];
    const float* bnv   = (const float*)d_in[8];
    float* out = (float*)d_out;

    const int conv_smem = 2 * STAGEB;   // 147,456 B
    cudaFuncSetAttribute(hmma_conv_lif, cudaFuncAttributeMaxDynamicSharedMemorySize, conv_smem);
    cudaFuncSetAttribute(proj_conv, cudaFuncAttributeMaxDynamicSharedMemorySize, PROJ_SMEM);
    cudaFuncSetAttribute(attn_out_h, cudaFuncAttributeMaxDynamicSharedMemorySize, AOUT_SMEM);

    wsplit_kernel<<<dim3(1024, 4), 256>>>(wq, wk, wv, wproj);
    split_t_kernel<<<dim3(16, 16, 64), dim3(32, 8)>>>(x);

    // merged q,k,v conv_bn + fused LIF (fp16 spike output)
    hmma_conv_lif<<<dim3(4, 12, 16), 256, conv_smem>>>(bng, bnb, bnm, bnv);

    // q spikes -> transposed fp16 for attn_out B operand
    transpose_h_kernel<<<dim3(16, 16, 64), 256>>>(0);

    // attention on tensor pipe (exact fp16)
    attn_m_h<<<dim3(BpC, Hh, 4), 256>>>();
    attn_out_h<<<dim3(BpC, Hh, 4), 256, AOUT_SMEM>>>();

    // attn spikes -> transposed fp16 for proj B operand
    transpose_h_kernel<<<dim3(16, 16, 64), 256>>>(1);

    // proj conv_bn (fp16 single-term)
    proj_conv<<<dim3(4, 4, 64), 256, PROJ_SMEM>>>(out, bng, bnb, bnm, bnv);
}

// round 16
// speedup vs baseline: 2.2983x; 1.0165x over previous
#include <cuda_runtime.h>
#include <cuda_bf16.h>
#include <cuda_fp16.h>
#include <cstdint>
#include <cstddef>

// ---------------- problem constants ----------------
#define Tt      4
#define Bt      64
#define BpC     16
#define Cc      512
#define Nn      512
#define Hh      8
#define GD      64
#define TAU     0.5f
#define THRESH  1.0f
#define SCALE   0.125f
#define EPSBN   1e-5f
#define SZ      (Bt*Cc*Nn)      // 16,777,216
#define CN      (Cc*Nn)

typedef unsigned long long ull;

// ---------------- scratch (device globals) ----------------
__device__ __align__(128) __half g_spkh[3ll*SZ];      // q,k,v spikes fp16 [b][c][n]
__device__ __align__(128) __half g_qT  [SZ];          // q spikes fp16 [b][n][c]
__device__ __align__(128) __half g_P   [16*8*4*4096]; // P per (bp,h,t) fp16: 4 MB
__device__ __align__(128) __nv_bfloat16 g_xhi[SZ];    // [b][n][c]
__device__ __align__(128) __nv_bfloat16 g_xlo[SZ];
__device__ __align__(128) __half        g_s16[SZ];    // attn spikes fp16 [b][n][c]
__device__ __align__(128) __nv_bfloat16 g_whi[3ll*CN];
__device__ __align__(128) __nv_bfloat16 g_wlo[3ll*CN];
__device__ __align__(128) __half        g_wp16[CN];

// ---------------- PTX helpers ----------------
static __device__ __forceinline__ uint32_t smem_u32(const void* p) {
    uint32_t a;
    asm("{ .reg .u64 t; cvta.to.shared.u64 t, %1; cvt.u32.u64 %0, t; }" : "=r"(a) : "l"(p));
    return a;
}
static __device__ __forceinline__ void cpasync16(uint32_t dst, const void* src) {
    asm volatile("cp.async.cg.shared.global [%0], [%1], 16;" :: "r"(dst), "l"(src));
}
#define CP_COMMIT()  asm volatile("cp.async.commit_group;" ::: "memory")
#define CP_WAIT(n)   asm volatile("cp.async.wait_group %0;" :: "n"(n) : "memory")

static __device__ __forceinline__ void ldm_x4(uint32_t* r, uint32_t addr) {
    asm volatile("ldmatrix.sync.aligned.m8n8.x4.shared.b16 {%0,%1,%2,%3}, [%4];"
        : "=r"(r[0]), "=r"(r[1]), "=r"(r[2]), "=r"(r[3]) : "r"(addr));
}
static __device__ __forceinline__ void mma_bf16(float* c, const uint32_t* a, const uint32_t* b) {
    asm volatile("mma.sync.aligned.m16n8k16.row.col.f32.bf16.bf16.f32 "
        "{%0,%1,%2,%3}, {%4,%5,%6,%7}, {%8,%9}, {%0,%1,%2,%3};"
        : "+f"(c[0]), "+f"(c[1]), "+f"(c[2]), "+f"(c[3])
        : "r"(a[0]), "r"(a[1]), "r"(a[2]), "r"(a[3]), "r"(b[0]), "r"(b[1]));
}
static __device__ __forceinline__ void mma_f16(float* c, const uint32_t* a, const uint32_t* b) {
    asm volatile("mma.sync.aligned.m16n8k16.row.col.f32.f16.f16.f32 "
        "{%0,%1,%2,%3}, {%4,%5,%6,%7}, {%8,%9}, {%0,%1,%2,%3};"
        : "+f"(c[0]), "+f"(c[1]), "+f"(c[2]), "+f"(c[3])
        : "r"(a[0]), "r"(a[1]), "r"(a[2]), "r"(a[3]), "r"(b[0]), "r"(b[1]));
}

// =====================================================================
// weight split: qkv -> bf16 hi/lo; proj -> fp16 single
// =====================================================================
__global__ __launch_bounds__(256) void wsplit_kernel(
    const float* __restrict__ wq, const float* __restrict__ wk,
    const float* __restrict__ wv, const float* __restrict__ wp)
{
    const int which = blockIdx.y;
    const float* w = (which == 0) ? wq : (which == 1) ? wk : (which == 2) ? wv : wp;
    const int i = blockIdx.x * 256 + threadIdx.x;
    float v = w[i];
    if (which < 3) {
        __nv_bfloat16 h = __float2bfloat16(v);
        g_whi[(size_t)which * CN + i] = h;
        g_wlo[(size_t)which * CN + i] = __float2bfloat16(v - __bfloat162float(h));
    } else {
        g_wp16[i] = __float2half(v);
    }
}

// =====================================================================
// x transpose + split: fp32 [b][c][n] -> bf16 hi/lo [b][n][c]
// =====================================================================
__global__ __launch_bounds__(256) void split_t_kernel(const float* __restrict__ in)
{
    __shared__ float t[32][33];
    const int b = blockIdx.z, c0 = blockIdx.y * 32, n0 = blockIdx.x * 32;
    const int tx = threadIdx.x, ty = threadIdx.y;
    const float* ib = in + (size_t)b * CN;
    #pragma unroll
    for (int j = 0; j < 4; j++)
        t[ty + 8*j][tx] = ib[(size_t)(c0 + ty + 8*j) * Nn + n0 + tx];
    __syncthreads();
    #pragma unroll
    for (int j = 0; j < 4; j++) {
        const int n = ty + 8*j;
        const float v = t[tx][n];
        const size_t o = ((size_t)b * Nn + n0 + n) * Cc + c0 + tx;
        const __nv_bfloat16 h = __float2bfloat16(v);
        g_xhi[o] = h;
        g_xlo[o] = __float2bfloat16(v - __bfloat162float(h));
    }
}

// =====================================================================
// fp16 transpose of q spikes: g_spkh q-plane [b][c][n] -> g_qT [b][n][c]
// =====================================================================
__global__ __launch_bounds__(256) void transpose_q_kernel()
{
    __shared__ __half t[32][34];
    const int b = blockIdx.z, c0 = blockIdx.y * 32, n0 = blockIdx.x * 32;
    const int tid = threadIdx.x;
    const int tx = tid & 31, ty = tid >> 5;
    const __half* src = g_spkh + (size_t)b * CN;
    #pragma unroll
    for (int j = 0; j < 4; j++)
        t[ty + 8*j][tx] = src[(size_t)(c0 + ty + 8*j) * Nn + n0 + tx];
    __syncthreads();
    #pragma unroll
    for (int j = 0; j < 4; j++) {
        const int n = ty + 8*j;
        g_qT[((size_t)b * Nn + n0 + n) * Cc + c0 + tx] = t[tx][n];
    }
}

// =====================================================================
// qkv HMMA conv_bn + FUSED LIF: grid (4, 12, 16 bp), t-loop inside.
// Spikes written as fp16 to g_spkh.
// =====================================================================
#define ROWB   144
#define TILEB  (128*ROWB)
#define STAGEB (4*TILEB)

__global__ __launch_bounds__(256) void hmma_conv_lif(
    const float* __restrict__ bng, const float* __restrict__ bnb,
    const float* __restrict__ bnm, const float* __restrict__ bnv)
{
    extern __shared__ char smem[];
    const uint32_t sb = smem_u32(smem);
    const int tid  = threadIdx.x;
    const int wid  = tid >> 5, lane = tid & 31;
    const int n0   = blockIdx.x * 128;
    const int bp   = blockIdx.z;
    const int wsel = blockIdx.y >> 2;
    const int r0   = (blockIdx.y & 3) * 128;

    __half* spk = g_spkh + (size_t)wsel * SZ;
    const __nv_bfloat16* wh = g_whi + (size_t)wsel * CN + (size_t)r0 * Cc;
    const __nv_bfloat16* wl = g_wlo + (size_t)wsel * CN + (size_t)r0 * Cc;

    const int lrow = tid >> 1;
    const int cb0  = (tid & 1) * 4;
    const uint32_t rowOff = (uint32_t)lrow * ROWB;
    const __nv_bfloat16* gAh = wh + (size_t)lrow * Cc;
    const __nv_bfloat16* gAl = wl + (size_t)lrow * Cc;

    const int wm = wid & 1, wn = wid >> 1;
    const int grp = lane >> 3, wi = lane & 7;

    float invA[4], biasA[4], invB[4], biasB[4];
    #pragma unroll
    for (int mi = 0; mi < 4; mi++) {
        const int rA = r0 + wm*64 + mi*16 + (lane >> 2);
        const int rB = rA + 8;
        invA[mi]  = bng[wsel*Cc + rA] / sqrtf(bnv[wsel*Cc + rA] + EPSBN);
        biasA[mi] = bnb[wsel*Cc + rA] - bnm[wsel*Cc + rA] * invA[mi];
        invB[mi]  = bng[wsel*Cc + rB] / sqrtf(bnv[wsel*Cc + rB] + EPSBN);
        biasB[mi] = bnb[wsel*Cc + rB] - bnm[wsel*Cc + rB] * invB[mi];
    }

    float mem[4][4][4];
    #pragma unroll
    for (int i = 0; i < 4; i++)
        #pragma unroll
        for (int j = 0; j < 4; j++)
            #pragma unroll
            for (int q = 0; q < 4; q++) mem[i][j][q] = 0.f;

    for (int t = 0; t < 4; t++) {
        const int b = t*BpC + bp;
        const __nv_bfloat16* gBh = g_xhi + ((size_t)b * Nn + n0) * Cc + (size_t)lrow * Cc;
        const __nv_bfloat16* gBl = g_xlo + ((size_t)b * Nn + n0) * Cc + (size_t)lrow * Cc;

        float acc[4][4][4];
        #pragma unroll
        for (int i = 0; i < 4; i++)
            #pragma unroll
            for (int j = 0; j < 4; j++)
                #pragma unroll
                for (int q = 0; q < 4; q++) acc[i][j][q] = 0.f;

        auto load_stage = [&](uint32_t st, int k0) {
            #pragma unroll
            for (int j = 0; j < 4; j++) {
                const int c = cb0 + j;
                const uint32_t off = rowOff + c * 16;
                cpasync16(st + off,           gAh + k0 + c*8);
                cpasync16(st + TILEB + off,   gAl + k0 + c*8);
                cpasync16(st + 2*TILEB + off, gBh + k0 + c*8);
                cpasync16(st + 3*TILEB + off, gBl + k0 + c*8);
            }
        };

        load_stage(sb, 0);
        CP_COMMIT();

        for (int kc = 0; kc < 8; kc++) {
            const int s = kc & 1;
            if (kc < 7) {
                load_stage(sb + (s^1)*STAGEB, (kc + 1) * 64);
                CP_COMMIT();
                CP_WAIT(1);
            } else {
                CP_WAIT(0);
            }
            __syncthreads();

            const uint32_t st = sb + s * STAGEB;
            #pragma unroll
            for (int ks = 0; ks < 4; ks++) {
                uint32_t Ah[4][4], Al[4][4], Bh[4][2], Bl[4][2];
                #pragma unroll
                for (int mi = 0; mi < 4; mi++) {
                    const uint32_t ra = st
                        + (uint32_t)(wm*64 + mi*16 + wi + (grp&1)*8) * ROWB
                        + (uint32_t)(ks*32 + (grp>>1)*16);
                    ldm_x4(Ah[mi], ra);
                    ldm_x4(Al[mi], ra + TILEB);
                }
                #pragma unroll
                for (int bt = 0; bt < 2; bt++) {
                    const uint32_t rb = st + 2*TILEB
                        + (uint32_t)(wn*32 + bt*16 + wi + (grp>>1)*8) * ROWB
                        + (uint32_t)(ks*32 + (grp&1)*16);
                    uint32_t r[4];
                    ldm_x4(r, rb);
                    Bh[bt*2][0] = r[0]; Bh[bt*2][1] = r[1];
                    Bh[bt*2+1][0] = r[2]; Bh[bt*2+1][1] = r[3];
                    ldm_x4(r, rb + TILEB);
                    Bl[bt*2][0] = r[0]; Bl[bt*2][1] = r[1];
                    Bl[bt*2+1][0] = r[2]; Bl[bt*2+1][1] = r[3];
                }
                #pragma unroll
                for (int mi = 0; mi < 4; mi++)
                    #pragma unroll
                    for (int nt = 0; nt < 4; nt++)
                        mma_bf16(acc[mi][nt], Ah[mi], Bh[nt]);
                #pragma unroll
                for (int mi = 0; mi < 4; mi++)
                    #pragma unroll
                    for (int nt = 0; nt < 4; nt++)
                        mma_bf16(acc[mi][nt], Al[mi], Bh[nt]);
                #pragma unroll
                for (int mi = 0; mi < 4; mi++)
                    #pragma unroll
                    for (int nt = 0; nt < 4; nt++)
                        mma_bf16(acc[mi][nt], Ah[mi], Bl[nt]);
            }
            __syncthreads();
        }

        #pragma unroll
        for (int mi = 0; mi < 4; mi++) {
            const int rA = r0 + wm*64 + mi*16 + (lane >> 2);
            const int rB = rA + 8;
            __half* pA = spk + ((size_t)b * Cc + rA) * Nn + n0;
            __half* pB = spk + ((size_t)b * Cc + rB) * Nn + n0;
            #pragma unroll
            for (int nt = 0; nt < 4; nt++) {
                const int nc = wn*32 + nt*8 + (lane & 3)*2;
                float pre[4];
                pre[0] = acc[mi][nt][0]*invA[mi] + biasA[mi];
                pre[1] = acc[mi][nt][1]*invA[mi] + biasA[mi];
                pre[2] = acc[mi][nt][2]*invB[mi] + biasB[mi];
                pre[3] = acc[mi][nt][3]*invB[mi] + biasB[mi];
                float s[4];
                #pragma unroll
                for (int q = 0; q < 4; q++) {
                    mem[mi][nt][q] = mem[mi][nt][q]*TAU + pre[q];
                    s[q] = (mem[mi][nt][q] > THRESH) ? 1.f : 0.f;
                    if (mem[mi][nt][q] > THRESH) mem[mi][nt][q] = 0.f;
                }
                *(__half2*)&pA[nc] = __floats2half2_rn(s[0], s[1]);
                *(__half2*)&pB[nc] = __floats2half2_rn(s[2], s[3]);
            }
        }
    }
}

// =====================================================================
// proj conv_bn: fp16 SINGLE-term. grid (4, 4, 64), 2 CTAs/SM
// =====================================================================
#define PTILE  (128*ROWB)               // 18432
#define PSTG   (2*PTILE)                // 36864
#define PROJ_SMEM (2*PSTG)              // 73728

__global__ __launch_bounds__(256, 2) void proj_conv(
    float* __restrict__ extout,
    const float* __restrict__ bng, const float* __restrict__ bnb,
    const float* __restrict__ bnm, const float* __restrict__ bnv)
{
    extern __shared__ char smem[];
    const uint32_t sb = smem_u32(smem);
    const int tid  = threadIdx.x;
    const int wid  = tid >> 5, lane = tid & 31;
    const int n0   = blockIdx.x * 128;
    const int r0   = blockIdx.y * 128;
    const int b    = blockIdx.z;

    const __half* wp = g_wp16 + (size_t)r0 * Cc;
    const __half* sp = g_s16 + ((size_t)b * Nn + n0) * Cc;

    const int lrow = tid >> 1;
    const int cb0  = (tid & 1) * 4;
    const uint32_t rowOff = (uint32_t)lrow * ROWB;
    const __half* gA = wp + (size_t)lrow * Cc;
    const __half* gB = sp + (size_t)lrow * Cc;

    float acc[4][4][4];
    #pragma unroll
    for (int i = 0; i < 4; i++)
        #pragma unroll
        for (int j = 0; j < 4; j++)
            #pragma unroll
            for (int q = 0; q < 4; q++) acc[i][j][q] = 0.f;

    const int wm = wid & 1, wn = wid >> 1;
    const int grp = lane >> 3, wi = lane & 7;

    auto load_stage = [&](uint32_t st, int k0) {
        #pragma unroll
        for (int j = 0; j < 4; j++) {
            const int c = cb0 + j;
            const uint32_t off = rowOff + c * 16;
            cpasync16(st + off,         gA + k0 + c*8);
            cpasync16(st + PTILE + off, gB + k0 + c*8);
        }
    };

    load_stage(sb, 0);
    CP_COMMIT();

    for (int kc = 0; kc < 8; kc++) {
        const int s = kc & 1;
        if (kc < 7) {
            load_stage(sb + (s^1)*PSTG, (kc + 1) * 64);
            CP_COMMIT();
            CP_WAIT(1);
        } else {
            CP_WAIT(0);
        }
        __syncthreads();

        const uint32_t st = sb + s * PSTG;
        #pragma unroll
        for (int ks = 0; ks < 4; ks++) {
            uint32_t A[4][4], B[4][2];
            #pragma unroll
            for (int mi = 0; mi < 4; mi++) {
                const uint32_t ra = st
                    + (uint32_t)(wm*64 + mi*16 + wi + (grp&1)*8) * ROWB
                    + (uint32_t)(ks*32 + (grp>>1)*16);
                ldm_x4(A[mi], ra);
            }
            #pragma unroll
            for (int bt = 0; bt < 2; bt++) {
                const uint32_t rb = st + PTILE
                    + (uint32_t)(wn*32 + bt*16 + wi + (grp>>1)*8) * ROWB
                    + (uint32_t)(ks*32 + (grp&1)*16);
                uint32_t r[4];
                ldm_x4(r, rb);
                B[bt*2][0] = r[0]; B[bt*2][1] = r[1];
                B[bt*2+1][0] = r[2]; B[bt*2+1][1] = r[3];
            }
            #pragma unroll
            for (int mi = 0; mi < 4; mi++)
                #pragma unroll
                for (int nt = 0; nt < 4; nt++)
                    mma_f16(acc[mi][nt], A[mi], B[nt]);
        }
        __syncthreads();
    }

    #pragma unroll
    for (int mi = 0; mi < 4; mi++) {
        const int rA = r0 + wm*64 + mi*16 + (lane >> 2);
        const int rB = rA + 8;
        const float invA  = bng[3*Cc + rA] / sqrtf(bnv[3*Cc + rA] + EPSBN);
        const float biasA = bnb[3*Cc + rA] - bnm[3*Cc + rA] * invA;
        const float invB  = bng[3*Cc + rB] / sqrtf(bnv[3*Cc + rB] + EPSBN);
        const float biasB = bnb[3*Cc + rB] - bnm[3*Cc + rB] * invB;
        float* pA = extout + ((size_t)b * Cc + rA) * Nn + n0;
        float* pB = extout + ((size_t)b * Cc + rB) * Nn + n0;
        #pragma unroll
        for (int nt = 0; nt < 4; nt++) {
            const int nc = wn*32 + nt*8 + (lane & 3)*2;
            float2 v0, v1;
            v0.x = acc[mi][nt][0]*invA + biasA;
            v0.y = acc[mi][nt][1]*invA + biasA;
            v1.x = acc[mi][nt][2]*invB + biasB;
            v1.y = acc[mi][nt][3]*invB + biasB;
            *(float2*)&pA[nc] = v0;
            *(float2*)&pB[nc] = v1;
        }
    }
}

// =====================================================================
// attn_m_h: P = V·K^T (64x64, inner 512) per (bp, h, t), fp16 HMMA (exact)
// =====================================================================
#define MROWB  144
#define MTILE  (64*MROWB)       // 9216

__global__ __launch_bounds__(256) void attn_m_h()
{
    __shared__ __align__(16) char smem[4*MTILE];     // 2 stages x (V|K)
    const uint32_t sb = smem_u32(smem);
    const int bp = blockIdx.x, h = blockIdx.y, t = blockIdx.z;
    const int tid = threadIdx.x;
    const int wid = tid >> 5, lane = tid & 31;
    const int b = t*BpC + bp;

    const __half* V = g_spkh + (size_t)2*SZ + ((size_t)b*Cc + h*GD) * Nn;
    const __half* K = g_spkh + (size_t)SZ   + ((size_t)b*Cc + h*GD) * Nn;

    const int lrow = tid >> 2;
    const int cq2  = (tid & 3) * 2;
    const uint32_t rowOff = (uint32_t)lrow * MROWB;
    const __half* gV = V + (size_t)lrow * Nn;
    const __half* gK = K + (size_t)lrow * Nn;

    const int wm = wid & 1, wn = wid >> 1;
    const int grp = lane >> 3, wi = lane & 7;

    float acc[2][2][4];
    #pragma unroll
    for (int i = 0; i < 2; i++)
        #pragma unroll
        for (int j = 0; j < 2; j++)
            #pragma unroll
            for (int q = 0; q < 4; q++) acc[i][j][q] = 0.f;

    auto load_stage = [&](uint32_t st, int k0) {
        #pragma unroll
        for (int j = 0; j < 2; j++) {
            const int c = cq2 + j;
            const uint32_t off = rowOff + c * 16;
            cpasync16(st + off,         gV + k0 + c*8);
            cpasync16(st + MTILE + off, gK + k0 + c*8);
        }
    };

    load_stage(sb, 0);
    CP_COMMIT();

    for (int kc = 0; kc < 8; kc++) {
        const int s = kc & 1;
        if (kc < 7) {
            load_stage(sb + (s^1)*2*MTILE, (kc + 1) * 64);
            CP_COMMIT();
            CP_WAIT(1);
        } else {
            CP_WAIT(0);
        }
        __syncthreads();

        const uint32_t st = sb + s*2*MTILE;
        #pragma unroll
        for (int ks = 0; ks < 4; ks++) {
            uint32_t A[2][4], B[2][2];
            #pragma unroll
            for (int mi = 0; mi < 2; mi++) {
                const uint32_t ra = st
                    + (uint32_t)(wm*32 + mi*16 + wi + (grp&1)*8) * MROWB
                    + (uint32_t)(ks*32 + (grp>>1)*16);
                ldm_x4(A[mi], ra);
            }
            {
                const uint32_t rb = st + MTILE
                    + (uint32_t)(wn*16 + wi + (grp>>1)*8) * MROWB
                    + (uint32_t)(ks*32 + (grp&1)*16);
                uint32_t r[4];
                ldm_x4(r, rb);
                B[0][0] = r[0]; B[0][1] = r[1];
                B[1][0] = r[2]; B[1][1] = r[3];
            }
            #pragma unroll
            for (int mi = 0; mi < 2; mi++)
                #pragma unroll
                for (int nt = 0; nt < 2; nt++)
                    mma_f16(acc[mi][nt], A[mi], B[nt]);
        }
        __syncthreads();
    }

    __half* Pout = g_P + (((size_t)(bp*Hh + h) * 4) + t) * 4096;
    #pragma unroll
    for (int mi = 0; mi < 2; mi++) {
        const int rA = wm*32 + mi*16 + (lane >> 2);
        const int rB = rA + 8;
        #pragma unroll
        for (int nt = 0; nt < 2; nt++) {
            const int nc = wn*16 + nt*8 + (lane & 3)*2;
            *(__half2*)&Pout[rA*64 + nc] = __floats2half2_rn(acc[mi][nt][0], acc[mi][nt][1]);
            *(__half2*)&Pout[rB*64 + nc] = __floats2half2_rn(acc[mi][nt][2], acc[mi][nt][3]);
        }
    }
}

// =====================================================================
// attn_out_h (SWAPPED): out^T[n][d] = Σ_dk Q^T[n][dk]·P_t[d][dk], + LIF
// over t; writes spikes DIRECTLY to g_s16 [b][n][c] (proj input layout).
// A = Q^T slice (128 n rows), B = P_t (64 d rows). grid (16, 8, 4 nq)
// =====================================================================
#define AOUT_SMEM (4*MTILE + 128*MROWB)   // 36864 + 18432 = 55296

__global__ __launch_bounds__(256) void attn_out_h()
{
    extern __shared__ char smem[];
    const uint32_t sb = smem_u32(smem);
    const uint32_t Ps = sb;
    const uint32_t Qs = sb + 4*MTILE;

    const int bp = blockIdx.x, h = blockIdx.y, nq = blockIdx.z;
    const int tid = threadIdx.x;
    const int wid = tid >> 5, lane = tid & 31;
    const int wm = wid & 3, wn = wid >> 2;     // 4 M(n) slabs x 2 N(d) slabs
    const int grp = lane >> 3, wi = lane & 7;

    // load all 4 P_t: 2048 16B-chunks over 256 threads
    {
        const __half* Pin = g_P + ((size_t)(bp*Hh + h) * 4) * 4096;
        #pragma unroll
        for (int j = 0; j < 8; j++) {
            const int cid = tid*8 + j;
            const int tt = cid >> 9, row = (cid >> 3) & 63, c = cid & 7;
            cpasync16(Ps + tt*MTILE + row*MROWB + c*16, Pin + tt*4096 + row*64 + c*8);
        }
        CP_COMMIT();
    }

    // Q loader: 128 rows x 8 chunks over 256 threads
    const int qrow = tid >> 1;
    const int qc0  = (tid & 1) * 4;

    float mem[2][4][4];
    #pragma unroll
    for (int i = 0; i < 2; i++)
        #pragma unroll
        for (int j = 0; j < 4; j++)
            #pragma unroll
            for (int q = 0; q < 4; q++) mem[i][j][q] = 0.f;

    for (int t = 0; t < 4; t++) {
        const int b = t*BpC + bp;
        const __half* Qt = g_qT + ((size_t)b * Nn + nq*128 + qrow) * Cc + h*GD;
        #pragma unroll
        for (int j = 0; j < 4; j++) {
            const int c = qc0 + j;
            cpasync16(Qs + qrow*MROWB + c*16, Qt + c*8);
        }
        CP_COMMIT(); CP_WAIT(0);
        __syncthreads();

        float acc[2][4][4];
        #pragma unroll
        for (int i = 0; i < 2; i++)
            #pragma unroll
            for (int j = 0; j < 4; j++)
                #pragma unroll
                for (int q = 0; q < 4; q++) acc[i][j][q] = 0.f;

        #pragma unroll
        for (int ks = 0; ks < 4; ks++) {
            uint32_t A[2][4], B[4][2];
            #pragma unroll
            for (int mi = 0; mi < 2; mi++) {
                const uint32_t ra = Qs
                    + (uint32_t)(wm*32 + mi*16 + wi + (grp&1)*8) * MROWB
                    + (uint32_t)(ks*32 + (grp>>1)*16);
                ldm_x4(A[mi], ra);
            }
            #pragma unroll
            for (int bt = 0; bt < 2; bt++) {
                const uint32_t rb = Ps + t*MTILE
                    + (uint32_t)(wn*32 + bt*16 + wi + (grp>>1)*8) * MROWB
                    + (uint32_t)(ks*32 + (grp&1)*16);
                uint32_t r[4];
                ldm_x4(r, rb);
                B[bt*2][0] = r[0]; B[bt*2][1] = r[1];
                B[bt*2+1][0] = r[2]; B[bt*2+1][1] = r[3];
            }
            #pragma unroll
            for (int mi = 0; mi < 2; mi++)
                #pragma unroll
                for (int nt = 0; nt < 4; nt++)
                    mma_f16(acc[mi][nt], A[mi], B[nt]);
        }

        // LIF epilogue: rows = n, cols = d; write [b][n][c] directly
        #pragma unroll
        for (int mi = 0; mi < 2; mi++) {
            const int nA = nq*128 + wm*32 + mi*16 + (lane >> 2);
            const int nB = nA + 8;
            __half* pA = g_s16 + ((size_t)b*Nn + nA) * Cc + h*GD;
            __half* pB = g_s16 + ((size_t)b*Nn + nB) * Cc + h*GD;
            #pragma unroll
            for (int nt = 0; nt < 4; nt++) {
                const int dc = wn*32 + nt*8 + (lane & 3)*2;
                float o[4];
                o[0] = acc[mi][nt][0]*SCALE; o[1] = acc[mi][nt][1]*SCALE;
                o[2] = acc[mi][nt][2]*SCALE; o[3] = acc[mi][nt][3]*SCALE;
                float s[4];
                #pragma unroll
                for (int q = 0; q < 4; q++) {
                    mem[mi][nt][q] = mem[mi][nt][q]*TAU + o[q];
                    s[q] = (mem[mi][nt][q] > THRESH) ? 1.f : 0.f;
                    if (mem[mi][nt][q] > THRESH) mem[mi][nt][q] = 0.f;
                }
                *(__half2*)&pA[dc] = __floats2half2_rn(s[0], s[1]);
                *(__half2*)&pB[dc] = __floats2half2_rn(s[2], s[3]);
            }
        }
        __syncthreads();   // protect Qs before next t overwrite
    }
}

// =====================================================================
// launch
// =====================================================================
extern "C" void kernel_launch(void* const* d_in, const int* in_sizes, int n_in,
                              void* d_out, int out_size)
{
    const float* x     = (const float*)d_in[0];
    const float* wq    = (const float*)d_in[1];
    const float* wk    = (const float*)d_in[2];
    const float* wv    = (const float*)d_in[3];
    const float* wproj = (const float*)d_in[4];
    const float* bng   = (const float*)d_in[5];
    const float* bnb   = (const float*)d_in[6];
    const float* bnm   = (const float*)d_in[7];
    const float* bnv   = (const float*)d_in[8];
    float* out = (float*)d_out;

    const int conv_smem = 2 * STAGEB;   // 147,456 B
    cudaFuncSetAttribute(hmma_conv_lif, cudaFuncAttributeMaxDynamicSharedMemorySize, conv_smem);
    cudaFuncSetAttribute(proj_conv, cudaFuncAttributeMaxDynamicSharedMemorySize, PROJ_SMEM);
    cudaFuncSetAttribute(attn_out_h, cudaFuncAttributeMaxDynamicSharedMemorySize, AOUT_SMEM);

    wsplit_kernel<<<dim3(1024, 4), 256>>>(wq, wk, wv, wproj);
    split_t_kernel<<<dim3(16, 16, 64), dim3(32, 8)>>>(x);

    // merged q,k,v conv_bn + fused LIF (fp16 spike output)
    hmma_conv_lif<<<dim3(4, 12, 16), 256, conv_smem>>>(bng, bnb, bnm, bnv);

    // q spikes -> transposed fp16 for attn_out A operand
    transpose_q_kernel<<<dim3(16, 16, 64), 256>>>();

    // attention on tensor pipe (exact fp16); out written directly [b][n][c]
    attn_m_h<<<dim3(BpC, Hh, 4), 256>>>();
    attn_out_h<<<dim3(BpC, Hh, 4), 256, AOUT_SMEM>>>();

    // proj conv_bn (fp16 single-term)
    proj_conv<<<dim3(4, 4, 64), 256, PROJ_SMEM>>>(out, bng, bnb, bnm, bnv);
}